// round 8
// baseline (speedup 1.0000x reference)
#include <cuda_runtime.h>
#include <cuda.h>
#include <cuda_bf16.h>
#include <stdint.h>

#define T_TOKENS 8192
#define DM 1024
#define DF 4096
#define NE 8
#define PAIRS 16384
#define MAXTILES 144
#define MAXT2 72

// tcgen05 availability: only in the arch-SPECIFIC device pass (sm_103a / sm_100a).
#if defined(__CUDA_ARCH__) && (defined(__CUDA_ARCH_FEAT_SM103_ALL) || defined(__CUDA_ARCH_FEAT_SM100_ALL) || defined(__CUDA_ARCH_SPECIFIC__))
#define HAS_TC 1
#else
#define HAS_TC 0
#endif

// ---------------- scratch (device globals; no allocations) ----------------
__device__ __align__(128) __nv_bfloat16 g_Ah[(size_t)PAIRS * DM];  // gathered x, slot-ordered, hi
__device__ __align__(128) __nv_bfloat16 g_Al[(size_t)PAIRS * DM];  // lo
__device__ __align__(128) __nv_bfloat16 g_Hh[(size_t)PAIRS * DF];
__device__ __align__(128) __nv_bfloat16 g_Hl[(size_t)PAIRS * DF];
__device__ __align__(128) float         g_Y[(size_t)PAIRS * DM];

// pre-split, pre-transposed weights: [E][N][K] bf16 hi/lo
__device__ __align__(128) __nv_bfloat16 g_w1h[(size_t)NE * DM * DF];
__device__ __align__(128) __nv_bfloat16 g_w1l[(size_t)NE * DM * DF];
__device__ __align__(128) __nv_bfloat16 g_w2h[(size_t)NE * DF * DM];
__device__ __align__(128) __nv_bfloat16 g_w2l[(size_t)NE * DF * DM];

__device__ int   g_pair_e[PAIRS];
__device__ float g_pair_w[PAIRS];
__device__ int   g_pair_slot[PAIRS];
__device__ int   g_rows_token[PAIRS];

__device__ int g_counts[NE];
__device__ int g_off[NE + 1];
__device__ int g_tile_e[MAXTILES];     // 256-row tiles
__device__ int g_tile_r0[MAXTILES];
__device__ int g_tile_valid[MAXTILES]; // 1..256
__device__ int g_num_tiles;

// ---------------- shared helpers ----------------
__device__ __forceinline__ uint32_t smaddr(const void* p) {
    return (uint32_t)__cvta_generic_to_shared(p);
}
__device__ __forceinline__ uint32_t pack_bf16(__nv_bfloat16 a, __nv_bfloat16 b) {
    return (uint32_t)__bfloat16_as_ushort(a) | ((uint32_t)__bfloat16_as_ushort(b) << 16);
}
__device__ __forceinline__ float gelu_exact(float v) {
    return 0.5f * v * (1.0f + erff(v * 0.70710678118654752f));
}

#if HAS_TC
// ---------------- tcgen05 / cg2 helpers ----------------
__device__ __forceinline__ uint32_t elect_one() {
    uint32_t pred;
    asm volatile("{\n\t.reg .pred p;\n\telect.sync _|p, 0xFFFFFFFF;\n\tselp.b32 %0, 1, 0, p;\n\t}"
                 : "=r"(pred));
    return pred;
}
__device__ __forceinline__ void cluster_sync_() {
    asm volatile("barrier.cluster.arrive.aligned;" ::: "memory");
    asm volatile("barrier.cluster.wait.aligned;" ::: "memory");
}
__device__ __forceinline__ void mbar_init(uint32_t addr, uint32_t cnt) {
    asm volatile("mbarrier.init.shared.b64 [%0], %1;" :: "r"(addr), "r"(cnt) : "memory");
}
__device__ __forceinline__ void mbar_inval(uint32_t addr) {
    asm volatile("mbarrier.inval.shared.b64 [%0];" :: "r"(addr) : "memory");
}
__device__ __forceinline__ void mbar_expect(uint32_t addr, uint32_t bytes) {
    asm volatile("mbarrier.arrive.expect_tx.shared.b64 _, [%0], %1;"
                 :: "r"(addr), "r"(bytes) : "memory");
}
__device__ __forceinline__ void mbar_wait(uint32_t addr, uint32_t parity) {
    asm volatile(
        "{\n\t.reg .pred P1;\n"
        "WAIT_%=:\n\t"
        "mbarrier.try_wait.parity.acquire.cta.shared::cta.b64 P1, [%0], %1, 0x989680;\n\t"
        "@P1 bra.uni DONE_%=;\n\t"
        "bra.uni WAIT_%=;\n"
        "DONE_%=:\n\t}"
        :: "r"(addr), "r"(parity) : "memory");
}
// cg2 TMA loads: both CTAs execute with local dst; complete_tx targets leader's barrier (bit24 cleared)
__device__ __forceinline__ void tma2d_cg2(uint32_t dst, const void* tm, int x, int y, uint32_t mbar) {
    asm volatile(
        "{\n\t.reg .b32 lb;\n\t"
        "and.b32 lb, %4, 0xFEFFFFFF;\n\t"
        "cp.async.bulk.tensor.2d.cta_group::2.shared::cluster.global.tile.mbarrier::complete_tx::bytes "
        "[%0], [%1, {%2, %3}], [lb];\n\t}"
        :: "r"(dst), "l"(tm), "r"(x), "r"(y), "r"(mbar) : "memory");
}
__device__ __forceinline__ void tma3d_cg2(uint32_t dst, const void* tm, int x, int y, int z, uint32_t mbar) {
    asm volatile(
        "{\n\t.reg .b32 lb;\n\t"
        "and.b32 lb, %5, 0xFEFFFFFF;\n\t"
        "cp.async.bulk.tensor.3d.cta_group::2.shared::cluster.global.tile.mbarrier::complete_tx::bytes "
        "[%0], [%1, {%2, %3, %4}], [lb];\n\t}"
        :: "r"(dst), "l"(tm), "r"(x), "r"(y), "r"(z), "r"(mbar) : "memory");
}
__device__ __forceinline__ void tc_mma_f16_ss2(uint32_t d, uint64_t a, uint64_t b,
                                               uint32_t idesc, uint32_t en) {
    asm volatile(
        "{\n\t.reg .pred p;\n\tsetp.ne.u32 p, %5, 0;\n\t"
        "tcgen05.mma.cta_group::2.kind::f16 [%0], %1, %2, %3, "
        "{%4, %4, %4, %4, %4, %4, %4, %4}, p;\n\t}"
        :: "r"(d), "l"(a), "l"(b), "r"(idesc), "r"(0u), "r"(en) : "memory");
}
__device__ __forceinline__ void tc_commit_mc2(uint32_t mbar) {
    asm volatile(
        "tcgen05.commit.cta_group::2.mbarrier::arrive::one.shared::cluster.multicast::cluster.b64 [%0], %1;"
        :: "r"(mbar), "h"((uint16_t)0x3) : "memory");
}
__device__ __forceinline__ void tc_alloc2(uint32_t smem_slot, uint32_t ncols) {
    asm volatile("tcgen05.alloc.cta_group::2.sync.aligned.shared::cta.b32 [%0], %1;"
                 :: "r"(smem_slot), "r"(ncols) : "memory");
}
__device__ __forceinline__ void tc_dealloc2(uint32_t tmem, uint32_t ncols) {
    asm volatile("tcgen05.dealloc.cta_group::2.sync.aligned.b32 %0, %1;" :: "r"(tmem), "r"(ncols));
}
__device__ __forceinline__ void tc_relinq2() {
    asm volatile("tcgen05.relinquish_alloc_permit.cta_group::2.sync.aligned;");
}
__device__ __forceinline__ void tc_fence_after() {
    asm volatile("tcgen05.fence::after_thread_sync;" ::: "memory");
}
__device__ __forceinline__ void tc_wait_ld() {
    asm volatile("tcgen05.wait::ld.sync.aligned;" ::: "memory");
}
__device__ __forceinline__ void tc_ld_x32(uint32_t* r, uint32_t addr) {
    asm volatile(
        "tcgen05.ld.sync.aligned.32x32b.x32.b32 "
        "{%0, %1, %2, %3, %4, %5, %6, %7, %8, %9, %10, %11, %12, %13, %14, %15, "
        " %16, %17, %18, %19, %20, %21, %22, %23, %24, %25, %26, %27, %28, %29, %30, %31}, [%32];"
        : "=r"(r[0]), "=r"(r[1]), "=r"(r[2]), "=r"(r[3]), "=r"(r[4]), "=r"(r[5]), "=r"(r[6]), "=r"(r[7]),
          "=r"(r[8]), "=r"(r[9]), "=r"(r[10]), "=r"(r[11]), "=r"(r[12]), "=r"(r[13]), "=r"(r[14]), "=r"(r[15]),
          "=r"(r[16]), "=r"(r[17]), "=r"(r[18]), "=r"(r[19]), "=r"(r[20]), "=r"(r[21]), "=r"(r[22]), "=r"(r[23]),
          "=r"(r[24]), "=r"(r[25]), "=r"(r[26]), "=r"(r[27]), "=r"(r[28]), "=r"(r[29]), "=r"(r[30]), "=r"(r[31])
        : "r"(addr));
}
// SW128 K-major descriptor base (LBO=1, SBO=64, version=1, layout SW128)
__device__ __forceinline__ uint64_t mk_desc(uint32_t addr) {
    const uint64_t DBASE = (2ULL << 61) | (1ULL << 46) | (64ULL << 32) | (1ULL << 16);
    return DBASE | (uint64_t)((addr >> 4) & 0x3FFF);
}
#endif  // HAS_TC

#if !HAS_TC
// ---------------- fallback-path helpers (mma.sync) ----------------
__device__ __forceinline__ void ldsm4(uint32_t* r, uint32_t addr) {
    asm volatile("ldmatrix.sync.aligned.m8n8.x4.shared.b16 {%0,%1,%2,%3}, [%4];\n"
                 : "=r"(r[0]), "=r"(r[1]), "=r"(r[2]), "=r"(r[3]) : "r"(addr));
}
__device__ __forceinline__ void ldsm4t(uint32_t* r, uint32_t addr) {
    asm volatile("ldmatrix.sync.aligned.m8n8.x4.trans.shared.b16 {%0,%1,%2,%3}, [%4];\n"
                 : "=r"(r[0]), "=r"(r[1]), "=r"(r[2]), "=r"(r[3]) : "r"(addr));
}
__device__ __forceinline__ void mma16816(float* c, const uint32_t* a, const uint32_t* b) {
    asm volatile(
        "mma.sync.aligned.m16n8k16.row.col.f32.bf16.bf16.f32 "
        "{%0,%1,%2,%3}, {%4,%5,%6,%7}, {%8,%9}, {%0,%1,%2,%3};\n"
        : "+f"(c[0]), "+f"(c[1]), "+f"(c[2]), "+f"(c[3])
        : "r"(a[0]), "r"(a[1]), "r"(a[2]), "r"(a[3]), "r"(b[0]), "r"(b[1]));
}
#endif  // !HAS_TC

// ---------------- kernel: gating (routing only) ----------------
__global__ __launch_bounds__(256) void gate_kernel(const float* __restrict__ x,
                                                   const float* __restrict__ gw) {
    const int tk = blockIdx.x;
    const int tid = threadIdx.x;
    const float* xr = x + (size_t)tk * DM;

    float p[NE];
#pragma unroll
    for (int e = 0; e < NE; ++e) p[e] = 0.f;
#pragma unroll
    for (int j = 0; j < 4; ++j) {
        int i = j * 256 + tid;
        float v = xr[i];
#pragma unroll
        for (int e = 0; e < NE; ++e) p[e] += v * gw[e * DM + i];
    }
#pragma unroll
    for (int e = 0; e < NE; ++e)
#pragma unroll
        for (int o = 16; o > 0; o >>= 1) p[e] += __shfl_xor_sync(0xffffffffu, p[e], o);

    __shared__ float sRed[8][NE];
    int lane = tid & 31, w = tid >> 5;
    if (lane == 0) {
#pragma unroll
        for (int e = 0; e < NE; ++e) sRed[w][e] = p[e];
    }
    __syncthreads();
    if (tid == 0) {
        float lg[NE];
#pragma unroll
        for (int e = 0; e < NE; ++e) {
            float s = 0.f;
#pragma unroll
            for (int ww = 0; ww < 8; ++ww) s += sRed[ww][e];
            lg[e] = s;
        }
        float m = lg[0];
#pragma unroll
        for (int e = 1; e < NE; ++e) m = fmaxf(m, lg[e]);
        float ex[NE], S = 0.f;
#pragma unroll
        for (int e = 0; e < NE; ++e) { ex[e] = expf(lg[e] - m); S += ex[e]; }
        int i0 = 0;
#pragma unroll
        for (int e = 1; e < NE; ++e) if (ex[e] > ex[i0]) i0 = e;
        int i1 = (i0 == 0) ? 1 : 0;
#pragma unroll
        for (int e = 0; e < NE; ++e) if (e != i0 && ex[e] > ex[i1]) i1 = e;
        float p0 = ex[i0] / S, p1 = ex[i1] / S;
        float den = p0 + p1 + 1e-9f;
        g_pair_e[2 * tk] = i0;     g_pair_w[2 * tk] = p0 / den;
        g_pair_e[2 * tk + 1] = i1; g_pair_w[2 * tk + 1] = p1 / den;
    }
}

// ---------------- kernel: counting sort (counts + scan + 256-row tiles + scatter) ----------------
__global__ __launch_bounds__(256) void sortscan_kernel() {
    __shared__ uint16_t loc[256][NE];
    __shared__ int s_cnt[NE];
    __shared__ int s_off[NE];
    const int t = threadIdx.x;
    const int p0 = t * 64;

    int lc[NE];
#pragma unroll
    for (int e = 0; e < NE; ++e) lc[e] = 0;
    for (int i = 0; i < 64; ++i) lc[g_pair_e[p0 + i]]++;
#pragma unroll
    for (int e = 0; e < NE; ++e) loc[t][e] = (uint16_t)lc[e];
    __syncthreads();

    if (t < NE) {
        int run = 0;
        for (int i = 0; i < 256; ++i) {
            int c = loc[i][t];
            loc[i][t] = (uint16_t)run;
            run += c;
        }
        s_cnt[t] = run;
        g_counts[t] = run;
    }
    __syncthreads();

    if (t == 0) {
        int off = 0, nt = 0;
        for (int e = 0; e < NE; ++e) {
            g_off[e] = off;
            s_off[e] = off;
            int c = s_cnt[e];
            int tiles = (c + 255) >> 8;
            for (int i = 0; i < tiles; ++i) {
                g_tile_e[nt] = e;
                g_tile_r0[nt] = off + i * 256;
                int v = c - i * 256;
                g_tile_valid[nt] = v > 256 ? 256 : v;
                ++nt;
            }
            off += c;
        }
        g_off[NE] = off;
        g_num_tiles = nt;
    }
    __syncthreads();

    int run[NE];
#pragma unroll
    for (int e = 0; e < NE; ++e) run[e] = s_off[e] + (int)loc[t][e];
    for (int i = 0; i < 64; ++i) {
        int p = p0 + i;
        int e = g_pair_e[p];
        int slot = run[e]++;
        g_pair_slot[p] = slot;
        g_rows_token[slot] = p >> 1;
    }
}

// ---------------- kernel: prep = A-gather (z==16) + weight split/transpose (z<16) ----------------
__global__ __launch_bounds__(256) void prep_kernel(const float* __restrict__ x,
                                                   const float* __restrict__ w1,
                                                   const float* __restrict__ w2) {
    const int z = blockIdx.z;
    const int t = threadIdx.x;

    if (z == 16) {
        const int b = blockIdx.y * 64 + blockIdx.x;
        for (int rr = 0; rr < 16; ++rr) {
            const int slot = b * 16 + rr;
            const int tok = g_rows_token[slot];
            const float4 v = reinterpret_cast<const float4*>(x + (size_t)tok * DM)[t];
            __nv_bfloat16 h0 = __float2bfloat16_rn(v.x), h1 = __float2bfloat16_rn(v.y);
            __nv_bfloat16 h2 = __float2bfloat16_rn(v.z), h3 = __float2bfloat16_rn(v.w);
            __nv_bfloat16 l0 = __float2bfloat16_rn(v.x - __bfloat162float(h0));
            __nv_bfloat16 l1 = __float2bfloat16_rn(v.y - __bfloat162float(h1));
            __nv_bfloat16 l2 = __float2bfloat16_rn(v.z - __bfloat162float(h2));
            __nv_bfloat16 l3 = __float2bfloat16_rn(v.w - __bfloat162float(h3));
            reinterpret_cast<uint2*>(g_Ah + (size_t)slot * DM)[t] =
                make_uint2(pack_bf16(h0, h1), pack_bf16(h2, h3));
            reinterpret_cast<uint2*>(g_Al + (size_t)slot * DM)[t] =
                make_uint2(pack_bf16(l0, l1), pack_bf16(l2, l3));
        }
        return;
    }

#if HAS_TC
    __shared__ float tile[64][65];
    const int layer = z >> 3;
    const int e = z & 7;
    const int K = layer ? DF : DM;
    const int N = layer ? DM : DF;
    const int K0 = (layer ? blockIdx.x : blockIdx.y) * 64;
    const int N0 = (layer ? blockIdx.y : blockIdx.x) * 64;
    const float* W = layer ? w2 : w1;
    __nv_bfloat16* Wh = layer ? g_w2h : g_w1h;
    __nv_bfloat16* Wl = layer ? g_w2l : g_w1l;

    const float* src = W + ((size_t)e * K + K0) * N + N0;
    const int r = t >> 4, c4 = (t & 15) * 4;
#pragma unroll
    for (int j = 0; j < 4; ++j) {
        int rr = r + j * 16;
        const float4 v = *reinterpret_cast<const float4*>(src + (size_t)rr * N + c4);
        tile[rr][c4 + 0] = v.x; tile[rr][c4 + 1] = v.y;
        tile[rr][c4 + 2] = v.z; tile[rr][c4 + 3] = v.w;
    }
    __syncthreads();
#pragma unroll
    for (int j = 0; j < 4; ++j) {
        int nn = r + j * 16;
        float v0 = tile[c4 + 0][nn], v1 = tile[c4 + 1][nn];
        float v2 = tile[c4 + 2][nn], v3 = tile[c4 + 3][nn];
        __nv_bfloat16 h0 = __float2bfloat16_rn(v0), h1 = __float2bfloat16_rn(v1);
        __nv_bfloat16 h2 = __float2bfloat16_rn(v2), h3 = __float2bfloat16_rn(v3);
        __nv_bfloat16 l0 = __float2bfloat16_rn(v0 - __bfloat162float(h0));
        __nv_bfloat16 l1 = __float2bfloat16_rn(v1 - __bfloat162float(h1));
        __nv_bfloat16 l2 = __float2bfloat16_rn(v2 - __bfloat162float(h2));
        __nv_bfloat16 l3 = __float2bfloat16_rn(v3 - __bfloat162float(h3));
        size_t out = ((size_t)e * N + N0 + nn) * K + K0 + c4;
        *reinterpret_cast<uint2*>(Wh + out) = make_uint2(pack_bf16(h0, h1), pack_bf16(h2, h3));
        *reinterpret_cast<uint2*>(Wl + out) = make_uint2(pack_bf16(l0, l1), pack_bf16(l2, l3));
    }
#endif
}

// ---------------- tcgen05 cg2 GEMM ----------------
// Cluster (2,1,1) along x. Pair computes M=256 x N=256; each CTA: A half (128 rows) + B half (128 cols).
// 3 stages x 64KB/CTA, K=64 per stage. 3-pass hi/lo bf16.
#define BUF_STRIDE 65536
#define OFF_AL 16384
#define OFF_BH 32768
#define OFF_BL 49152
#define OFF_TMEM 196608
#define OFF_MBAR 196624
#define SMEM_DYN 198656
#define STAGE_BYTES 65536u

// idesc cg2: F32 accum, BF16 a/b, K-major, N=256, M_total=256
#define GEMM_IDESC2 ((1u << 4) | (1u << 7) | (1u << 10) | ((256u / 8) << 17) | ((256u / 16) << 24))

template <bool FIRST>
__global__ __launch_bounds__(256)
void moe_gemm_tc(const __grid_constant__ CUtensorMap tmAh,
                 const __grid_constant__ CUtensorMap tmAl,
                 const __grid_constant__ CUtensorMap tmBh,
                 const __grid_constant__ CUtensorMap tmBl,
                 const float* __restrict__ bias) {
#if HAS_TC
    constexpr int KTOT = FIRST ? DM : DF;
    constexpr int NTOT = FIRST ? DF : DM;
    constexpr int NC = KTOT / 64;

    const int tileIdx = blockIdx.y;
    if (tileIdx >= g_num_tiles) return;
    const int rank = blockIdx.x & 1;
    const int e = g_tile_e[tileIdx];
    const int row0 = g_tile_r0[tileIdx];
    const int vrows = g_tile_valid[tileIdx];
    const int n0 = (blockIdx.x >> 1) * 256;

    extern __shared__ char dyn[];
    const uint32_t raw = smaddr(dyn);
    const uint32_t sbase = (raw + 1023u) & ~1023u;
    const int t = threadIdx.x;
    const int w = t >> 5, lane = t & 31;

    if (w == 0) {
        tc_alloc2(sbase + OFF_TMEM, 256);
        tc_relinq2();
    }
    if (t == 0) {
#pragma unroll
        for (int s = 0; s < 6; ++s) mbar_init(sbase + OFF_MBAR + s * 8, 1);
    }
    __syncthreads();
    // all inits (both CTAs) must precede any cg2 TMA / multicast commit
    cluster_sync_();

    uint32_t tmem;
    asm volatile("ld.shared.b32 %0, [%1];" : "=r"(tmem) : "r"(sbase + OFF_TMEM));

    uint64_t dA[3], dAl_[3], dB[3], dBl_[3];
#pragma unroll
    for (int s = 0; s < 3; ++s) {
        uint32_t b = sbase + s * BUF_STRIDE;
        dA[s]   = mk_desc(b);
        dAl_[s] = mk_desc(b + OFF_AL);
        dB[s]   = mk_desc(b + OFF_BH);
        dBl_[s] = mk_desc(b + OFF_BL);
    }

    if (w == 0 && elect_one()) {
        const uint32_t mbF = sbase + OFF_MBAR;        // full[0..2] (leader-side accounting)
        const uint32_t mbM = sbase + OFF_MBAR + 24;   // mmaDone[0..2] (multicast, local copies)
        const int arow = row0 + rank * 128;
        const int bcol = n0 + rank * 128;

        auto issue = [&](int i) {
            const int b = i % 3;
            const uint32_t bb = sbase + (uint32_t)b * BUF_STRIDE;
            const int k0 = i * 64;
            if (rank == 0) mbar_expect(mbF + b * 8, 2u * STAGE_BYTES);
            tma2d_cg2(bb,          (const void*)&tmAh, k0, arow, mbF + b * 8);
            tma2d_cg2(bb + OFF_AL, (const void*)&tmAl, k0, arow, mbF + b * 8);
            tma3d_cg2(bb + OFF_BH, (const void*)&tmBh, k0, bcol, e, mbF + b * 8);
            tma3d_cg2(bb + OFF_BL, (const void*)&tmBl, k0, bcol, e, mbF + b * 8);
        };

        issue(0); issue(1); issue(2);

        uint32_t pF[3] = {0, 0, 0}, pM[3] = {0, 0, 0};
#pragma unroll 1
        for (int i = 0; i < NC; ++i) {
            const int b = i % 3;
            if (rank == 0) {
                mbar_wait(mbF + b * 8, pF[b]); pF[b] ^= 1;
#pragma unroll
                for (int ks = 0; ks < 4; ++ks) {
                    const uint64_t oa = (uint64_t)(ks * 2);
                    const uint32_t en0 = (i == 0 && ks == 0) ? 0u : 1u;
                    tc_mma_f16_ss2(tmem, dA[b] + oa,   dB[b] + oa,   GEMM_IDESC2, en0);
                    tc_mma_f16_ss2(tmem, dA[b] + oa,   dBl_[b] + oa, GEMM_IDESC2, 1u);
                    tc_mma_f16_ss2(tmem, dAl_[b] + oa, dB[b] + oa,   GEMM_IDESC2, 1u);
                }
                tc_commit_mc2(mbM + b * 8);
            }
            if (i + 3 < NC) {
                mbar_wait(mbM + b * 8, pM[b]); pM[b] ^= 1;
                issue(i + 3);
            }
        }
        // drain mmaDone for last 3 stages (both ranks; multicast delivered locally)
#pragma unroll
        for (int q = 3; q >= 1; --q) {
            const int b = (NC - q) % 3;
            mbar_wait(mbM + b * 8, pM[b]);
            pM[b] ^= 1;
        }
    }
    __syncthreads();
    tc_fence_after();

    // ---------------- epilogue (per CTA: its 128 rows x 256 cols) ----------------
    const int rloc = (w & 3) * 32 + lane;
    const int cbase = (w >> 2) * 128;
    int vr = vrows - rank * 128;
    vr = vr < 0 ? 0 : (vr > 128 ? 128 : vr);
    const bool valid = rloc < vr;
    const int rowg = row0 + rank * 128 + rloc;
    const float* bn = bias + (size_t)e * NTOT + n0 + cbase;

#pragma unroll
    for (int j = 0; j < 4; ++j) {
        uint32_t dr[32];
        tc_ld_x32(dr, tmem + cbase + j * 32);
        tc_wait_ld();
        if (valid) {
            int nb = cbase + j * 32;
            if (FIRST) {
                __nv_bfloat16* oH = g_Hh + (size_t)rowg * DF + n0 + nb;
                __nv_bfloat16* oL = g_Hl + (size_t)rowg * DF + n0 + nb;
#pragma unroll
                for (int c = 0; c < 32; c += 2) {
                    float v0 = gelu_exact(__uint_as_float(dr[c]) + bn[j * 32 + c]);
                    float v1 = gelu_exact(__uint_as_float(dr[c + 1]) + bn[j * 32 + c + 1]);
                    __nv_bfloat16 h0 = __float2bfloat16_rn(v0);
                    __nv_bfloat16 h1 = __float2bfloat16_rn(v1);
                    *reinterpret_cast<uint32_t*>(oH + c) = pack_bf16(h0, h1);
                    __nv_bfloat16 l0 = __float2bfloat16_rn(v0 - __bfloat162float(h0));
                    __nv_bfloat16 l1 = __float2bfloat16_rn(v1 - __bfloat162float(h1));
                    *reinterpret_cast<uint32_t*>(oL + c) = pack_bf16(l0, l1);
                }
            } else {
                float* oY = g_Y + (size_t)rowg * DM + n0 + nb;
#pragma unroll
                for (int c = 0; c < 32; c += 2) {
                    float v0 = __uint_as_float(dr[c]) + bn[j * 32 + c];
                    float v1 = __uint_as_float(dr[c + 1]) + bn[j * 32 + c + 1];
                    *reinterpret_cast<float2*>(oY + c) = make_float2(v0, v1);
                }
            }
        }
    }

    __syncthreads();
    if (t == 0) {
#pragma unroll
        for (int s = 0; s < 6; ++s) mbar_inval(sbase + OFF_MBAR + s * 8);
    }
    __syncthreads();
    cluster_sync_();
    if (w == 0) tc_dealloc2(tmem, 256);
    cluster_sync_();
#endif  // HAS_TC
}

// ---------------- fallback GEMM (mma.sync; 256-tiles split in half) ----------------
template <bool FIRST>
__global__ __launch_bounds__(256) void moe_gemm_fb(const float* __restrict__ W,
                                                   const float* __restrict__ bias) {
#if !HAS_TC
    constexpr int KTOT = FIRST ? DM : DF;
    constexpr int LDW  = FIRST ? DF : DM;
    const int tileIdx = blockIdx.y >> 1;
    if (tileIdx >= g_num_tiles) return;
    const int half = blockIdx.y & 1;
    const int e = g_tile_e[tileIdx];
    const int row0 = g_tile_r0[tileIdx] + half * 128;
    int vrows = g_tile_valid[tileIdx] - half * 128;
    vrows = vrows < 0 ? 0 : (vrows > 128 ? 128 : vrows);
    if (vrows == 0) return;
    const int n0 = blockIdx.x * 128;
    const float* Wn = W + (size_t)e * KTOT * LDW + n0;
    const float* bn = bias + (size_t)e * LDW + n0;

    __shared__ __align__(16) __nv_bfloat16 sAh[128 * 40];
    __shared__ __align__(16) __nv_bfloat16 sAl[128 * 40];
    __shared__ __align__(16) __nv_bfloat16 sBh[32 * 136];
    __shared__ __align__(16) __nv_bfloat16 sBl[32 * 136];

    const int t = threadIdx.x;
    float c[4][4][4];
#pragma unroll
    for (int a = 0; a < 4; ++a)
#pragma unroll
        for (int b = 0; b < 4; ++b)
#pragma unroll
            for (int q = 0; q < 4; ++q) c[a][b][q] = 0.f;

    const int lane = t & 31, warp = t >> 5;
    const int wm = warp >> 2, wn = warp & 3;
    const int m0 = wm * 64;
    const int sub = t & 15, rgrp = t >> 4;

    for (int k0 = 0; k0 < KTOT; k0 += 32) {
        __syncthreads();
#pragma unroll
        for (int rr = 0; rr < 8; ++rr) {
            int r = rr * 16 + rgrp;
            int rg = row0 + r; if (rg > PAIRS - 1) rg = PAIRS - 1;
            const uint32_t* ph = reinterpret_cast<const uint32_t*>(
                (FIRST ? g_Ah : g_Hh) + (size_t)rg * KTOT + k0);
            const uint32_t* pl = reinterpret_cast<const uint32_t*>(
                (FIRST ? g_Al : g_Hl) + (size_t)rg * KTOT + k0);
            *reinterpret_cast<uint32_t*>(&sAh[r * 40 + sub * 2]) = ph[sub];
            *reinterpret_cast<uint32_t*>(&sAl[r * 40 + sub * 2]) = pl[sub];
        }
#pragma unroll
        for (int i = 0; i < 4; ++i) {
            int lin = (i * 256 + t) * 4;
            int kr = lin >> 7;
            int nc = lin & 127;
            const float4 v = *reinterpret_cast<const float4*>(Wn + (size_t)(k0 + kr) * LDW + nc);
            __nv_bfloat16 h0 = __float2bfloat16_rn(v.x);
            __nv_bfloat16 h1 = __float2bfloat16_rn(v.y);
            __nv_bfloat16 h2 = __float2bfloat16_rn(v.z);
            __nv_bfloat16 h3 = __float2bfloat16_rn(v.w);
            __nv_bfloat16 l0 = __float2bfloat16_rn(v.x - __bfloat162float(h0));
            __nv_bfloat16 l1 = __float2bfloat16_rn(v.y - __bfloat162float(h1));
            __nv_bfloat16 l2 = __float2bfloat16_rn(v.z - __bfloat162float(h2));
            __nv_bfloat16 l3 = __float2bfloat16_rn(v.w - __bfloat162float(h3));
            *reinterpret_cast<uint2*>(&sBh[kr * 136 + nc]) = make_uint2(pack_bf16(h0, h1), pack_bf16(h2, h3));
            *reinterpret_cast<uint2*>(&sBl[kr * 136 + nc]) = make_uint2(pack_bf16(l0, l1), pack_bf16(l2, l3));
        }
        __syncthreads();

#pragma unroll
        for (int ks = 0; ks < 2; ++ks) {
            uint32_t ah[4][4], al[4][4], bh[4][2], bl[4][2];
            {
                int ar = lane & 15;
                int acol = ks * 16 + (lane >> 4) * 8;
#pragma unroll
                for (int fm = 0; fm < 4; ++fm) {
                    ldsm4(ah[fm], smaddr(&sAh[(m0 + fm * 16 + ar) * 40 + acol]));
                    ldsm4(al[fm], smaddr(&sAl[(m0 + fm * 16 + ar) * 40 + acol]));
                }
                int brow = ks * 16 + (lane & 15);
                int bcol = wn * 32 + (lane >> 4) * 8;
#pragma unroll
                for (int hb = 0; hb < 2; ++hb) {
                    uint32_t r[4];
                    ldsm4t(r, smaddr(&sBh[brow * 136 + bcol + hb * 16]));
                    bh[2 * hb][0] = r[0]; bh[2 * hb][1] = r[1];
                    bh[2 * hb + 1][0] = r[2]; bh[2 * hb + 1][1] = r[3];
                    ldsm4t(r, smaddr(&sBl[brow * 136 + bcol + hb * 16]));
                    bl[2 * hb][0] = r[0]; bl[2 * hb][1] = r[1];
                    bl[2 * hb + 1][0] = r[2]; bl[2 * hb + 1][1] = r[3];
                }
            }
#pragma unroll
            for (int fm = 0; fm < 4; ++fm)
#pragma unroll
                for (int fn = 0; fn < 4; ++fn) {
                    mma16816(c[fm][fn], ah[fm], bh[fn]);
                    mma16816(c[fm][fn], ah[fm], bl[fn]);
                    mma16816(c[fm][fn], al[fm], bh[fn]);
                }
        }
    }

    const int lgrp = lane >> 2, lq = lane & 3;
#pragma unroll
    for (int fm = 0; fm < 4; ++fm) {
        int rl = m0 + fm * 16 + lgrp;
#pragma unroll
        for (int fn = 0; fn < 4; ++fn) {
            int nc = wn * 32 + fn * 8 + lq * 2;
            float bv0 = bn[nc], bv1 = bn[nc + 1];
            float* cc = c[fm][fn];
#pragma unroll
            for (int h = 0; h < 2; ++h) {
                int rloc = rl + h * 8;
                if (rloc < vrows) {
                    int row = row0 + rloc;
                    float v0 = cc[h * 2 + 0] + bv0;
                    float v1 = cc[h * 2 + 1] + bv1;
                    if (FIRST) {
                        v0 = gelu_exact(v0);
                        v1 = gelu_exact(v1);
                        __nv_bfloat16 h0 = __float2bfloat16_rn(v0);
                        __nv_bfloat16 h1 = __float2bfloat16_rn(v1);
                        *reinterpret_cast<uint32_t*>(&g_Hh[(size_t)row * DF + n0 + nc]) = pack_bf16(h0, h1);
                        __nv_bfloat16 l0 = __float2bfloat16_rn(v0 - __bfloat162float(h0));
                        __nv_bfloat16 l1 = __float2bfloat16_rn(v1 - __bfloat162float(h1));
                        *reinterpret_cast<uint32_t*>(&g_Hl[(size_t)row * DF + n0 + nc]) = pack_bf16(l0, l1);
                    } else {
                        *reinterpret_cast<float2*>(&g_Y[(size_t)row * DM + n0 + nc]) = make_float2(v0, v1);
                    }
                }
            }
        }
    }
#endif  // !HAS_TC
}

// ---------------- kernel: weighted combine ----------------
__global__ __launch_bounds__(256) void combine_kernel(float* __restrict__ out) {
    const int tk = blockIdx.x;
    const int d = threadIdx.x * 4;
    int s0 = g_pair_slot[2 * tk], s1 = g_pair_slot[2 * tk + 1];
    float w0 = g_pair_w[2 * tk], w1 = g_pair_w[2 * tk + 1];
    const float4 a = *reinterpret_cast<const float4*>(&g_Y[(size_t)s0 * DM + d]);
    const float4 b = *reinterpret_cast<const float4*>(&g_Y[(size_t)s1 * DM + d]);
    float4 o;
    o.x = w0 * a.x + w1 * b.x;
    o.y = w0 * a.y + w1 * b.y;
    o.z = w0 * a.z + w1 * b.z;
    o.w = w0 * a.w + w1 * b.w;
    *reinterpret_cast<float4*>(&out[(size_t)tk * DM + d]) = o;
}

// ---------------- host: tensor map construction ----------------
typedef CUresult (*TmEncodeFn)(CUtensorMap*, CUtensorMapDataType, cuuint32_t, void*,
                               const cuuint64_t*, const cuuint64_t*, const cuuint32_t*,
                               const cuuint32_t*, CUtensorMapInterleave, CUtensorMapSwizzle,
                               CUtensorMapL2promotion, CUtensorMapFloatOOBfill);

static void tm2d(TmEncodeFn enc, CUtensorMap* tm, void* base, unsigned long long K,
                 unsigned long long R) {
    cuuint64_t dims[2] = {K, R};
    cuuint64_t st[1] = {K * 2};
    cuuint32_t box[2] = {64, 128};
    cuuint32_t es[2] = {1, 1};
    enc(tm, CU_TENSOR_MAP_DATA_TYPE_BFLOAT16, 2, base, dims, st, box, es,
        CU_TENSOR_MAP_INTERLEAVE_NONE, CU_TENSOR_MAP_SWIZZLE_128B,
        CU_TENSOR_MAP_L2_PROMOTION_L2_128B, CU_TENSOR_MAP_FLOAT_OOB_FILL_NONE);
}
static void tm3d(TmEncodeFn enc, CUtensorMap* tm, void* base, unsigned long long K,
                 unsigned long long N) {
    cuuint64_t dims[3] = {K, N, NE};
    cuuint64_t st[2] = {K * 2, N * K * 2};
    cuuint32_t box[3] = {64, 128, 1};   // per-CTA B half (cg2 N-split)
    cuuint32_t es[3] = {1, 1, 1};
    enc(tm, CU_TENSOR_MAP_DATA_TYPE_BFLOAT16, 3, base, dims, st, box, es,
        CU_TENSOR_MAP_INTERLEAVE_NONE, CU_TENSOR_MAP_SWIZZLE_128B,
        CU_TENSOR_MAP_L2_PROMOTION_L2_128B, CU_TENSOR_MAP_FLOAT_OOB_FILL_NONE);
}

// ---------------- launch ----------------
extern "C" void kernel_launch(void* const* d_in, const int* in_sizes, int n_in,
                              void* d_out, int out_size) {
    const float* x  = (const float*)d_in[0];
    const float* gw = (const float*)d_in[1];
    const float* w1 = (const float*)d_in[2];
    const float* b1 = (const float*)d_in[3];
    const float* w2 = (const float*)d_in[4];
    const float* b2 = (const float*)d_in[5];
    float* out = (float*)d_out;

    cudaFuncSetAttribute(moe_gemm_tc<true>,  cudaFuncAttributeMaxDynamicSharedMemorySize, SMEM_DYN);
    cudaFuncSetAttribute(moe_gemm_tc<false>, cudaFuncAttributeMaxDynamicSharedMemorySize, SMEM_DYN);

    void *pAh, *pAl, *pHh, *pHl, *pW1h, *pW1l, *pW2h, *pW2l;
    cudaGetSymbolAddress(&pAh, g_Ah);
    cudaGetSymbolAddress(&pAl, g_Al);
    cudaGetSymbolAddress(&pHh, g_Hh);
    cudaGetSymbolAddress(&pHl, g_Hl);
    cudaGetSymbolAddress(&pW1h, g_w1h);
    cudaGetSymbolAddress(&pW1l, g_w1l);
    cudaGetSymbolAddress(&pW2h, g_w2h);
    cudaGetSymbolAddress(&pW2l, g_w2l);

    void* sym = nullptr;
    cudaDriverEntryPointQueryResult qr;
    cudaGetDriverEntryPoint("cuTensorMapEncodeTiled", &sym, cudaEnableDefault, &qr);
    TmEncodeFn enc = (TmEncodeFn)sym;

    CUtensorMap tAh, tAl, tB1h, tB1l, tHh, tHl, tB2h, tB2l;
    if (enc) {
        tm2d(enc, &tAh, pAh, DM, PAIRS);
        tm2d(enc, &tAl, pAl, DM, PAIRS);
        tm3d(enc, &tB1h, pW1h, DM, DF);
        tm3d(enc, &tB1l, pW1l, DM, DF);
        tm2d(enc, &tHh, pHh, DF, PAIRS);
        tm2d(enc, &tHl, pHl, DF, PAIRS);
        tm3d(enc, &tB2h, pW2h, DF, DM);
        tm3d(enc, &tB2l, pW2l, DF, DM);
    }

    gate_kernel<<<T_TOKENS, 256>>>(x, gw);                                     // idx 0
    sortscan_kernel<<<1, 256>>>();                                             // idx 1
    prep_kernel<<<dim3(64, 16, 17), 256>>>(x, w1, w2);                         // idx 2

    // cluster launch config (2 CTAs along x)
    cudaLaunchAttribute cat[1];
    cat[0].id = cudaLaunchAttributeClusterDimension;
    cat[0].val.clusterDim.x = 2;
    cat[0].val.clusterDim.y = 1;
    cat[0].val.clusterDim.z = 1;

    {
        cudaLaunchConfig_t cfg = {};
        cfg.gridDim = dim3((DF / 256) * 2, MAXT2, 1);
        cfg.blockDim = dim3(256, 1, 1);
        cfg.dynamicSmemBytes = SMEM_DYN;
        cfg.stream = 0;
        cfg.attrs = cat;
        cfg.numAttrs = 1;
        cudaLaunchKernelEx(&cfg, moe_gemm_tc<true>, tAh, tAl, tB1h, tB1l, b1);  // idx 3
    }
    moe_gemm_fb<true><<<dim3(DF / 128, MAXT2 * 2), 256>>>(w1, b1);              // idx 4 (no-op on tc build)
    {
        cudaLaunchConfig_t cfg = {};
        cfg.gridDim = dim3((DM / 256) * 2, MAXT2, 1);
        cfg.blockDim = dim3(256, 1, 1);
        cfg.dynamicSmemBytes = SMEM_DYN;
        cfg.stream = 0;
        cfg.attrs = cat;
        cfg.numAttrs = 1;
        cudaLaunchKernelEx(&cfg, moe_gemm_tc<false>, tHh, tHl, tB2h, tB2l, b2); // idx 5
    }
    moe_gemm_fb<false><<<dim3(DM / 128, MAXT2 * 2), 256>>>(w2, b2);             // idx 6
    combine_kernel<<<T_TOKENS, 256>>>(out);                                     // idx 7
}

// round 9
// speedup vs baseline: 1.1212x; 1.1212x over previous
#include <cuda_runtime.h>
#include <cuda.h>
#include <cuda_bf16.h>
#include <stdint.h>

#define T_TOKENS 8192
#define DM 1024
#define DF 4096
#define NE 8
#define PAIRS 16384
#define MAXTILES 144
#define MAXT2 72

// tcgen05 availability: only in the arch-SPECIFIC device pass (sm_103a / sm_100a).
#if defined(__CUDA_ARCH__) && (defined(__CUDA_ARCH_FEAT_SM103_ALL) || defined(__CUDA_ARCH_FEAT_SM100_ALL) || defined(__CUDA_ARCH_SPECIFIC__))
#define HAS_TC 1
#else
#define HAS_TC 0
#endif

// ---------------- scratch (device globals; no allocations) ----------------
__device__ __align__(128) __nv_bfloat16 g_Ah[(size_t)PAIRS * DM];
__device__ __align__(128) __nv_bfloat16 g_Al[(size_t)PAIRS * DM];
__device__ __align__(128) __nv_bfloat16 g_Hh[(size_t)PAIRS * DF];
__device__ __align__(128) __nv_bfloat16 g_Hl[(size_t)PAIRS * DF];
__device__ __align__(128) float         g_Y[(size_t)PAIRS * DM];

__device__ __align__(128) __nv_bfloat16 g_w1h[(size_t)NE * DM * DF];
__device__ __align__(128) __nv_bfloat16 g_w1l[(size_t)NE * DM * DF];
__device__ __align__(128) __nv_bfloat16 g_w2h[(size_t)NE * DF * DM];
__device__ __align__(128) __nv_bfloat16 g_w2l[(size_t)NE * DF * DM];

__device__ int   g_pair_e[PAIRS];
__device__ float g_pair_w[PAIRS];
__device__ int   g_pair_slot[PAIRS];
__device__ int   g_rows_token[PAIRS];

__device__ int g_counts[NE];
__device__ int g_off[NE + 1];
__device__ int g_tile_e[MAXTILES];
__device__ int g_tile_r0[MAXTILES];
__device__ int g_tile_valid[MAXTILES];
__device__ int g_num_tiles;

// ---------------- shared helpers ----------------
__device__ __forceinline__ uint32_t smaddr(const void* p) {
    return (uint32_t)__cvta_generic_to_shared(p);
}
__device__ __forceinline__ uint32_t pack_bf16(__nv_bfloat16 a, __nv_bfloat16 b) {
    return (uint32_t)__bfloat16_as_ushort(a) | ((uint32_t)__bfloat16_as_ushort(b) << 16);
}
__device__ __forceinline__ float gelu_exact(float v) {
    return 0.5f * v * (1.0f + erff(v * 0.70710678118654752f));
}

#if HAS_TC
// ---------------- tcgen05 / cg2 helpers ----------------
__device__ __forceinline__ uint32_t elect_one() {
    uint32_t pred;
    asm volatile("{\n\t.reg .pred p;\n\telect.sync _|p, 0xFFFFFFFF;\n\tselp.b32 %0, 1, 0, p;\n\t}"
                 : "=r"(pred));
    return pred;
}
__device__ __forceinline__ void cluster_sync_() {
    asm volatile("barrier.cluster.arrive.aligned;" ::: "memory");
    asm volatile("barrier.cluster.wait.aligned;" ::: "memory");
}
__device__ __forceinline__ void mbar_init(uint32_t addr, uint32_t cnt) {
    asm volatile("mbarrier.init.shared.b64 [%0], %1;" :: "r"(addr), "r"(cnt) : "memory");
}
__device__ __forceinline__ void mbar_inval(uint32_t addr) {
    asm volatile("mbarrier.inval.shared.b64 [%0];" :: "r"(addr) : "memory");
}
__device__ __forceinline__ void mbar_expect(uint32_t addr, uint32_t bytes) {
    asm volatile("mbarrier.arrive.expect_tx.shared.b64 _, [%0], %1;"
                 :: "r"(addr), "r"(bytes) : "memory");
}
__device__ __forceinline__ void mbar_wait(uint32_t addr, uint32_t parity) {
    asm volatile(
        "{\n\t.reg .pred P1;\n"
        "WAIT_%=:\n\t"
        "mbarrier.try_wait.parity.acquire.cta.shared::cta.b64 P1, [%0], %1, 0x989680;\n\t"
        "@P1 bra.uni DONE_%=;\n\t"
        "bra.uni WAIT_%=;\n"
        "DONE_%=:\n\t}"
        :: "r"(addr), "r"(parity) : "memory");
}
__device__ __forceinline__ void tma2d_cg2(uint32_t dst, const void* tm, int x, int y, uint32_t mbar) {
    asm volatile(
        "{\n\t.reg .b32 lb;\n\t"
        "and.b32 lb, %4, 0xFEFFFFFF;\n\t"
        "cp.async.bulk.tensor.2d.cta_group::2.shared::cluster.global.tile.mbarrier::complete_tx::bytes "
        "[%0], [%1, {%2, %3}], [lb];\n\t}"
        :: "r"(dst), "l"(tm), "r"(x), "r"(y), "r"(mbar) : "memory");
}
__device__ __forceinline__ void tma3d_cg2(uint32_t dst, const void* tm, int x, int y, int z, uint32_t mbar) {
    asm volatile(
        "{\n\t.reg .b32 lb;\n\t"
        "and.b32 lb, %5, 0xFEFFFFFF;\n\t"
        "cp.async.bulk.tensor.3d.cta_group::2.shared::cluster.global.tile.mbarrier::complete_tx::bytes "
        "[%0], [%1, {%2, %3, %4}], [lb];\n\t}"
        :: "r"(dst), "l"(tm), "r"(x), "r"(y), "r"(z), "r"(mbar) : "memory");
}
__device__ __forceinline__ void tc_mma_f16_ss2(uint32_t d, uint64_t a, uint64_t b,
                                               uint32_t idesc, uint32_t en) {
    asm volatile(
        "{\n\t.reg .pred p;\n\tsetp.ne.u32 p, %5, 0;\n\t"
        "tcgen05.mma.cta_group::2.kind::f16 [%0], %1, %2, %3, "
        "{%4, %4, %4, %4, %4, %4, %4, %4}, p;\n\t}"
        :: "r"(d), "l"(a), "l"(b), "r"(idesc), "r"(0u), "r"(en) : "memory");
}
__device__ __forceinline__ void tc_commit_mc2(uint32_t mbar) {
    asm volatile(
        "tcgen05.commit.cta_group::2.mbarrier::arrive::one.shared::cluster.multicast::cluster.b64 [%0], %1;"
        :: "r"(mbar), "h"((uint16_t)0x3) : "memory");
}
__device__ __forceinline__ void tc_alloc2(uint32_t smem_slot, uint32_t ncols) {
    asm volatile("tcgen05.alloc.cta_group::2.sync.aligned.shared::cta.b32 [%0], %1;"
                 :: "r"(smem_slot), "r"(ncols) : "memory");
}
__device__ __forceinline__ void tc_dealloc2(uint32_t tmem, uint32_t ncols) {
    asm volatile("tcgen05.dealloc.cta_group::2.sync.aligned.b32 %0, %1;" :: "r"(tmem), "r"(ncols));
}
__device__ __forceinline__ void tc_relinq2() {
    asm volatile("tcgen05.relinquish_alloc_permit.cta_group::2.sync.aligned;");
}
__device__ __forceinline__ void tc_fence_after() {
    asm volatile("tcgen05.fence::after_thread_sync;" ::: "memory");
}
__device__ __forceinline__ void tc_wait_ld() {
    asm volatile("tcgen05.wait::ld.sync.aligned;" ::: "memory");
}
__device__ __forceinline__ void tc_ld_x32(uint32_t* r, uint32_t addr) {
    asm volatile(
        "tcgen05.ld.sync.aligned.32x32b.x32.b32 "
        "{%0, %1, %2, %3, %4, %5, %6, %7, %8, %9, %10, %11, %12, %13, %14, %15, "
        " %16, %17, %18, %19, %20, %21, %22, %23, %24, %25, %26, %27, %28, %29, %30, %31}, [%32];"
        : "=r"(r[0]), "=r"(r[1]), "=r"(r[2]), "=r"(r[3]), "=r"(r[4]), "=r"(r[5]), "=r"(r[6]), "=r"(r[7]),
          "=r"(r[8]), "=r"(r[9]), "=r"(r[10]), "=r"(r[11]), "=r"(r[12]), "=r"(r[13]), "=r"(r[14]), "=r"(r[15]),
          "=r"(r[16]), "=r"(r[17]), "=r"(r[18]), "=r"(r[19]), "=r"(r[20]), "=r"(r[21]), "=r"(r[22]), "=r"(r[23]),
          "=r"(r[24]), "=r"(r[25]), "=r"(r[26]), "=r"(r[27]), "=r"(r[28]), "=r"(r[29]), "=r"(r[30]), "=r"(r[31])
        : "r"(addr));
}
// SW128 K-major descriptor base (LBO=1, SBO=64, version=1, layout SW128)
__device__ __forceinline__ uint64_t mk_desc(uint32_t addr) {
    const uint64_t DBASE = (2ULL << 61) | (1ULL << 46) | (64ULL << 32) | (1ULL << 16);
    return DBASE | (uint64_t)((addr >> 4) & 0x3FFF);
}
#endif  // HAS_TC

#if !HAS_TC
// ---------------- fallback-path helpers (mma.sync) ----------------
__device__ __forceinline__ void ldsm4(uint32_t* r, uint32_t addr) {
    asm volatile("ldmatrix.sync.aligned.m8n8.x4.shared.b16 {%0,%1,%2,%3}, [%4];\n"
                 : "=r"(r[0]), "=r"(r[1]), "=r"(r[2]), "=r"(r[3]) : "r"(addr));
}
__device__ __forceinline__ void ldsm4t(uint32_t* r, uint32_t addr) {
    asm volatile("ldmatrix.sync.aligned.m8n8.x4.trans.shared.b16 {%0,%1,%2,%3}, [%4];\n"
                 : "=r"(r[0]), "=r"(r[1]), "=r"(r[2]), "=r"(r[3]) : "r"(addr));
}
__device__ __forceinline__ void mma16816(float* c, const uint32_t* a, const uint32_t* b) {
    asm volatile(
        "mma.sync.aligned.m16n8k16.row.col.f32.bf16.bf16.f32 "
        "{%0,%1,%2,%3}, {%4,%5,%6,%7}, {%8,%9}, {%0,%1,%2,%3};\n"
        : "+f"(c[0]), "+f"(c[1]), "+f"(c[2]), "+f"(c[3])
        : "r"(a[0]), "r"(a[1]), "r"(a[2]), "r"(a[3]), "r"(b[0]), "r"(b[1]));
}
#endif  // !HAS_TC

// ---------------- kernel: gating (routing only) ----------------
__global__ __launch_bounds__(256) void gate_kernel(const float* __restrict__ x,
                                                   const float* __restrict__ gw) {
    const int tk = blockIdx.x;
    const int tid = threadIdx.x;
    const float* xr = x + (size_t)tk * DM;

    float p[NE];
#pragma unroll
    for (int e = 0; e < NE; ++e) p[e] = 0.f;
#pragma unroll
    for (int j = 0; j < 4; ++j) {
        int i = j * 256 + tid;
        float v = xr[i];
#pragma unroll
        for (int e = 0; e < NE; ++e) p[e] += v * gw[e * DM + i];
    }
#pragma unroll
    for (int e = 0; e < NE; ++e)
#pragma unroll
        for (int o = 16; o > 0; o >>= 1) p[e] += __shfl_xor_sync(0xffffffffu, p[e], o);

    __shared__ float sRed[8][NE];
    int lane = tid & 31, w = tid >> 5;
    if (lane == 0) {
#pragma unroll
        for (int e = 0; e < NE; ++e) sRed[w][e] = p[e];
    }
    __syncthreads();
    if (tid == 0) {
        float lg[NE];
#pragma unroll
        for (int e = 0; e < NE; ++e) {
            float s = 0.f;
#pragma unroll
            for (int ww = 0; ww < 8; ++ww) s += sRed[ww][e];
            lg[e] = s;
        }
        float m = lg[0];
#pragma unroll
        for (int e = 1; e < NE; ++e) m = fmaxf(m, lg[e]);
        float ex[NE], S = 0.f;
#pragma unroll
        for (int e = 0; e < NE; ++e) { ex[e] = expf(lg[e] - m); S += ex[e]; }
        int i0 = 0;
#pragma unroll
        for (int e = 1; e < NE; ++e) if (ex[e] > ex[i0]) i0 = e;
        int i1 = (i0 == 0) ? 1 : 0;
#pragma unroll
        for (int e = 0; e < NE; ++e) if (e != i0 && ex[e] > ex[i1]) i1 = e;
        float p0 = ex[i0] / S, p1 = ex[i1] / S;
        float den = p0 + p1 + 1e-9f;
        g_pair_e[2 * tk] = i0;     g_pair_w[2 * tk] = p0 / den;
        g_pair_e[2 * tk + 1] = i1; g_pair_w[2 * tk + 1] = p1 / den;
    }
}

// ---------------- kernel: counting sort (counts + scan + 256-row tiles + scatter) ----------------
__global__ __launch_bounds__(256) void sortscan_kernel() {
    __shared__ uint16_t loc[256][NE];
    __shared__ int s_cnt[NE];
    __shared__ int s_off[NE];
    const int t = threadIdx.x;
    const int p0 = t * 64;

    int lc[NE];
#pragma unroll
    for (int e = 0; e < NE; ++e) lc[e] = 0;
    for (int i = 0; i < 64; ++i) lc[g_pair_e[p0 + i]]++;
#pragma unroll
    for (int e = 0; e < NE; ++e) loc[t][e] = (uint16_t)lc[e];
    __syncthreads();

    if (t < NE) {
        int run = 0;
        for (int i = 0; i < 256; ++i) {
            int c = loc[i][t];
            loc[i][t] = (uint16_t)run;
            run += c;
        }
        s_cnt[t] = run;
        g_counts[t] = run;
    }
    __syncthreads();

    if (t == 0) {
        int off = 0, nt = 0;
        for (int e = 0; e < NE; ++e) {
            g_off[e] = off;
            s_off[e] = off;
            int c = s_cnt[e];
            int tiles = (c + 255) >> 8;
            for (int i = 0; i < tiles; ++i) {
                g_tile_e[nt] = e;
                g_tile_r0[nt] = off + i * 256;
                int v = c - i * 256;
                g_tile_valid[nt] = v > 256 ? 256 : v;
                ++nt;
            }
            off += c;
        }
        g_off[NE] = off;
        g_num_tiles = nt;
    }
    __syncthreads();

    int run[NE];
#pragma unroll
    for (int e = 0; e < NE; ++e) run[e] = s_off[e] + (int)loc[t][e];
    for (int i = 0; i < 64; ++i) {
        int p = p0 + i;
        int e = g_pair_e[p];
        int slot = run[e]++;
        g_pair_slot[p] = slot;
        g_rows_token[slot] = p >> 1;
    }
}

// ---------------- kernel: prep = A-gather (z==16) + weight split/transpose (z<16) ----------------
__global__ __launch_bounds__(256) void prep_kernel(const float* __restrict__ x,
                                                   const float* __restrict__ w1,
                                                   const float* __restrict__ w2) {
    const int z = blockIdx.z;
    const int t = threadIdx.x;

    if (z == 16) {
        const int b = blockIdx.y * 64 + blockIdx.x;
        for (int rr = 0; rr < 16; ++rr) {
            const int slot = b * 16 + rr;
            const int tok = g_rows_token[slot];
            const float4 v = reinterpret_cast<const float4*>(x + (size_t)tok * DM)[t];
            __nv_bfloat16 h0 = __float2bfloat16_rn(v.x), h1 = __float2bfloat16_rn(v.y);
            __nv_bfloat16 h2 = __float2bfloat16_rn(v.z), h3 = __float2bfloat16_rn(v.w);
            __nv_bfloat16 l0 = __float2bfloat16_rn(v.x - __bfloat162float(h0));
            __nv_bfloat16 l1 = __float2bfloat16_rn(v.y - __bfloat162float(h1));
            __nv_bfloat16 l2 = __float2bfloat16_rn(v.z - __bfloat162float(h2));
            __nv_bfloat16 l3 = __float2bfloat16_rn(v.w - __bfloat162float(h3));
            reinterpret_cast<uint2*>(g_Ah + (size_t)slot * DM)[t] =
                make_uint2(pack_bf16(h0, h1), pack_bf16(h2, h3));
            reinterpret_cast<uint2*>(g_Al + (size_t)slot * DM)[t] =
                make_uint2(pack_bf16(l0, l1), pack_bf16(l2, l3));
        }
        return;
    }

#if HAS_TC
    __shared__ float tile[64][65];
    const int layer = z >> 3;
    const int e = z & 7;
    const int K = layer ? DF : DM;
    const int N = layer ? DM : DF;
    const int K0 = (layer ? blockIdx.x : blockIdx.y) * 64;
    const int N0 = (layer ? blockIdx.y : blockIdx.x) * 64;
    const float* W = layer ? w2 : w1;
    __nv_bfloat16* Wh = layer ? g_w2h : g_w1h;
    __nv_bfloat16* Wl = layer ? g_w2l : g_w1l;

    const float* src = W + ((size_t)e * K + K0) * N + N0;
    const int r = t >> 4, c4 = (t & 15) * 4;
#pragma unroll
    for (int j = 0; j < 4; ++j) {
        int rr = r + j * 16;
        const float4 v = *reinterpret_cast<const float4*>(src + (size_t)rr * N + c4);
        tile[rr][c4 + 0] = v.x; tile[rr][c4 + 1] = v.y;
        tile[rr][c4 + 2] = v.z; tile[rr][c4 + 3] = v.w;
    }
    __syncthreads();
#pragma unroll
    for (int j = 0; j < 4; ++j) {
        int nn = r + j * 16;
        float v0 = tile[c4 + 0][nn], v1 = tile[c4 + 1][nn];
        float v2 = tile[c4 + 2][nn], v3 = tile[c4 + 3][nn];
        __nv_bfloat16 h0 = __float2bfloat16_rn(v0), h1 = __float2bfloat16_rn(v1);
        __nv_bfloat16 h2 = __float2bfloat16_rn(v2), h3 = __float2bfloat16_rn(v3);
        __nv_bfloat16 l0 = __float2bfloat16_rn(v0 - __bfloat162float(h0));
        __nv_bfloat16 l1 = __float2bfloat16_rn(v1 - __bfloat162float(h1));
        __nv_bfloat16 l2 = __float2bfloat16_rn(v2 - __bfloat162float(h2));
        __nv_bfloat16 l3 = __float2bfloat16_rn(v3 - __bfloat162float(h3));
        size_t out = ((size_t)e * N + N0 + nn) * K + K0 + c4;
        *reinterpret_cast<uint2*>(Wh + out) = make_uint2(pack_bf16(h0, h1), pack_bf16(h2, h3));
        *reinterpret_cast<uint2*>(Wl + out) = make_uint2(pack_bf16(l0, l1), pack_bf16(l2, l3));
    }
#endif
}

// ---------------- tcgen05 cg2 GEMM (warp-specialized producer/consumer) ----------------
// Cluster (2,1,1). Pair computes M=256 x N=256; each CTA: A half (128 rows) + B half (128 cols).
// 3 stages x 64KB/CTA, K=64 per stage. 3-pass hi/lo bf16.
// warp0 = TMA producer (both ranks); warp1 = MMA consumer (rank 0 only).
#define BUF_STRIDE 65536
#define OFF_AL 16384
#define OFF_BH 32768
#define OFF_BL 49152
#define OFF_TMEM 196608
#define OFF_MBAR 196624
#define SMEM_DYN 198656
#define STAGE_BYTES 65536u
// mbar layout: full[0..2] @ +0,8,16 ; empty[0..2] @ +24,32,40 ; final @ +48

// idesc cg2: F32 accum, BF16 a/b, K-major, N=256, M_total=256
#define GEMM_IDESC2 ((1u << 4) | (1u << 7) | (1u << 10) | ((256u / 8) << 17) | ((256u / 16) << 24))

template <bool FIRST>
__global__ __launch_bounds__(256)
void moe_gemm_tc(const __grid_constant__ CUtensorMap tmAh,
                 const __grid_constant__ CUtensorMap tmAl,
                 const __grid_constant__ CUtensorMap tmBh,
                 const __grid_constant__ CUtensorMap tmBl,
                 const float* __restrict__ bias) {
#if HAS_TC
    constexpr int KTOT = FIRST ? DM : DF;
    constexpr int NTOT = FIRST ? DF : DM;
    constexpr int NC = KTOT / 64;

    const int tileIdx = blockIdx.y;
    if (tileIdx >= g_num_tiles) return;
    const int rank = blockIdx.x & 1;
    const int e = g_tile_e[tileIdx];
    const int row0 = g_tile_r0[tileIdx];
    const int vrows = g_tile_valid[tileIdx];
    const int n0 = (blockIdx.x >> 1) * 256;

    extern __shared__ char dyn[];
    const uint32_t raw = smaddr(dyn);
    const uint32_t sbase = (raw + 1023u) & ~1023u;
    const int t = threadIdx.x;
    const int w = t >> 5, lane = t & 31;

    if (w == 0) {
        tc_alloc2(sbase + OFF_TMEM, 256);
        tc_relinq2();
    }
    if (t == 0) {
#pragma unroll
        for (int s = 0; s < 7; ++s) mbar_init(sbase + OFF_MBAR + s * 8, 1);
    }
    __syncthreads();
    // all inits (both CTAs) must precede any cg2 TMA / multicast commit
    cluster_sync_();

    uint32_t tmem;
    asm volatile("ld.shared.b32 %0, [%1];" : "=r"(tmem) : "r"(sbase + OFF_TMEM));

    const uint32_t mbF = sbase + OFF_MBAR;        // full[0..2]
    const uint32_t mbE = sbase + OFF_MBAR + 24;   // empty[0..2]
    const uint32_t mbZ = sbase + OFF_MBAR + 48;   // final

    if (w == 0 && elect_one()) {
        // ---------------- producer: TMA only ----------------
        const int arow = row0 + rank * 128;
        const int bcol = n0 + rank * 128;
        uint32_t pE = 0;  // parity bits for empty[0..2]
#pragma unroll 1
        for (int i = 0; i < NC; ++i) {
            const int b = i % 3;
            if (i >= 3) {
                mbar_wait(mbE + b * 8, (pE >> b) & 1u);
                pE ^= (1u << b);
            }
            if (rank == 0) mbar_expect(mbF + b * 8, 2u * STAGE_BYTES);
            const uint32_t bb = sbase + (uint32_t)b * BUF_STRIDE;
            const int k0 = i * 64;
            tma2d_cg2(bb,          (const void*)&tmAh, k0, arow, mbF + b * 8);
            tma2d_cg2(bb + OFF_AL, (const void*)&tmAl, k0, arow, mbF + b * 8);
            tma3d_cg2(bb + OFF_BH, (const void*)&tmBh, k0, bcol, e, mbF + b * 8);
            tma3d_cg2(bb + OFF_BL, (const void*)&tmBl, k0, bcol, e, mbF + b * 8);
        }
    } else if (w == 1 && rank == 0 && elect_one()) {
        // ---------------- consumer: MMA only ----------------
        uint64_t dA[3], dAl_[3], dB[3], dBl_[3];
#pragma unroll
        for (int s = 0; s < 3; ++s) {
            uint32_t b = sbase + s * BUF_STRIDE;
            dA[s]   = mk_desc(b);
            dAl_[s] = mk_desc(b + OFF_AL);
            dB[s]   = mk_desc(b + OFF_BH);
            dBl_[s] = mk_desc(b + OFF_BL);
        }
        uint32_t pF = 0;  // parity bits for full[0..2]
#pragma unroll 1
        for (int i = 0; i < NC; ++i) {
            const int b = i % 3;
            mbar_wait(mbF + b * 8, (pF >> b) & 1u);
            pF ^= (1u << b);
#pragma unroll
            for (int ks = 0; ks < 4; ++ks) {
                const uint64_t oa = (uint64_t)(ks * 2);
                const uint32_t en0 = (i == 0 && ks == 0) ? 0u : 1u;
                tc_mma_f16_ss2(tmem, dA[b] + oa,   dB[b] + oa,   GEMM_IDESC2, en0);
                tc_mma_f16_ss2(tmem, dA[b] + oa,   dBl_[b] + oa, GEMM_IDESC2, 1u);
                tc_mma_f16_ss2(tmem, dAl_[b] + oa, dB[b] + oa,   GEMM_IDESC2, 1u);
            }
            tc_commit_mc2((i == NC - 1) ? mbZ : (mbE + b * 8));
        }
    }

    // all threads (both ranks): wait for final MMA completion
    mbar_wait(mbZ, 0);
    tc_fence_after();

    // ---------------- epilogue (per CTA: its 128 rows x 256 cols) ----------------
    const int rloc = (w & 3) * 32 + lane;
    const int cbase = (w >> 2) * 128;
    int vr = vrows - rank * 128;
    vr = vr < 0 ? 0 : (vr > 128 ? 128 : vr);
    const bool valid = rloc < vr;
    const int rowg = row0 + rank * 128 + rloc;
    const float* bn = bias + (size_t)e * NTOT + n0 + cbase;

#pragma unroll
    for (int j = 0; j < 4; ++j) {
        uint32_t dr[32];
        tc_ld_x32(dr, tmem + cbase + j * 32);
        tc_wait_ld();
        if (valid) {
            int nb = cbase + j * 32;
            if (FIRST) {
                __nv_bfloat16* oH = g_Hh + (size_t)rowg * DF + n0 + nb;
                __nv_bfloat16* oL = g_Hl + (size_t)rowg * DF + n0 + nb;
#pragma unroll
                for (int c = 0; c < 32; c += 2) {
                    float v0 = gelu_exact(__uint_as_float(dr[c]) + bn[j * 32 + c]);
                    float v1 = gelu_exact(__uint_as_float(dr[c + 1]) + bn[j * 32 + c + 1]);
                    __nv_bfloat16 h0 = __float2bfloat16_rn(v0);
                    __nv_bfloat16 h1 = __float2bfloat16_rn(v1);
                    *reinterpret_cast<uint32_t*>(oH + c) = pack_bf16(h0, h1);
                    __nv_bfloat16 l0 = __float2bfloat16_rn(v0 - __bfloat162float(h0));
                    __nv_bfloat16 l1 = __float2bfloat16_rn(v1 - __bfloat162float(h1));
                    *reinterpret_cast<uint32_t*>(oL + c) = pack_bf16(l0, l1);
                }
            } else {
                float* oY = g_Y + (size_t)rowg * DM + n0 + nb;
#pragma unroll
                for (int c = 0; c < 32; c += 2) {
                    float v0 = __uint_as_float(dr[c]) + bn[j * 32 + c];
                    float v1 = __uint_as_float(dr[c + 1]) + bn[j * 32 + c + 1];
                    *reinterpret_cast<float2*>(oY + c) = make_float2(v0, v1);
                }
            }
        }
    }

    __syncthreads();
    if (t == 0) {
#pragma unroll
        for (int s = 0; s < 7; ++s) mbar_inval(sbase + OFF_MBAR + s * 8);
    }
    __syncthreads();
    cluster_sync_();
    if (w == 0) tc_dealloc2(tmem, 256);
    cluster_sync_();
#endif  // HAS_TC
}

// ---------------- fallback GEMM (mma.sync; 256-tiles split in half) ----------------
template <bool FIRST>
__global__ __launch_bounds__(256) void moe_gemm_fb(const float* __restrict__ W,
                                                   const float* __restrict__ bias) {
#if !HAS_TC
    constexpr int KTOT = FIRST ? DM : DF;
    constexpr int LDW  = FIRST ? DF : DM;
    const int tileIdx = blockIdx.y >> 1;
    if (tileIdx >= g_num_tiles) return;
    const int half = blockIdx.y & 1;
    const int e = g_tile_e[tileIdx];
    const int row0 = g_tile_r0[tileIdx] + half * 128;
    int vrows = g_tile_valid[tileIdx] - half * 128;
    vrows = vrows < 0 ? 0 : (vrows > 128 ? 128 : vrows);
    if (vrows == 0) return;
    const int n0 = blockIdx.x * 128;
    const float* Wn = W + (size_t)e * KTOT * LDW + n0;
    const float* bn = bias + (size_t)e * LDW + n0;

    __shared__ __align__(16) __nv_bfloat16 sAh[128 * 40];
    __shared__ __align__(16) __nv_bfloat16 sAl[128 * 40];
    __shared__ __align__(16) __nv_bfloat16 sBh[32 * 136];
    __shared__ __align__(16) __nv_bfloat16 sBl[32 * 136];

    const int t = threadIdx.x;
    float c[4][4][4];
#pragma unroll
    for (int a = 0; a < 4; ++a)
#pragma unroll
        for (int b = 0; b < 4; ++b)
#pragma unroll
            for (int q = 0; q < 4; ++q) c[a][b][q] = 0.f;

    const int lane = t & 31, warp = t >> 5;
    const int wm = warp >> 2, wn = warp & 3;
    const int m0 = wm * 64;
    const int sub = t & 15, rgrp = t >> 4;

    for (int k0 = 0; k0 < KTOT; k0 += 32) {
        __syncthreads();
#pragma unroll
        for (int rr = 0; rr < 8; ++rr) {
            int r = rr * 16 + rgrp;
            int rg = row0 + r; if (rg > PAIRS - 1) rg = PAIRS - 1;
            const uint32_t* ph = reinterpret_cast<const uint32_t*>(
                (FIRST ? g_Ah : g_Hh) + (size_t)rg * KTOT + k0);
            const uint32_t* pl = reinterpret_cast<const uint32_t*>(
                (FIRST ? g_Al : g_Hl) + (size_t)rg * KTOT + k0);
            *reinterpret_cast<uint32_t*>(&sAh[r * 40 + sub * 2]) = ph[sub];
            *reinterpret_cast<uint32_t*>(&sAl[r * 40 + sub * 2]) = pl[sub];
        }
#pragma unroll
        for (int i = 0; i < 4; ++i) {
            int lin = (i * 256 + t) * 4;
            int kr = lin >> 7;
            int nc = lin & 127;
            const float4 v = *reinterpret_cast<const float4*>(Wn + (size_t)(k0 + kr) * LDW + nc);
            __nv_bfloat16 h0 = __float2bfloat16_rn(v.x);
            __nv_bfloat16 h1 = __float2bfloat16_rn(v.y);
            __nv_bfloat16 h2 = __float2bfloat16_rn(v.z);
            __nv_bfloat16 h3 = __float2bfloat16_rn(v.w);
            __nv_bfloat16 l0 = __float2bfloat16_rn(v.x - __bfloat162float(h0));
            __nv_bfloat16 l1 = __float2bfloat16_rn(v.y - __bfloat162float(h1));
            __nv_bfloat16 l2 = __float2bfloat16_rn(v.z - __bfloat162float(h2));
            __nv_bfloat16 l3 = __float2bfloat16_rn(v.w - __bfloat162float(h3));
            *reinterpret_cast<uint2*>(&sBh[kr * 136 + nc]) = make_uint2(pack_bf16(h0, h1), pack_bf16(h2, h3));
            *reinterpret_cast<uint2*>(&sBl[kr * 136 + nc]) = make_uint2(pack_bf16(l0, l1), pack_bf16(l2, l3));
        }
        __syncthreads();

#pragma unroll
        for (int ks = 0; ks < 2; ++ks) {
            uint32_t ah[4][4], al[4][4], bh[4][2], bl[4][2];
            {
                int ar = lane & 15;
                int acol = ks * 16 + (lane >> 4) * 8;
#pragma unroll
                for (int fm = 0; fm < 4; ++fm) {
                    ldsm4(ah[fm], smaddr(&sAh[(m0 + fm * 16 + ar) * 40 + acol]));
                    ldsm4(al[fm], smaddr(&sAl[(m0 + fm * 16 + ar) * 40 + acol]));
                }
                int brow = ks * 16 + (lane & 15);
                int bcol = wn * 32 + (lane >> 4) * 8;
#pragma unroll
                for (int hb = 0; hb < 2; ++hb) {
                    uint32_t r[4];
                    ldsm4t(r, smaddr(&sBh[brow * 136 + bcol + hb * 16]));
                    bh[2 * hb][0] = r[0]; bh[2 * hb][1] = r[1];
                    bh[2 * hb + 1][0] = r[2]; bh[2 * hb + 1][1] = r[3];
                    ldsm4t(r, smaddr(&sBl[brow * 136 + bcol + hb * 16]));
                    bl[2 * hb][0] = r[0]; bl[2 * hb][1] = r[1];
                    bl[2 * hb + 1][0] = r[2]; bl[2 * hb + 1][1] = r[3];
                }
            }
#pragma unroll
            for (int fm = 0; fm < 4; ++fm)
#pragma unroll
                for (int fn = 0; fn < 4; ++fn) {
                    mma16816(c[fm][fn], ah[fm], bh[fn]);
                    mma16816(c[fm][fn], ah[fm], bl[fn]);
                    mma16816(c[fm][fn], al[fm], bh[fn]);
                }
        }
    }

    const int lgrp = lane >> 2, lq = lane & 3;
#pragma unroll
    for (int fm = 0; fm < 4; ++fm) {
        int rl = m0 + fm * 16 + lgrp;
#pragma unroll
        for (int fn = 0; fn < 4; ++fn) {
            int nc = wn * 32 + fn * 8 + lq * 2;
            float bv0 = bn[nc], bv1 = bn[nc + 1];
            float* cc = c[fm][fn];
#pragma unroll
            for (int h = 0; h < 2; ++h) {
                int rloc = rl + h * 8;
                if (rloc < vrows) {
                    int row = row0 + rloc;
                    float v0 = cc[h * 2 + 0] + bv0;
                    float v1 = cc[h * 2 + 1] + bv1;
                    if (FIRST) {
                        v0 = gelu_exact(v0);
                        v1 = gelu_exact(v1);
                        __nv_bfloat16 h0 = __float2bfloat16_rn(v0);
                        __nv_bfloat16 h1 = __float2bfloat16_rn(v1);
                        *reinterpret_cast<uint32_t*>(&g_Hh[(size_t)row * DF + n0 + nc]) = pack_bf16(h0, h1);
                        __nv_bfloat16 l0 = __float2bfloat16_rn(v0 - __bfloat162float(h0));
                        __nv_bfloat16 l1 = __float2bfloat16_rn(v1 - __bfloat162float(h1));
                        *reinterpret_cast<uint32_t*>(&g_Hl[(size_t)row * DF + n0 + nc]) = pack_bf16(l0, l1);
                    } else {
                        *reinterpret_cast<float2*>(&g_Y[(size_t)row * DM + n0 + nc]) = make_float2(v0, v1);
                    }
                }
            }
        }
    }
#endif  // !HAS_TC
}

// ---------------- kernel: weighted combine ----------------
__global__ __launch_bounds__(256) void combine_kernel(float* __restrict__ out) {
    const int tk = blockIdx.x;
    const int d = threadIdx.x * 4;
    int s0 = g_pair_slot[2 * tk], s1 = g_pair_slot[2 * tk + 1];
    float w0 = g_pair_w[2 * tk], w1 = g_pair_w[2 * tk + 1];
    const float4 a = *reinterpret_cast<const float4*>(&g_Y[(size_t)s0 * DM + d]);
    const float4 b = *reinterpret_cast<const float4*>(&g_Y[(size_t)s1 * DM + d]);
    float4 o;
    o.x = w0 * a.x + w1 * b.x;
    o.y = w0 * a.y + w1 * b.y;
    o.z = w0 * a.z + w1 * b.z;
    o.w = w0 * a.w + w1 * b.w;
    *reinterpret_cast<float4*>(&out[(size_t)tk * DM + d]) = o;
}

// ---------------- host: tensor map construction ----------------
typedef CUresult (*TmEncodeFn)(CUtensorMap*, CUtensorMapDataType, cuuint32_t, void*,
                               const cuuint64_t*, const cuuint64_t*, const cuuint32_t*,
                               const cuuint32_t*, CUtensorMapInterleave, CUtensorMapSwizzle,
                               CUtensorMapL2promotion, CUtensorMapFloatOOBfill);

static void tm2d(TmEncodeFn enc, CUtensorMap* tm, void* base, unsigned long long K,
                 unsigned long long R) {
    cuuint64_t dims[2] = {K, R};
    cuuint64_t st[1] = {K * 2};
    cuuint32_t box[2] = {64, 128};
    cuuint32_t es[2] = {1, 1};
    enc(tm, CU_TENSOR_MAP_DATA_TYPE_BFLOAT16, 2, base, dims, st, box, es,
        CU_TENSOR_MAP_INTERLEAVE_NONE, CU_TENSOR_MAP_SWIZZLE_128B,
        CU_TENSOR_MAP_L2_PROMOTION_L2_128B, CU_TENSOR_MAP_FLOAT_OOB_FILL_NONE);
}
static void tm3d(TmEncodeFn enc, CUtensorMap* tm, void* base, unsigned long long K,
                 unsigned long long N) {
    cuuint64_t dims[3] = {K, N, NE};
    cuuint64_t st[2] = {K * 2, N * K * 2};
    cuuint32_t box[3] = {64, 128, 1};   // per-CTA B half (cg2 N-split)
    cuuint32_t es[3] = {1, 1, 1};
    enc(tm, CU_TENSOR_MAP_DATA_TYPE_BFLOAT16, 3, base, dims, st, box, es,
        CU_TENSOR_MAP_INTERLEAVE_NONE, CU_TENSOR_MAP_SWIZZLE_128B,
        CU_TENSOR_MAP_L2_PROMOTION_L2_128B, CU_TENSOR_MAP_FLOAT_OOB_FILL_NONE);
}

// ---------------- launch ----------------
extern "C" void kernel_launch(void* const* d_in, const int* in_sizes, int n_in,
                              void* d_out, int out_size) {
    const float* x  = (const float*)d_in[0];
    const float* gw = (const float*)d_in[1];
    const float* w1 = (const float*)d_in[2];
    const float* b1 = (const float*)d_in[3];
    const float* w2 = (const float*)d_in[4];
    const float* b2 = (const float*)d_in[5];
    float* out = (float*)d_out;

    cudaFuncSetAttribute(moe_gemm_tc<true>,  cudaFuncAttributeMaxDynamicSharedMemorySize, SMEM_DYN);
    cudaFuncSetAttribute(moe_gemm_tc<false>, cudaFuncAttributeMaxDynamicSharedMemorySize, SMEM_DYN);

    void *pAh, *pAl, *pHh, *pHl, *pW1h, *pW1l, *pW2h, *pW2l;
    cudaGetSymbolAddress(&pAh, g_Ah);
    cudaGetSymbolAddress(&pAl, g_Al);
    cudaGetSymbolAddress(&pHh, g_Hh);
    cudaGetSymbolAddress(&pHl, g_Hl);
    cudaGetSymbolAddress(&pW1h, g_w1h);
    cudaGetSymbolAddress(&pW1l, g_w1l);
    cudaGetSymbolAddress(&pW2h, g_w2h);
    cudaGetSymbolAddress(&pW2l, g_w2l);

    void* sym = nullptr;
    cudaDriverEntryPointQueryResult qr;
    cudaGetDriverEntryPoint("cuTensorMapEncodeTiled", &sym, cudaEnableDefault, &qr);
    TmEncodeFn enc = (TmEncodeFn)sym;

    CUtensorMap tAh, tAl, tB1h, tB1l, tHh, tHl, tB2h, tB2l;
    if (enc) {
        tm2d(enc, &tAh, pAh, DM, PAIRS);
        tm2d(enc, &tAl, pAl, DM, PAIRS);
        tm3d(enc, &tB1h, pW1h, DM, DF);
        tm3d(enc, &tB1l, pW1l, DM, DF);
        tm2d(enc, &tHh, pHh, DF, PAIRS);
        tm2d(enc, &tHl, pHl, DF, PAIRS);
        tm3d(enc, &tB2h, pW2h, DF, DM);
        tm3d(enc, &tB2l, pW2l, DF, DM);
    }

    gate_kernel<<<T_TOKENS, 256>>>(x, gw);                                     // idx 0
    sortscan_kernel<<<1, 256>>>();                                             // idx 1
    prep_kernel<<<dim3(64, 16, 17), 256>>>(x, w1, w2);                         // idx 2

    cudaLaunchAttribute cat[1];
    cat[0].id = cudaLaunchAttributeClusterDimension;
    cat[0].val.clusterDim.x = 2;
    cat[0].val.clusterDim.y = 1;
    cat[0].val.clusterDim.z = 1;

    {
        cudaLaunchConfig_t cfg = {};
        cfg.gridDim = dim3((DF / 256) * 2, MAXT2, 1);
        cfg.blockDim = dim3(256, 1, 1);
        cfg.dynamicSmemBytes = SMEM_DYN;
        cfg.stream = 0;
        cfg.attrs = cat;
        cfg.numAttrs = 1;
        cudaLaunchKernelEx(&cfg, moe_gemm_tc<true>, tAh, tAl, tB1h, tB1l, b1);  // idx 3
    }
    moe_gemm_fb<true><<<dim3(DF / 128, MAXT2 * 2), 256>>>(w1, b1);              // idx 4 (no-op on tc build)
    {
        cudaLaunchConfig_t cfg = {};
        cfg.gridDim = dim3((DM / 256) * 2, MAXT2, 1);
        cfg.blockDim = dim3(256, 1, 1);
        cfg.dynamicSmemBytes = SMEM_DYN;
        cfg.stream = 0;
        cfg.attrs = cat;
        cfg.numAttrs = 1;
        cudaLaunchKernelEx(&cfg, moe_gemm_tc<false>, tHh, tHl, tB2h, tB2l, b2); // idx 5
    }
    moe_gemm_fb<false><<<dim3(DM / 128, MAXT2 * 2), 256>>>(w2, b2);             // idx 6
    combine_kernel<<<T_TOKENS, 256>>>(out);                                     // idx 7
}

// round 10
// speedup vs baseline: 1.2968x; 1.1566x over previous
#include <cuda_runtime.h>
#include <cuda.h>
#include <cuda_bf16.h>
#include <stdint.h>

#define T_TOKENS 8192
#define DM 1024
#define DF 4096
#define NE 8
#define PAIRS 16384
#define MAXTILES 144
#define MAXT2 72
#define NCLUST 74

// tcgen05 availability: only in the arch-SPECIFIC device pass (sm_103a / sm_100a).
#if defined(__CUDA_ARCH__) && (defined(__CUDA_ARCH_FEAT_SM103_ALL) || defined(__CUDA_ARCH_FEAT_SM100_ALL) || defined(__CUDA_ARCH_SPECIFIC__))
#define HAS_TC 1
#else
#define HAS_TC 0
#endif

// ---------------- scratch (device globals; no allocations) ----------------
__device__ __align__(128) __nv_bfloat16 g_Ah[(size_t)PAIRS * DM];
__device__ __align__(128) __nv_bfloat16 g_Al[(size_t)PAIRS * DM];
__device__ __align__(128) __nv_bfloat16 g_Hh[(size_t)PAIRS * DF];
__device__ __align__(128) __nv_bfloat16 g_Hl[(size_t)PAIRS * DF];
__device__ __align__(128) float         g_Y[(size_t)PAIRS * DM];

__device__ __align__(128) __nv_bfloat16 g_w1h[(size_t)NE * DM * DF];
__device__ __align__(128) __nv_bfloat16 g_w1l[(size_t)NE * DM * DF];
__device__ __align__(128) __nv_bfloat16 g_w2h[(size_t)NE * DF * DM];
__device__ __align__(128) __nv_bfloat16 g_w2l[(size_t)NE * DF * DM];

__device__ int   g_pair_e[PAIRS];
__device__ float g_pair_w[PAIRS];
__device__ int   g_pair_slot[PAIRS];
__device__ int   g_rows_token[PAIRS];

__device__ int g_counts[NE];
__device__ int g_off[NE + 1];
__device__ int g_tile_e[MAXTILES];
__device__ int g_tile_r0[MAXTILES];
__device__ int g_tile_valid[MAXTILES];
__device__ int g_num_tiles;

// ---------------- shared helpers ----------------
__device__ __forceinline__ uint32_t smaddr(const void* p) {
    return (uint32_t)__cvta_generic_to_shared(p);
}
__device__ __forceinline__ uint32_t pack_bf16(__nv_bfloat16 a, __nv_bfloat16 b) {
    return (uint32_t)__bfloat16_as_ushort(a) | ((uint32_t)__bfloat16_as_ushort(b) << 16);
}
__device__ __forceinline__ float gelu_exact(float v) {
    return 0.5f * v * (1.0f + erff(v * 0.70710678118654752f));
}

#if HAS_TC
// ---------------- tcgen05 / cg2 helpers ----------------
__device__ __forceinline__ uint32_t elect_one() {
    uint32_t pred;
    asm volatile("{\n\t.reg .pred p;\n\telect.sync _|p, 0xFFFFFFFF;\n\tselp.b32 %0, 1, 0, p;\n\t}"
                 : "=r"(pred));
    return pred;
}
__device__ __forceinline__ void cluster_sync_() {
    asm volatile("barrier.cluster.arrive.aligned;" ::: "memory");
    asm volatile("barrier.cluster.wait.aligned;" ::: "memory");
}
__device__ __forceinline__ void mbar_init(uint32_t addr, uint32_t cnt) {
    asm volatile("mbarrier.init.shared.b64 [%0], %1;" :: "r"(addr), "r"(cnt) : "memory");
}
__device__ __forceinline__ void mbar_inval(uint32_t addr) {
    asm volatile("mbarrier.inval.shared.b64 [%0];" :: "r"(addr) : "memory");
}
__device__ __forceinline__ void mbar_expect(uint32_t addr, uint32_t bytes) {
    asm volatile("mbarrier.arrive.expect_tx.shared.b64 _, [%0], %1;"
                 :: "r"(addr), "r"(bytes) : "memory");
}
__device__ __forceinline__ void mbar_wait(uint32_t addr, uint32_t parity) {
    asm volatile(
        "{\n\t.reg .pred P1;\n"
        "WAIT_%=:\n\t"
        "mbarrier.try_wait.parity.acquire.cta.shared::cta.b64 P1, [%0], %1, 0x989680;\n\t"
        "@P1 bra.uni DONE_%=;\n\t"
        "bra.uni WAIT_%=;\n"
        "DONE_%=:\n\t}"
        :: "r"(addr), "r"(parity) : "memory");
}
// arrive on rank0's mbarrier (cg2 leader: clear bit 24)
__device__ __forceinline__ void mbar_arrive_leader(uint32_t addr) {
    asm volatile(
        "{\n\t.reg .b32 la;\n\t"
        "and.b32 la, %0, 0xFEFFFFFF;\n\t"
        "mbarrier.arrive.shared::cluster.b64 _, [la];\n\t}"
        :: "r"(addr) : "memory");
}
__device__ __forceinline__ void tma2d_cg2(uint32_t dst, const void* tm, int x, int y, uint32_t mbar) {
    asm volatile(
        "{\n\t.reg .b32 lb;\n\t"
        "and.b32 lb, %4, 0xFEFFFFFF;\n\t"
        "cp.async.bulk.tensor.2d.cta_group::2.shared::cluster.global.tile.mbarrier::complete_tx::bytes "
        "[%0], [%1, {%2, %3}], [lb];\n\t}"
        :: "r"(dst), "l"(tm), "r"(x), "r"(y), "r"(mbar) : "memory");
}
__device__ __forceinline__ void tma3d_cg2(uint32_t dst, const void* tm, int x, int y, int z, uint32_t mbar) {
    asm volatile(
        "{\n\t.reg .b32 lb;\n\t"
        "and.b32 lb, %5, 0xFEFFFFFF;\n\t"
        "cp.async.bulk.tensor.3d.cta_group::2.shared::cluster.global.tile.mbarrier::complete_tx::bytes "
        "[%0], [%1, {%2, %3, %4}], [lb];\n\t}"
        :: "r"(dst), "l"(tm), "r"(x), "r"(y), "r"(z), "r"(mbar) : "memory");
}
__device__ __forceinline__ void tc_mma_f16_ss2(uint32_t d, uint64_t a, uint64_t b,
                                               uint32_t idesc, uint32_t en) {
    asm volatile(
        "{\n\t.reg .pred p;\n\tsetp.ne.u32 p, %5, 0;\n\t"
        "tcgen05.mma.cta_group::2.kind::f16 [%0], %1, %2, %3, "
        "{%4, %4, %4, %4, %4, %4, %4, %4}, p;\n\t}"
        :: "r"(d), "l"(a), "l"(b), "r"(idesc), "r"(0u), "r"(en) : "memory");
}
__device__ __forceinline__ void tc_commit_mc2(uint32_t mbar) {
    asm volatile(
        "tcgen05.commit.cta_group::2.mbarrier::arrive::one.shared::cluster.multicast::cluster.b64 [%0], %1;"
        :: "r"(mbar), "h"((uint16_t)0x3) : "memory");
}
__device__ __forceinline__ void tc_alloc2(uint32_t smem_slot, uint32_t ncols) {
    asm volatile("tcgen05.alloc.cta_group::2.sync.aligned.shared::cta.b32 [%0], %1;"
                 :: "r"(smem_slot), "r"(ncols) : "memory");
}
__device__ __forceinline__ void tc_dealloc2(uint32_t tmem, uint32_t ncols) {
    asm volatile("tcgen05.dealloc.cta_group::2.sync.aligned.b32 %0, %1;" :: "r"(tmem), "r"(ncols));
}
__device__ __forceinline__ void tc_relinq2() {
    asm volatile("tcgen05.relinquish_alloc_permit.cta_group::2.sync.aligned;");
}
__device__ __forceinline__ void tc_fence_after() {
    asm volatile("tcgen05.fence::after_thread_sync;" ::: "memory");
}
__device__ __forceinline__ void tc_fence_before() {
    asm volatile("tcgen05.fence::before_thread_sync;" ::: "memory");
}
__device__ __forceinline__ void tc_wait_ld() {
    asm volatile("tcgen05.wait::ld.sync.aligned;" ::: "memory");
}
__device__ __forceinline__ void tc_ld_x32(uint32_t* r, uint32_t addr) {
    asm volatile(
        "tcgen05.ld.sync.aligned.32x32b.x32.b32 "
        "{%0, %1, %2, %3, %4, %5, %6, %7, %8, %9, %10, %11, %12, %13, %14, %15, "
        " %16, %17, %18, %19, %20, %21, %22, %23, %24, %25, %26, %27, %28, %29, %30, %31}, [%32];"
        : "=r"(r[0]), "=r"(r[1]), "=r"(r[2]), "=r"(r[3]), "=r"(r[4]), "=r"(r[5]), "=r"(r[6]), "=r"(r[7]),
          "=r"(r[8]), "=r"(r[9]), "=r"(r[10]), "=r"(r[11]), "=r"(r[12]), "=r"(r[13]), "=r"(r[14]), "=r"(r[15]),
          "=r"(r[16]), "=r"(r[17]), "=r"(r[18]), "=r"(r[19]), "=r"(r[20]), "=r"(r[21]), "=r"(r[22]), "=r"(r[23]),
          "=r"(r[24]), "=r"(r[25]), "=r"(r[26]), "=r"(r[27]), "=r"(r[28]), "=r"(r[29]), "=r"(r[30]), "=r"(r[31])
        : "r"(addr));
}
// SW128 K-major descriptor base (LBO=1, SBO=64, version=1, layout SW128)
__device__ __forceinline__ uint64_t mk_desc(uint32_t addr) {
    const uint64_t DBASE = (2ULL << 61) | (1ULL << 46) | (64ULL << 32) | (1ULL << 16);
    return DBASE | (uint64_t)((addr >> 4) & 0x3FFF);
}
#endif  // HAS_TC

#if !HAS_TC
// ---------------- fallback-path helpers (mma.sync) ----------------
__device__ __forceinline__ void ldsm4(uint32_t* r, uint32_t addr) {
    asm volatile("ldmatrix.sync.aligned.m8n8.x4.shared.b16 {%0,%1,%2,%3}, [%4];\n"
                 : "=r"(r[0]), "=r"(r[1]), "=r"(r[2]), "=r"(r[3]) : "r"(addr));
}
__device__ __forceinline__ void ldsm4t(uint32_t* r, uint32_t addr) {
    asm volatile("ldmatrix.sync.aligned.m8n8.x4.trans.shared.b16 {%0,%1,%2,%3}, [%4];\n"
                 : "=r"(r[0]), "=r"(r[1]), "=r"(r[2]), "=r"(r[3]) : "r"(addr));
}
__device__ __forceinline__ void mma16816(float* c, const uint32_t* a, const uint32_t* b) {
    asm volatile(
        "mma.sync.aligned.m16n8k16.row.col.f32.bf16.bf16.f32 "
        "{%0,%1,%2,%3}, {%4,%5,%6,%7}, {%8,%9}, {%0,%1,%2,%3};\n"
        : "+f"(c[0]), "+f"(c[1]), "+f"(c[2]), "+f"(c[3])
        : "r"(a[0]), "r"(a[1]), "r"(a[2]), "r"(a[3]), "r"(b[0]), "r"(b[1]));
}
#endif  // !HAS_TC

// ---------------- kernel: gating (routing only) ----------------
__global__ __launch_bounds__(256) void gate_kernel(const float* __restrict__ x,
                                                   const float* __restrict__ gw) {
    const int tk = blockIdx.x;
    const int tid = threadIdx.x;
    const float* xr = x + (size_t)tk * DM;

    float p[NE];
#pragma unroll
    for (int e = 0; e < NE; ++e) p[e] = 0.f;
#pragma unroll
    for (int j = 0; j < 4; ++j) {
        int i = j * 256 + tid;
        float v = xr[i];
#pragma unroll
        for (int e = 0; e < NE; ++e) p[e] += v * gw[e * DM + i];
    }
#pragma unroll
    for (int e = 0; e < NE; ++e)
#pragma unroll
        for (int o = 16; o > 0; o >>= 1) p[e] += __shfl_xor_sync(0xffffffffu, p[e], o);

    __shared__ float sRed[8][NE];
    int lane = tid & 31, w = tid >> 5;
    if (lane == 0) {
#pragma unroll
        for (int e = 0; e < NE; ++e) sRed[w][e] = p[e];
    }
    __syncthreads();
    if (tid == 0) {
        float lg[NE];
#pragma unroll
        for (int e = 0; e < NE; ++e) {
            float s = 0.f;
#pragma unroll
            for (int ww = 0; ww < 8; ++ww) s += sRed[ww][e];
            lg[e] = s;
        }
        float m = lg[0];
#pragma unroll
        for (int e = 1; e < NE; ++e) m = fmaxf(m, lg[e]);
        float ex[NE], S = 0.f;
#pragma unroll
        for (int e = 0; e < NE; ++e) { ex[e] = expf(lg[e] - m); S += ex[e]; }
        int i0 = 0;
#pragma unroll
        for (int e = 1; e < NE; ++e) if (ex[e] > ex[i0]) i0 = e;
        int i1 = (i0 == 0) ? 1 : 0;
#pragma unroll
        for (int e = 0; e < NE; ++e) if (e != i0 && ex[e] > ex[i1]) i1 = e;
        float p0 = ex[i0] / S, p1 = ex[i1] / S;
        float den = p0 + p1 + 1e-9f;
        g_pair_e[2 * tk] = i0;     g_pair_w[2 * tk] = p0 / den;
        g_pair_e[2 * tk + 1] = i1; g_pair_w[2 * tk + 1] = p1 / den;
    }
}

// ---------------- kernel: counting sort (counts + scan + 256-row tiles + scatter) ----------------
__global__ __launch_bounds__(256) void sortscan_kernel() {
    __shared__ uint16_t loc[256][NE];
    __shared__ int s_cnt[NE];
    __shared__ int s_off[NE];
    const int t = threadIdx.x;
    const int p0 = t * 64;

    int lc[NE];
#pragma unroll
    for (int e = 0; e < NE; ++e) lc[e] = 0;
    for (int i = 0; i < 64; ++i) lc[g_pair_e[p0 + i]]++;
#pragma unroll
    for (int e = 0; e < NE; ++e) loc[t][e] = (uint16_t)lc[e];
    __syncthreads();

    if (t < NE) {
        int run = 0;
        for (int i = 0; i < 256; ++i) {
            int c = loc[i][t];
            loc[i][t] = (uint16_t)run;
            run += c;
        }
        s_cnt[t] = run;
        g_counts[t] = run;
    }
    __syncthreads();

    if (t == 0) {
        int off = 0, nt = 0;
        for (int e = 0; e < NE; ++e) {
            g_off[e] = off;
            s_off[e] = off;
            int c = s_cnt[e];
            int tiles = (c + 255) >> 8;
            for (int i = 0; i < tiles; ++i) {
                g_tile_e[nt] = e;
                g_tile_r0[nt] = off + i * 256;
                int v = c - i * 256;
                g_tile_valid[nt] = v > 256 ? 256 : v;
                ++nt;
            }
            off += c;
        }
        g_off[NE] = off;
        g_num_tiles = nt;
    }
    __syncthreads();

    int run[NE];
#pragma unroll
    for (int e = 0; e < NE; ++e) run[e] = s_off[e] + (int)loc[t][e];
    for (int i = 0; i < 64; ++i) {
        int p = p0 + i;
        int e = g_pair_e[p];
        int slot = run[e]++;
        g_pair_slot[p] = slot;
        g_rows_token[slot] = p >> 1;
    }
}

// ---------------- kernel: prep = A-gather (z==16) + weight split/transpose (z<16) ----------------
__global__ __launch_bounds__(256) void prep_kernel(const float* __restrict__ x,
                                                   const float* __restrict__ w1,
                                                   const float* __restrict__ w2) {
    const int z = blockIdx.z;
    const int t = threadIdx.x;

    if (z == 16) {
        const int b = blockIdx.y * 64 + blockIdx.x;
        for (int rr = 0; rr < 16; ++rr) {
            const int slot = b * 16 + rr;
            const int tok = g_rows_token[slot];
            const float4 v = reinterpret_cast<const float4*>(x + (size_t)tok * DM)[t];
            __nv_bfloat16 h0 = __float2bfloat16_rn(v.x), h1 = __float2bfloat16_rn(v.y);
            __nv_bfloat16 h2 = __float2bfloat16_rn(v.z), h3 = __float2bfloat16_rn(v.w);
            __nv_bfloat16 l0 = __float2bfloat16_rn(v.x - __bfloat162float(h0));
            __nv_bfloat16 l1 = __float2bfloat16_rn(v.y - __bfloat162float(h1));
            __nv_bfloat16 l2 = __float2bfloat16_rn(v.z - __bfloat162float(h2));
            __nv_bfloat16 l3 = __float2bfloat16_rn(v.w - __bfloat162float(h3));
            reinterpret_cast<uint2*>(g_Ah + (size_t)slot * DM)[t] =
                make_uint2(pack_bf16(h0, h1), pack_bf16(h2, h3));
            reinterpret_cast<uint2*>(g_Al + (size_t)slot * DM)[t] =
                make_uint2(pack_bf16(l0, l1), pack_bf16(l2, l3));
        }
        return;
    }

#if HAS_TC
    __shared__ float tile[64][65];
    const int layer = z >> 3;
    const int e = z & 7;
    const int K = layer ? DF : DM;
    const int N = layer ? DM : DF;
    const int K0 = (layer ? blockIdx.x : blockIdx.y) * 64;
    const int N0 = (layer ? blockIdx.y : blockIdx.x) * 64;
    const float* W = layer ? w2 : w1;
    __nv_bfloat16* Wh = layer ? g_w2h : g_w1h;
    __nv_bfloat16* Wl = layer ? g_w2l : g_w1l;

    const float* src = W + ((size_t)e * K + K0) * N + N0;
    const int r = t >> 4, c4 = (t & 15) * 4;
#pragma unroll
    for (int j = 0; j < 4; ++j) {
        int rr = r + j * 16;
        const float4 v = *reinterpret_cast<const float4*>(src + (size_t)rr * N + c4);
        tile[rr][c4 + 0] = v.x; tile[rr][c4 + 1] = v.y;
        tile[rr][c4 + 2] = v.z; tile[rr][c4 + 3] = v.w;
    }
    __syncthreads();
#pragma unroll
    for (int j = 0; j < 4; ++j) {
        int nn = r + j * 16;
        float v0 = tile[c4 + 0][nn], v1 = tile[c4 + 1][nn];
        float v2 = tile[c4 + 2][nn], v3 = tile[c4 + 3][nn];
        __nv_bfloat16 h0 = __float2bfloat16_rn(v0), h1 = __float2bfloat16_rn(v1);
        __nv_bfloat16 h2 = __float2bfloat16_rn(v2), h3 = __float2bfloat16_rn(v3);
        __nv_bfloat16 l0 = __float2bfloat16_rn(v0 - __bfloat162float(h0));
        __nv_bfloat16 l1 = __float2bfloat16_rn(v1 - __bfloat162float(h1));
        __nv_bfloat16 l2 = __float2bfloat16_rn(v2 - __bfloat162float(h2));
        __nv_bfloat16 l3 = __float2bfloat16_rn(v3 - __bfloat162float(h3));
        size_t out = ((size_t)e * N + N0 + nn) * K + K0 + c4;
        *reinterpret_cast<uint2*>(Wh + out) = make_uint2(pack_bf16(h0, h1), pack_bf16(h2, h3));
        *reinterpret_cast<uint2*>(Wl + out) = make_uint2(pack_bf16(l0, l1), pack_bf16(l2, l3));
    }
#endif
}

// ---------------- tcgen05 cg2 GEMM: persistent clusters, double-buffered TMEM D ----------------
// Cluster (2,1,1); 74 persistent clusters. Pair computes M=256 x N=256 tiles.
// warp0 = TMA producer (both ranks); warp1(rank0) = MMA consumer; warps2-7 = epilogue.
#define BUF_STRIDE 65536
#define OFF_AL 16384
#define OFF_BH 32768
#define OFF_BL 49152
#define OFF_TMEM 196608
#define OFF_MBAR 196624
#define SMEM_DYN 198656
#define STAGE_BYTES 65536u
// mbar layout: full[0..2]@+0,8,16 ; empty[0..2]@+24,32,40 ; done[0..1]@+48,56 ; free[0..1]@+64,72

#define GEMM_IDESC2 ((1u << 4) | (1u << 7) | (1u << 10) | ((256u / 8) << 17) | ((256u / 16) << 24))

template <bool FIRST>
__global__ __launch_bounds__(256)
void moe_gemm_tc(const __grid_constant__ CUtensorMap tmAh,
                 const __grid_constant__ CUtensorMap tmAl,
                 const __grid_constant__ CUtensorMap tmBh,
                 const __grid_constant__ CUtensorMap tmBl,
                 const float* __restrict__ bias) {
#if HAS_TC
    constexpr int KTOT = FIRST ? DM : DF;
    constexpr int NTOT = FIRST ? DF : DM;
    constexpr int NC = KTOT / 64;
    constexpr int NXT = NTOT / 256;

    const int cid = blockIdx.y;
    const int rank = blockIdx.x & 1;
    const int tot = g_num_tiles * NXT;

    extern __shared__ char dyn[];
    const uint32_t raw = smaddr(dyn);
    const uint32_t sbase = (raw + 1023u) & ~1023u;
    const int t = threadIdx.x;
    const int w = t >> 5, lane = t & 31;

    if (w == 0) {
        tc_alloc2(sbase + OFF_TMEM, 512);
        tc_relinq2();
    }
    if (t == 0) {
#pragma unroll
        for (int s = 0; s < 8; ++s) mbar_init(sbase + OFF_MBAR + s * 8, 1);  // full,empty,done
        mbar_init(sbase + OFF_MBAR + 64, 2);  // free[0]
        mbar_init(sbase + OFF_MBAR + 72, 2);  // free[1]
    }
    __syncthreads();
    cluster_sync_();

    uint32_t tmem;
    asm volatile("ld.shared.b32 %0, [%1];" : "=r"(tmem) : "r"(sbase + OFF_TMEM));

    const uint32_t mbF = sbase + OFF_MBAR;         // full[0..2]
    const uint32_t mbE = sbase + OFF_MBAR + 24;    // empty[0..2]
    const uint32_t mbD = sbase + OFF_MBAR + 48;    // done[0..1]
    const uint32_t mbR = sbase + OFF_MBAR + 64;    // free[0..1]

    if (w == 0 && elect_one()) {
        // ================= producer: continuous TMA across tiles =================
        uint32_t pE = 0, pDp = 0;
        int s = 0;
#pragma unroll 1
        for (int tt = 0;; ++tt) {
            const int T = cid + tt * NCLUST;
            if (T >= tot) break;
            const int rt = T / NXT, nt = T % NXT;
            const int e = g_tile_e[rt];
            const int arow = g_tile_r0[rt] + rank * 128;
            const int bcol = nt * 256 + rank * 128;
#pragma unroll 1
            for (int i = 0; i < NC; ++i, ++s) {
                const int b = s % 3;
                if (s >= 3) {
                    const int sp_ = s - 3;
                    if ((sp_ % NC) == NC - 1) {
                        const int d = (sp_ / NC) & 1;
                        mbar_wait(mbD + d * 8, (pDp >> d) & 1u); pDp ^= 1u << d;
                    } else {
                        mbar_wait(mbE + b * 8, (pE >> b) & 1u); pE ^= 1u << b;
                    }
                }
                if (rank == 0) mbar_expect(mbF + b * 8, 2u * STAGE_BYTES);
                const uint32_t bb = sbase + (uint32_t)b * BUF_STRIDE;
                const int k0 = i * 64;
                tma2d_cg2(bb,          (const void*)&tmAh, k0, arow, mbF + b * 8);
                tma2d_cg2(bb + OFF_AL, (const void*)&tmAl, k0, arow, mbF + b * 8);
                tma3d_cg2(bb + OFF_BH, (const void*)&tmBh, k0, bcol, e, mbF + b * 8);
                tma3d_cg2(bb + OFF_BL, (const void*)&tmBl, k0, bcol, e, mbF + b * 8);
            }
        }
    } else if (w == 1 && rank == 0 && elect_one()) {
        // ================= consumer: MMA =================
        uint64_t dA[3], dAl_[3], dB[3], dBl_[3];
#pragma unroll
        for (int s2 = 0; s2 < 3; ++s2) {
            uint32_t b = sbase + s2 * BUF_STRIDE;
            dA[s2]   = mk_desc(b);
            dAl_[s2] = mk_desc(b + OFF_AL);
            dB[s2]   = mk_desc(b + OFF_BH);
            dBl_[s2] = mk_desc(b + OFF_BL);
        }
        uint32_t pF = 0, pFree = 0;
        int s = 0, ttn = 0;
#pragma unroll 1
        for (int tt = 0;; ++tt) {
            const int T = cid + tt * NCLUST;
            if (T >= tot) break;
            ttn = tt + 1;
            const int d = tt & 1;
            if (tt >= 2) {
                mbar_wait(mbR + d * 8, (pFree >> d) & 1u); pFree ^= 1u << d;
                tc_fence_after();
            }
            const uint32_t dtm = tmem + d * 256;
#pragma unroll 1
            for (int i = 0; i < NC; ++i, ++s) {
                const int b = s % 3;
                mbar_wait(mbF + b * 8, (pF >> b) & 1u); pF ^= 1u << b;
#pragma unroll
                for (int ks = 0; ks < 4; ++ks) {
                    const uint64_t oa = (uint64_t)(ks * 2);
                    const uint32_t en0 = (i == 0 && ks == 0) ? 0u : 1u;
                    tc_mma_f16_ss2(dtm, dA[b] + oa,   dB[b] + oa,   GEMM_IDESC2, en0);
                    tc_mma_f16_ss2(dtm, dA[b] + oa,   dBl_[b] + oa, GEMM_IDESC2, 1u);
                    tc_mma_f16_ss2(dtm, dAl_[b] + oa, dB[b] + oa,   GEMM_IDESC2, 1u);
                }
                tc_commit_mc2((i == NC - 1) ? (mbD + d * 8) : (mbE + b * 8));
            }
        }
        // drain trailing frees so no remote arrival is pending at inval
#pragma unroll 1
        for (int k = (ttn >= 2 ? ttn - 2 : 0); k < ttn; ++k) {
            const int d = k & 1;
            mbar_wait(mbR + d * 8, (pFree >> d) & 1u); pFree ^= 1u << d;
        }
    } else if (w >= 2) {
        // ================= epilogue: warps 2..7 =================
        const int sp_ = w & 3;                 // TMEM subpartition
        const int rloc = sp_ * 32 + lane;
        int cstart, cnum;
        if (w == 4 || w == 5)      { cstart = 0;   cnum = 8; }
        else if (w == 2 || w == 3) { cstart = 0;   cnum = 4; }
        else                       { cstart = 128; cnum = 4; }

        uint32_t pDe = 0;
#pragma unroll 1
        for (int tt = 0;; ++tt) {
            const int T = cid + tt * NCLUST;
            if (T >= tot) break;
            const int d = tt & 1;
            mbar_wait(mbD + d * 8, (pDe >> d) & 1u); pDe ^= 1u << d;
            tc_fence_after();

            const int rt = T / NXT, nt = T % NXT;
            const int e = g_tile_e[rt];
            const int row0 = g_tile_r0[rt];
            const int n0 = nt * 256;
            int vr = g_tile_valid[rt] - rank * 128;
            vr = vr < 0 ? 0 : (vr > 128 ? 128 : vr);
            const bool valid = rloc < vr;
            const int rowg = row0 + rank * 128 + rloc;
            const uint32_t dtm = tmem + d * 256;
            const float* bb = bias + (size_t)e * NTOT + n0;

#pragma unroll 1
            for (int j = 0; j < cnum; ++j) {
                const int col = cstart + j * 32;
                uint32_t dr[32];
                tc_ld_x32(dr, dtm + col);
                tc_wait_ld();
                if (valid) {
                    if (FIRST) {
                        __nv_bfloat16* oH = g_Hh + (size_t)rowg * DF + n0 + col;
                        __nv_bfloat16* oL = g_Hl + (size_t)rowg * DF + n0 + col;
#pragma unroll
                        for (int c = 0; c < 32; c += 2) {
                            float v0 = gelu_exact(__uint_as_float(dr[c]) + bb[col + c]);
                            float v1 = gelu_exact(__uint_as_float(dr[c + 1]) + bb[col + c + 1]);
                            __nv_bfloat16 h0 = __float2bfloat16_rn(v0);
                            __nv_bfloat16 h1 = __float2bfloat16_rn(v1);
                            *reinterpret_cast<uint32_t*>(oH + c) = pack_bf16(h0, h1);
                            __nv_bfloat16 l0 = __float2bfloat16_rn(v0 - __bfloat162float(h0));
                            __nv_bfloat16 l1 = __float2bfloat16_rn(v1 - __bfloat162float(h1));
                            *reinterpret_cast<uint32_t*>(oL + c) = pack_bf16(l0, l1);
                        }
                    } else {
                        float* oY = g_Y + (size_t)rowg * DM + n0 + col;
#pragma unroll
                        for (int c = 0; c < 32; c += 2) {
                            float v0 = __uint_as_float(dr[c]) + bb[col + c];
                            float v1 = __uint_as_float(dr[c + 1]) + bb[col + c + 1];
                            *reinterpret_cast<float2*>(oY + c) = make_float2(v0, v1);
                        }
                    }
                }
            }
            tc_fence_before();
            asm volatile("bar.sync 1, 192;" ::: "memory");
            if (w == 2 && elect_one()) mbar_arrive_leader(mbR + d * 8);
        }
    }

    __syncthreads();
    if (t == 0) {
#pragma unroll
        for (int s = 0; s < 10; ++s) mbar_inval(sbase + OFF_MBAR + s * 8);
    }
    __syncthreads();
    cluster_sync_();
    if (w == 0) tc_dealloc2(tmem, 512);
    cluster_sync_();
#endif  // HAS_TC
}

// ---------------- fallback GEMM (mma.sync; 256-tiles split in half) ----------------
template <bool FIRST>
__global__ __launch_bounds__(256) void moe_gemm_fb(const float* __restrict__ W,
                                                   const float* __restrict__ bias) {
#if !HAS_TC
    constexpr int KTOT = FIRST ? DM : DF;
    constexpr int LDW  = FIRST ? DF : DM;
    const int tileIdx = blockIdx.y >> 1;
    if (tileIdx >= g_num_tiles) return;
    const int half = blockIdx.y & 1;
    const int e = g_tile_e[tileIdx];
    const int row0 = g_tile_r0[tileIdx] + half * 128;
    int vrows = g_tile_valid[tileIdx] - half * 128;
    vrows = vrows < 0 ? 0 : (vrows > 128 ? 128 : vrows);
    if (vrows == 0) return;
    const int n0 = blockIdx.x * 128;
    const float* Wn = W + (size_t)e * KTOT * LDW + n0;
    const float* bn = bias + (size_t)e * LDW + n0;

    __shared__ __align__(16) __nv_bfloat16 sAh[128 * 40];
    __shared__ __align__(16) __nv_bfloat16 sAl[128 * 40];
    __shared__ __align__(16) __nv_bfloat16 sBh[32 * 136];
    __shared__ __align__(16) __nv_bfloat16 sBl[32 * 136];

    const int t = threadIdx.x;
    float c[4][4][4];
#pragma unroll
    for (int a = 0; a < 4; ++a)
#pragma unroll
        for (int b = 0; b < 4; ++b)
#pragma unroll
            for (int q = 0; q < 4; ++q) c[a][b][q] = 0.f;

    const int lane = t & 31, warp = t >> 5;
    const int wm = warp >> 2, wn = warp & 3;
    const int m0 = wm * 64;
    const int sub = t & 15, rgrp = t >> 4;

    for (int k0 = 0; k0 < KTOT; k0 += 32) {
        __syncthreads();
#pragma unroll
        for (int rr = 0; rr < 8; ++rr) {
            int r = rr * 16 + rgrp;
            int rg = row0 + r; if (rg > PAIRS - 1) rg = PAIRS - 1;
            const uint32_t* ph = reinterpret_cast<const uint32_t*>(
                (FIRST ? g_Ah : g_Hh) + (size_t)rg * KTOT + k0);
            const uint32_t* pl = reinterpret_cast<const uint32_t*>(
                (FIRST ? g_Al : g_Hl) + (size_t)rg * KTOT + k0);
            *reinterpret_cast<uint32_t*>(&sAh[r * 40 + sub * 2]) = ph[sub];
            *reinterpret_cast<uint32_t*>(&sAl[r * 40 + sub * 2]) = pl[sub];
        }
#pragma unroll
        for (int i = 0; i < 4; ++i) {
            int lin = (i * 256 + t) * 4;
            int kr = lin >> 7;
            int nc = lin & 127;
            const float4 v = *reinterpret_cast<const float4*>(Wn + (size_t)(k0 + kr) * LDW + nc);
            __nv_bfloat16 h0 = __float2bfloat16_rn(v.x);
            __nv_bfloat16 h1 = __float2bfloat16_rn(v.y);
            __nv_bfloat16 h2 = __float2bfloat16_rn(v.z);
            __nv_bfloat16 h3 = __float2bfloat16_rn(v.w);
            __nv_bfloat16 l0 = __float2bfloat16_rn(v.x - __bfloat162float(h0));
            __nv_bfloat16 l1 = __float2bfloat16_rn(v.y - __bfloat162float(h1));
            __nv_bfloat16 l2 = __float2bfloat16_rn(v.z - __bfloat162float(h2));
            __nv_bfloat16 l3 = __float2bfloat16_rn(v.w - __bfloat162float(h3));
            *reinterpret_cast<uint2*>(&sBh[kr * 136 + nc]) = make_uint2(pack_bf16(h0, h1), pack_bf16(h2, h3));
            *reinterpret_cast<uint2*>(&sBl[kr * 136 + nc]) = make_uint2(pack_bf16(l0, l1), pack_bf16(l2, l3));
        }
        __syncthreads();

#pragma unroll
        for (int ks = 0; ks < 2; ++ks) {
            uint32_t ah[4][4], al[4][4], bh[4][2], bl[4][2];
            {
                int ar = lane & 15;
                int acol = ks * 16 + (lane >> 4) * 8;
#pragma unroll
                for (int fm = 0; fm < 4; ++fm) {
                    ldsm4(ah[fm], smaddr(&sAh[(m0 + fm * 16 + ar) * 40 + acol]));
                    ldsm4(al[fm], smaddr(&sAl[(m0 + fm * 16 + ar) * 40 + acol]));
                }
                int brow = ks * 16 + (lane & 15);
                int bcol = wn * 32 + (lane >> 4) * 8;
#pragma unroll
                for (int hb = 0; hb < 2; ++hb) {
                    uint32_t r[4];
                    ldsm4t(r, smaddr(&sBh[brow * 136 + bcol + hb * 16]));
                    bh[2 * hb][0] = r[0]; bh[2 * hb][1] = r[1];
                    bh[2 * hb + 1][0] = r[2]; bh[2 * hb + 1][1] = r[3];
                    ldsm4t(r, smaddr(&sBl[brow * 136 + bcol + hb * 16]));
                    bl[2 * hb][0] = r[0]; bl[2 * hb][1] = r[1];
                    bl[2 * hb + 1][0] = r[2]; bl[2 * hb + 1][1] = r[3];
                }
            }
#pragma unroll
            for (int fm = 0; fm < 4; ++fm)
#pragma unroll
                for (int fn = 0; fn < 4; ++fn) {
                    mma16816(c[fm][fn], ah[fm], bh[fn]);
                    mma16816(c[fm][fn], ah[fm], bl[fn]);
                    mma16816(c[fm][fn], al[fm], bh[fn]);
                }
        }
    }

    const int lgrp = lane >> 2, lq = lane & 3;
#pragma unroll
    for (int fm = 0; fm < 4; ++fm) {
        int rl = m0 + fm * 16 + lgrp;
#pragma unroll
        for (int fn = 0; fn < 4; ++fn) {
            int nc = wn * 32 + fn * 8 + lq * 2;
            float bv0 = bn[nc], bv1 = bn[nc + 1];
            float* cc = c[fm][fn];
#pragma unroll
            for (int h = 0; h < 2; ++h) {
                int rloc = rl + h * 8;
                if (rloc < vrows) {
                    int row = row0 + rloc;
                    float v0 = cc[h * 2 + 0] + bv0;
                    float v1 = cc[h * 2 + 1] + bv1;
                    if (FIRST) {
                        v0 = gelu_exact(v0);
                        v1 = gelu_exact(v1);
                        __nv_bfloat16 h0 = __float2bfloat16_rn(v0);
                        __nv_bfloat16 h1 = __float2bfloat16_rn(v1);
                        *reinterpret_cast<uint32_t*>(&g_Hh[(size_t)row * DF + n0 + nc]) = pack_bf16(h0, h1);
                        __nv_bfloat16 l0 = __float2bfloat16_rn(v0 - __bfloat162float(h0));
                        __nv_bfloat16 l1 = __float2bfloat16_rn(v1 - __bfloat162float(h1));
                        *reinterpret_cast<uint32_t*>(&g_Hl[(size_t)row * DF + n0 + nc]) = pack_bf16(l0, l1);
                    } else {
                        *reinterpret_cast<float2*>(&g_Y[(size_t)row * DM + n0 + nc]) = make_float2(v0, v1);
                    }
                }
            }
        }
    }
#endif  // !HAS_TC
}

// ---------------- kernel: weighted combine ----------------
__global__ __launch_bounds__(256) void combine_kernel(float* __restrict__ out) {
    const int tk = blockIdx.x;
    const int d = threadIdx.x * 4;
    int s0 = g_pair_slot[2 * tk], s1 = g_pair_slot[2 * tk + 1];
    float w0 = g_pair_w[2 * tk], w1 = g_pair_w[2 * tk + 1];
    const float4 a = *reinterpret_cast<const float4*>(&g_Y[(size_t)s0 * DM + d]);
    const float4 b = *reinterpret_cast<const float4*>(&g_Y[(size_t)s1 * DM + d]);
    float4 o;
    o.x = w0 * a.x + w1 * b.x;
    o.y = w0 * a.y + w1 * b.y;
    o.z = w0 * a.z + w1 * b.z;
    o.w = w0 * a.w + w1 * b.w;
    *reinterpret_cast<float4*>(&out[(size_t)tk * DM + d]) = o;
}

// ---------------- host: tensor map construction ----------------
typedef CUresult (*TmEncodeFn)(CUtensorMap*, CUtensorMapDataType, cuuint32_t, void*,
                               const cuuint64_t*, const cuuint64_t*, const cuuint32_t*,
                               const cuuint32_t*, CUtensorMapInterleave, CUtensorMapSwizzle,
                               CUtensorMapL2promotion, CUtensorMapFloatOOBfill);

static void tm2d(TmEncodeFn enc, CUtensorMap* tm, void* base, unsigned long long K,
                 unsigned long long R) {
    cuuint64_t dims[2] = {K, R};
    cuuint64_t st[1] = {K * 2};
    cuuint32_t box[2] = {64, 128};
    cuuint32_t es[2] = {1, 1};
    enc(tm, CU_TENSOR_MAP_DATA_TYPE_BFLOAT16, 2, base, dims, st, box, es,
        CU_TENSOR_MAP_INTERLEAVE_NONE, CU_TENSOR_MAP_SWIZZLE_128B,
        CU_TENSOR_MAP_L2_PROMOTION_L2_128B, CU_TENSOR_MAP_FLOAT_OOB_FILL_NONE);
}
static void tm3d(TmEncodeFn enc, CUtensorMap* tm, void* base, unsigned long long K,
                 unsigned long long N) {
    cuuint64_t dims[3] = {K, N, NE};
    cuuint64_t st[2] = {K * 2, N * K * 2};
    cuuint32_t box[3] = {64, 128, 1};
    cuuint32_t es[3] = {1, 1, 1};
    enc(tm, CU_TENSOR_MAP_DATA_TYPE_BFLOAT16, 3, base, dims, st, box, es,
        CU_TENSOR_MAP_INTERLEAVE_NONE, CU_TENSOR_MAP_SWIZZLE_128B,
        CU_TENSOR_MAP_L2_PROMOTION_L2_128B, CU_TENSOR_MAP_FLOAT_OOB_FILL_NONE);
}

// ---------------- launch ----------------
extern "C" void kernel_launch(void* const* d_in, const int* in_sizes, int n_in,
                              void* d_out, int out_size) {
    const float* x  = (const float*)d_in[0];
    const float* gw = (const float*)d_in[1];
    const float* w1 = (const float*)d_in[2];
    const float* b1 = (const float*)d_in[3];
    const float* w2 = (const float*)d_in[4];
    const float* b2 = (const float*)d_in[5];
    float* out = (float*)d_out;

    cudaFuncSetAttribute(moe_gemm_tc<true>,  cudaFuncAttributeMaxDynamicSharedMemorySize, SMEM_DYN);
    cudaFuncSetAttribute(moe_gemm_tc<false>, cudaFuncAttributeMaxDynamicSharedMemorySize, SMEM_DYN);

    void *pAh, *pAl, *pHh, *pHl, *pW1h, *pW1l, *pW2h, *pW2l;
    cudaGetSymbolAddress(&pAh, g_Ah);
    cudaGetSymbolAddress(&pAl, g_Al);
    cudaGetSymbolAddress(&pHh, g_Hh);
    cudaGetSymbolAddress(&pHl, g_Hl);
    cudaGetSymbolAddress(&pW1h, g_w1h);
    cudaGetSymbolAddress(&pW1l, g_w1l);
    cudaGetSymbolAddress(&pW2h, g_w2h);
    cudaGetSymbolAddress(&pW2l, g_w2l);

    void* sym = nullptr;
    cudaDriverEntryPointQueryResult qr;
    cudaGetDriverEntryPoint("cuTensorMapEncodeTiled", &sym, cudaEnableDefault, &qr);
    TmEncodeFn enc = (TmEncodeFn)sym;

    CUtensorMap tAh, tAl, tB1h, tB1l, tHh, tHl, tB2h, tB2l;
    if (enc) {
        tm2d(enc, &tAh, pAh, DM, PAIRS);
        tm2d(enc, &tAl, pAl, DM, PAIRS);
        tm3d(enc, &tB1h, pW1h, DM, DF);
        tm3d(enc, &tB1l, pW1l, DM, DF);
        tm2d(enc, &tHh, pHh, DF, PAIRS);
        tm2d(enc, &tHl, pHl, DF, PAIRS);
        tm3d(enc, &tB2h, pW2h, DF, DM);
        tm3d(enc, &tB2l, pW2l, DF, DM);
    }

    gate_kernel<<<T_TOKENS, 256>>>(x, gw);                                     // idx 0
    sortscan_kernel<<<1, 256>>>();                                             // idx 1
    prep_kernel<<<dim3(64, 16, 17), 256>>>(x, w1, w2);                         // idx 2

    cudaLaunchAttribute cat[1];
    cat[0].id = cudaLaunchAttributeClusterDimension;
    cat[0].val.clusterDim.x = 2;
    cat[0].val.clusterDim.y = 1;
    cat[0].val.clusterDim.z = 1;

    {
        cudaLaunchConfig_t cfg = {};
        cfg.gridDim = dim3(2, NCLUST, 1);
        cfg.blockDim = dim3(256, 1, 1);
        cfg.dynamicSmemBytes = SMEM_DYN;
        cfg.stream = 0;
        cfg.attrs = cat;
        cfg.numAttrs = 1;
        cudaLaunchKernelEx(&cfg, moe_gemm_tc<true>, tAh, tAl, tB1h, tB1l, b1);  // idx 3
    }
    moe_gemm_fb<true><<<dim3(DF / 128, MAXT2 * 2), 256>>>(w1, b1);              // idx 4 (no-op on tc build)
    {
        cudaLaunchConfig_t cfg = {};
        cfg.gridDim = dim3(2, NCLUST, 1);
        cfg.blockDim = dim3(256, 1, 1);
        cfg.dynamicSmemBytes = SMEM_DYN;
        cfg.stream = 0;
        cfg.attrs = cat;
        cfg.numAttrs = 1;
        cudaLaunchKernelEx(&cfg, moe_gemm_tc<false>, tHh, tHl, tB2h, tB2l, b2); // idx 5
    }
    moe_gemm_fb<false><<<dim3(DM / 128, MAXT2 * 2), 256>>>(w2, b2);             // idx 6
    combine_kernel<<<T_TOKENS, 256>>>(out);                                     // idx 7
}

// round 11
// speedup vs baseline: 1.5793x; 1.2179x over previous
#include <cuda_runtime.h>
#include <cuda.h>
#include <cuda_bf16.h>
#include <stdint.h>

#define T_TOKENS 8192
#define DM 1024
#define DF 4096
#define NE 8
#define PAIRS 16384
#define MAXTILES 144
#define MAXT2 72
#define NCLUST 74

// tcgen05 availability: only in the arch-SPECIFIC device pass (sm_103a / sm_100a).
#if defined(__CUDA_ARCH__) && (defined(__CUDA_ARCH_FEAT_SM103_ALL) || defined(__CUDA_ARCH_FEAT_SM100_ALL) || defined(__CUDA_ARCH_SPECIFIC__))
#define HAS_TC 1
#else
#define HAS_TC 0
#endif

// ---------------- scratch (device globals; no allocations) ----------------
__device__ __align__(128) __nv_bfloat16 g_Ah[(size_t)PAIRS * DM];
__device__ __align__(128) __nv_bfloat16 g_Al[(size_t)PAIRS * DM];
__device__ __align__(128) float         g_Hf[(size_t)PAIRS * DF];   // raw GEMM1 out (bias added)
__device__ __align__(128) __nv_bfloat16 g_Hh[(size_t)PAIRS * DF];
__device__ __align__(128) __nv_bfloat16 g_Hl[(size_t)PAIRS * DF];
__device__ __align__(128) float         g_Y[(size_t)PAIRS * DM];

__device__ __align__(128) __nv_bfloat16 g_w1h[(size_t)NE * DM * DF];
__device__ __align__(128) __nv_bfloat16 g_w1l[(size_t)NE * DM * DF];
__device__ __align__(128) __nv_bfloat16 g_w2h[(size_t)NE * DF * DM];
__device__ __align__(128) __nv_bfloat16 g_w2l[(size_t)NE * DF * DM];

__device__ int   g_pair_e[PAIRS];
__device__ float g_pair_w[PAIRS];
__device__ int   g_pair_slot[PAIRS];
__device__ int   g_rows_token[PAIRS];

__device__ int g_counts[NE];
__device__ int g_off[NE + 1];
__device__ int g_tile_e[MAXTILES];
__device__ int g_tile_r0[MAXTILES];
__device__ int g_tile_valid[MAXTILES];
__device__ int g_num_tiles;

// ---------------- shared helpers ----------------
__device__ __forceinline__ uint32_t smaddr(const void* p) {
    return (uint32_t)__cvta_generic_to_shared(p);
}
__device__ __forceinline__ uint32_t pack_bf16(__nv_bfloat16 a, __nv_bfloat16 b) {
    return (uint32_t)__bfloat16_as_ushort(a) | ((uint32_t)__bfloat16_as_ushort(b) << 16);
}
__device__ __forceinline__ float gelu_exact(float v) {
    return 0.5f * v * (1.0f + erff(v * 0.70710678118654752f));
}

#if HAS_TC
// ---------------- tcgen05 / cg2 helpers ----------------
__device__ __forceinline__ uint32_t elect_one() {
    uint32_t pred;
    asm volatile("{\n\t.reg .pred p;\n\telect.sync _|p, 0xFFFFFFFF;\n\tselp.b32 %0, 1, 0, p;\n\t}"
                 : "=r"(pred));
    return pred;
}
__device__ __forceinline__ void cluster_sync_() {
    asm volatile("barrier.cluster.arrive.aligned;" ::: "memory");
    asm volatile("barrier.cluster.wait.aligned;" ::: "memory");
}
__device__ __forceinline__ void mbar_init(uint32_t addr, uint32_t cnt) {
    asm volatile("mbarrier.init.shared.b64 [%0], %1;" :: "r"(addr), "r"(cnt) : "memory");
}
__device__ __forceinline__ void mbar_inval(uint32_t addr) {
    asm volatile("mbarrier.inval.shared.b64 [%0];" :: "r"(addr) : "memory");
}
__device__ __forceinline__ void mbar_expect(uint32_t addr, uint32_t bytes) {
    asm volatile("mbarrier.arrive.expect_tx.shared.b64 _, [%0], %1;"
                 :: "r"(addr), "r"(bytes) : "memory");
}
__device__ __forceinline__ void mbar_wait(uint32_t addr, uint32_t parity) {
    asm volatile(
        "{\n\t.reg .pred P1;\n"
        "WAIT_%=:\n\t"
        "mbarrier.try_wait.parity.acquire.cta.shared::cta.b64 P1, [%0], %1, 0x989680;\n\t"
        "@P1 bra.uni DONE_%=;\n\t"
        "bra.uni WAIT_%=;\n"
        "DONE_%=:\n\t}"
        :: "r"(addr), "r"(parity) : "memory");
}
// arrive on rank0's mbarrier (cg2 leader: clear bit 24)
__device__ __forceinline__ void mbar_arrive_leader(uint32_t addr) {
    asm volatile(
        "{\n\t.reg .b32 la;\n\t"
        "and.b32 la, %0, 0xFEFFFFFF;\n\t"
        "mbarrier.arrive.shared::cluster.b64 _, [la];\n\t}"
        :: "r"(addr) : "memory");
}
__device__ __forceinline__ void tma2d_cg2(uint32_t dst, const void* tm, int x, int y, uint32_t mbar) {
    asm volatile(
        "{\n\t.reg .b32 lb;\n\t"
        "and.b32 lb, %4, 0xFEFFFFFF;\n\t"
        "cp.async.bulk.tensor.2d.cta_group::2.shared::cluster.global.tile.mbarrier::complete_tx::bytes "
        "[%0], [%1, {%2, %3}], [lb];\n\t}"
        :: "r"(dst), "l"(tm), "r"(x), "r"(y), "r"(mbar) : "memory");
}
__device__ __forceinline__ void tma3d_cg2(uint32_t dst, const void* tm, int x, int y, int z, uint32_t mbar) {
    asm volatile(
        "{\n\t.reg .b32 lb;\n\t"
        "and.b32 lb, %5, 0xFEFFFFFF;\n\t"
        "cp.async.bulk.tensor.3d.cta_group::2.shared::cluster.global.tile.mbarrier::complete_tx::bytes "
        "[%0], [%1, {%2, %3, %4}], [lb];\n\t}"
        :: "r"(dst), "l"(tm), "r"(x), "r"(y), "r"(z), "r"(mbar) : "memory");
}
__device__ __forceinline__ void tc_mma_f16_ss2(uint32_t d, uint64_t a, uint64_t b,
                                               uint32_t idesc, uint32_t en) {
    asm volatile(
        "{\n\t.reg .pred p;\n\tsetp.ne.u32 p, %5, 0;\n\t"
        "tcgen05.mma.cta_group::2.kind::f16 [%0], %1, %2, %3, "
        "{%4, %4, %4, %4, %4, %4, %4, %4}, p;\n\t}"
        :: "r"(d), "l"(a), "l"(b), "r"(idesc), "r"(0u), "r"(en) : "memory");
}
__device__ __forceinline__ void tc_commit_mc2(uint32_t mbar) {
    asm volatile(
        "tcgen05.commit.cta_group::2.mbarrier::arrive::one.shared::cluster.multicast::cluster.b64 [%0], %1;"
        :: "r"(mbar), "h"((uint16_t)0x3) : "memory");
}
__device__ __forceinline__ void tc_alloc2(uint32_t smem_slot, uint32_t ncols) {
    asm volatile("tcgen05.alloc.cta_group::2.sync.aligned.shared::cta.b32 [%0], %1;"
                 :: "r"(smem_slot), "r"(ncols) : "memory");
}
__device__ __forceinline__ void tc_dealloc2(uint32_t tmem, uint32_t ncols) {
    asm volatile("tcgen05.dealloc.cta_group::2.sync.aligned.b32 %0, %1;" :: "r"(tmem), "r"(ncols));
}
__device__ __forceinline__ void tc_relinq2() {
    asm volatile("tcgen05.relinquish_alloc_permit.cta_group::2.sync.aligned;");
}
__device__ __forceinline__ void tc_fence_after() {
    asm volatile("tcgen05.fence::after_thread_sync;" ::: "memory");
}
__device__ __forceinline__ void tc_fence_before() {
    asm volatile("tcgen05.fence::before_thread_sync;" ::: "memory");
}
__device__ __forceinline__ void tc_wait_ld() {
    asm volatile("tcgen05.wait::ld.sync.aligned;" ::: "memory");
}
__device__ __forceinline__ void tc_ld_x32(uint32_t* r, uint32_t addr) {
    asm volatile(
        "tcgen05.ld.sync.aligned.32x32b.x32.b32 "
        "{%0, %1, %2, %3, %4, %5, %6, %7, %8, %9, %10, %11, %12, %13, %14, %15, "
        " %16, %17, %18, %19, %20, %21, %22, %23, %24, %25, %26, %27, %28, %29, %30, %31}, [%32];"
        : "=r"(r[0]), "=r"(r[1]), "=r"(r[2]), "=r"(r[3]), "=r"(r[4]), "=r"(r[5]), "=r"(r[6]), "=r"(r[7]),
          "=r"(r[8]), "=r"(r[9]), "=r"(r[10]), "=r"(r[11]), "=r"(r[12]), "=r"(r[13]), "=r"(r[14]), "=r"(r[15]),
          "=r"(r[16]), "=r"(r[17]), "=r"(r[18]), "=r"(r[19]), "=r"(r[20]), "=r"(r[21]), "=r"(r[22]), "=r"(r[23]),
          "=r"(r[24]), "=r"(r[25]), "=r"(r[26]), "=r"(r[27]), "=r"(r[28]), "=r"(r[29]), "=r"(r[30]), "=r"(r[31])
        : "r"(addr));
}
// SW128 K-major descriptor base (LBO=1, SBO=64, version=1, layout SW128)
__device__ __forceinline__ uint64_t mk_desc(uint32_t addr) {
    const uint64_t DBASE = (2ULL << 61) | (1ULL << 46) | (64ULL << 32) | (1ULL << 16);
    return DBASE | (uint64_t)((addr >> 4) & 0x3FFF);
}
#endif  // HAS_TC

#if !HAS_TC
// ---------------- fallback-path helpers (mma.sync) ----------------
__device__ __forceinline__ void ldsm4(uint32_t* r, uint32_t addr) {
    asm volatile("ldmatrix.sync.aligned.m8n8.x4.shared.b16 {%0,%1,%2,%3}, [%4];\n"
                 : "=r"(r[0]), "=r"(r[1]), "=r"(r[2]), "=r"(r[3]) : "r"(addr));
}
__device__ __forceinline__ void ldsm4t(uint32_t* r, uint32_t addr) {
    asm volatile("ldmatrix.sync.aligned.m8n8.x4.trans.shared.b16 {%0,%1,%2,%3}, [%4];\n"
                 : "=r"(r[0]), "=r"(r[1]), "=r"(r[2]), "=r"(r[3]) : "r"(addr));
}
__device__ __forceinline__ void mma16816(float* c, const uint32_t* a, const uint32_t* b) {
    asm volatile(
        "mma.sync.aligned.m16n8k16.row.col.f32.bf16.bf16.f32 "
        "{%0,%1,%2,%3}, {%4,%5,%6,%7}, {%8,%9}, {%0,%1,%2,%3};\n"
        : "+f"(c[0]), "+f"(c[1]), "+f"(c[2]), "+f"(c[3])
        : "r"(a[0]), "r"(a[1]), "r"(a[2]), "r"(a[3]), "r"(b[0]), "r"(b[1]));
}
#endif  // !HAS_TC

// ---------------- kernel: gating (routing only) ----------------
__global__ __launch_bounds__(256) void gate_kernel(const float* __restrict__ x,
                                                   const float* __restrict__ gw) {
    const int tk = blockIdx.x;
    const int tid = threadIdx.x;
    const float* xr = x + (size_t)tk * DM;

    float p[NE];
#pragma unroll
    for (int e = 0; e < NE; ++e) p[e] = 0.f;
#pragma unroll
    for (int j = 0; j < 4; ++j) {
        int i = j * 256 + tid;
        float v = xr[i];
#pragma unroll
        for (int e = 0; e < NE; ++e) p[e] += v * gw[e * DM + i];
    }
#pragma unroll
    for (int e = 0; e < NE; ++e)
#pragma unroll
        for (int o = 16; o > 0; o >>= 1) p[e] += __shfl_xor_sync(0xffffffffu, p[e], o);

    __shared__ float sRed[8][NE];
    int lane = tid & 31, w = tid >> 5;
    if (lane == 0) {
#pragma unroll
        for (int e = 0; e < NE; ++e) sRed[w][e] = p[e];
    }
    __syncthreads();
    if (tid == 0) {
        float lg[NE];
#pragma unroll
        for (int e = 0; e < NE; ++e) {
            float s = 0.f;
#pragma unroll
            for (int ww = 0; ww < 8; ++ww) s += sRed[ww][e];
            lg[e] = s;
        }
        float m = lg[0];
#pragma unroll
        for (int e = 1; e < NE; ++e) m = fmaxf(m, lg[e]);
        float ex[NE], S = 0.f;
#pragma unroll
        for (int e = 0; e < NE; ++e) { ex[e] = expf(lg[e] - m); S += ex[e]; }
        int i0 = 0;
#pragma unroll
        for (int e = 1; e < NE; ++e) if (ex[e] > ex[i0]) i0 = e;
        int i1 = (i0 == 0) ? 1 : 0;
#pragma unroll
        for (int e = 0; e < NE; ++e) if (e != i0 && ex[e] > ex[i1]) i1 = e;
        float p0 = ex[i0] / S, p1 = ex[i1] / S;
        float den = p0 + p1 + 1e-9f;
        g_pair_e[2 * tk] = i0;     g_pair_w[2 * tk] = p0 / den;
        g_pair_e[2 * tk + 1] = i1; g_pair_w[2 * tk + 1] = p1 / den;
    }
}

// ---------------- kernel: counting sort (counts + scan + 256-row tiles + scatter) ----------------
__global__ __launch_bounds__(256) void sortscan_kernel() {
    __shared__ uint16_t loc[256][NE];
    __shared__ int s_cnt[NE];
    __shared__ int s_off[NE];
    const int t = threadIdx.x;
    const int p0 = t * 64;

    int lc[NE];
#pragma unroll
    for (int e = 0; e < NE; ++e) lc[e] = 0;
    for (int i = 0; i < 64; ++i) lc[g_pair_e[p0 + i]]++;
#pragma unroll
    for (int e = 0; e < NE; ++e) loc[t][e] = (uint16_t)lc[e];
    __syncthreads();

    if (t < NE) {
        int run = 0;
        for (int i = 0; i < 256; ++i) {
            int c = loc[i][t];
            loc[i][t] = (uint16_t)run;
            run += c;
        }
        s_cnt[t] = run;
        g_counts[t] = run;
    }
    __syncthreads();

    if (t == 0) {
        int off = 0, nt = 0;
        for (int e = 0; e < NE; ++e) {
            g_off[e] = off;
            s_off[e] = off;
            int c = s_cnt[e];
            int tiles = (c + 255) >> 8;
            for (int i = 0; i < tiles; ++i) {
                g_tile_e[nt] = e;
                g_tile_r0[nt] = off + i * 256;
                int v = c - i * 256;
                g_tile_valid[nt] = v > 256 ? 256 : v;
                ++nt;
            }
            off += c;
        }
        g_off[NE] = off;
        g_num_tiles = nt;
    }
    __syncthreads();

    int run[NE];
#pragma unroll
    for (int e = 0; e < NE; ++e) run[e] = s_off[e] + (int)loc[t][e];
    for (int i = 0; i < 64; ++i) {
        int p = p0 + i;
        int e = g_pair_e[p];
        int slot = run[e]++;
        g_pair_slot[p] = slot;
        g_rows_token[slot] = p >> 1;
    }
}

// ---------------- kernel: prep = A-gather (z==16) + weight split/transpose (z<16) ----------------
__global__ __launch_bounds__(256) void prep_kernel(const float* __restrict__ x,
                                                   const float* __restrict__ w1,
                                                   const float* __restrict__ w2) {
    const int z = blockIdx.z;
    const int t = threadIdx.x;

    if (z == 16) {
        const int b = blockIdx.y * 64 + blockIdx.x;
        for (int rr = 0; rr < 16; ++rr) {
            const int slot = b * 16 + rr;
            const int tok = g_rows_token[slot];
            const float4 v = reinterpret_cast<const float4*>(x + (size_t)tok * DM)[t];
            __nv_bfloat16 h0 = __float2bfloat16_rn(v.x), h1 = __float2bfloat16_rn(v.y);
            __nv_bfloat16 h2 = __float2bfloat16_rn(v.z), h3 = __float2bfloat16_rn(v.w);
            __nv_bfloat16 l0 = __float2bfloat16_rn(v.x - __bfloat162float(h0));
            __nv_bfloat16 l1 = __float2bfloat16_rn(v.y - __bfloat162float(h1));
            __nv_bfloat16 l2 = __float2bfloat16_rn(v.z - __bfloat162float(h2));
            __nv_bfloat16 l3 = __float2bfloat16_rn(v.w - __bfloat162float(h3));
            reinterpret_cast<uint2*>(g_Ah + (size_t)slot * DM)[t] =
                make_uint2(pack_bf16(h0, h1), pack_bf16(h2, h3));
            reinterpret_cast<uint2*>(g_Al + (size_t)slot * DM)[t] =
                make_uint2(pack_bf16(l0, l1), pack_bf16(l2, l3));
        }
        return;
    }

#if HAS_TC
    __shared__ float tile[64][65];
    const int layer = z >> 3;
    const int e = z & 7;
    const int K = layer ? DF : DM;
    const int N = layer ? DM : DF;
    const int K0 = (layer ? blockIdx.x : blockIdx.y) * 64;
    const int N0 = (layer ? blockIdx.y : blockIdx.x) * 64;
    const float* W = layer ? w2 : w1;
    __nv_bfloat16* Wh = layer ? g_w2h : g_w1h;
    __nv_bfloat16* Wl = layer ? g_w2l : g_w1l;

    const float* src = W + ((size_t)e * K + K0) * N + N0;
    const int r = t >> 4, c4 = (t & 15) * 4;
#pragma unroll
    for (int j = 0; j < 4; ++j) {
        int rr = r + j * 16;
        const float4 v = *reinterpret_cast<const float4*>(src + (size_t)rr * N + c4);
        tile[rr][c4 + 0] = v.x; tile[rr][c4 + 1] = v.y;
        tile[rr][c4 + 2] = v.z; tile[rr][c4 + 3] = v.w;
    }
    __syncthreads();
#pragma unroll
    for (int j = 0; j < 4; ++j) {
        int nn = r + j * 16;
        float v0 = tile[c4 + 0][nn], v1 = tile[c4 + 1][nn];
        float v2 = tile[c4 + 2][nn], v3 = tile[c4 + 3][nn];
        __nv_bfloat16 h0 = __float2bfloat16_rn(v0), h1 = __float2bfloat16_rn(v1);
        __nv_bfloat16 h2 = __float2bfloat16_rn(v2), h3 = __float2bfloat16_rn(v3);
        __nv_bfloat16 l0 = __float2bfloat16_rn(v0 - __bfloat162float(h0));
        __nv_bfloat16 l1 = __float2bfloat16_rn(v1 - __bfloat162float(h1));
        __nv_bfloat16 l2 = __float2bfloat16_rn(v2 - __bfloat162float(h2));
        __nv_bfloat16 l3 = __float2bfloat16_rn(v3 - __bfloat162float(h3));
        size_t out = ((size_t)e * N + N0 + nn) * K + K0 + c4;
        *reinterpret_cast<uint2*>(Wh + out) = make_uint2(pack_bf16(h0, h1), pack_bf16(h2, h3));
        *reinterpret_cast<uint2*>(Wl + out) = make_uint2(pack_bf16(l0, l1), pack_bf16(l2, l3));
    }
#endif
}

// ---------------- kernel: post-GEMM1 GELU + hi/lo split (streaming) ----------------
__global__ __launch_bounds__(256) void postgelu_kernel() {
    const size_t base = (size_t)blockIdx.x * DF;
    const int t = threadIdx.x;
#pragma unroll
    for (int j = 0; j < 4; ++j) {
        const int i = (j * 256 + t) * 4;
        const float4 v = *reinterpret_cast<const float4*>(g_Hf + base + i);
        float a0 = gelu_exact(v.x);
        float a1 = gelu_exact(v.y);
        float a2 = gelu_exact(v.z);
        float a3 = gelu_exact(v.w);
        __nv_bfloat16 h0 = __float2bfloat16_rn(a0), h1 = __float2bfloat16_rn(a1);
        __nv_bfloat16 h2 = __float2bfloat16_rn(a2), h3 = __float2bfloat16_rn(a3);
        __nv_bfloat16 l0 = __float2bfloat16_rn(a0 - __bfloat162float(h0));
        __nv_bfloat16 l1 = __float2bfloat16_rn(a1 - __bfloat162float(h1));
        __nv_bfloat16 l2 = __float2bfloat16_rn(a2 - __bfloat162float(h2));
        __nv_bfloat16 l3 = __float2bfloat16_rn(a3 - __bfloat162float(h3));
        *reinterpret_cast<uint2*>(g_Hh + base + i) = make_uint2(pack_bf16(h0, h1), pack_bf16(h2, h3));
        *reinterpret_cast<uint2*>(g_Hl + base + i) = make_uint2(pack_bf16(l0, l1), pack_bf16(l2, l3));
    }
}

// ---------------- tcgen05 cg2 GEMM: persistent clusters, double-buffered TMEM D ----------------
#define BUF_STRIDE 65536
#define OFF_AL 16384
#define OFF_BH 32768
#define OFF_BL 49152
#define OFF_TMEM 196608
#define OFF_MBAR 196624
#define SMEM_DYN 198656
#define STAGE_BYTES 65536u
// mbar layout: full[0..2]@+0,8,16 ; empty[0..2]@+24,32,40 ; done[0..1]@+48,56 ; free[0..1]@+64,72

#define GEMM_IDESC2 ((1u << 4) | (1u << 7) | (1u << 10) | ((256u / 8) << 17) | ((256u / 16) << 24))

template <bool FIRST>
__global__ __launch_bounds__(256)
void moe_gemm_tc(const __grid_constant__ CUtensorMap tmAh,
                 const __grid_constant__ CUtensorMap tmAl,
                 const __grid_constant__ CUtensorMap tmBh,
                 const __grid_constant__ CUtensorMap tmBl,
                 const float* __restrict__ bias) {
#if HAS_TC
    constexpr int KTOT = FIRST ? DM : DF;
    constexpr int NTOT = FIRST ? DF : DM;
    constexpr int NC = KTOT / 64;
    constexpr int NXT = NTOT / 256;

    const int cid = blockIdx.y;
    const int rank = blockIdx.x & 1;
    const int tot = g_num_tiles * NXT;

    extern __shared__ char dyn[];
    const uint32_t raw = smaddr(dyn);
    const uint32_t sbase = (raw + 1023u) & ~1023u;
    const int t = threadIdx.x;
    const int w = t >> 5, lane = t & 31;

    if (w == 0) {
        tc_alloc2(sbase + OFF_TMEM, 512);
        tc_relinq2();
    }
    if (t == 0) {
#pragma unroll
        for (int s = 0; s < 8; ++s) mbar_init(sbase + OFF_MBAR + s * 8, 1);
        mbar_init(sbase + OFF_MBAR + 64, 2);
        mbar_init(sbase + OFF_MBAR + 72, 2);
    }
    __syncthreads();
    cluster_sync_();

    uint32_t tmem;
    asm volatile("ld.shared.b32 %0, [%1];" : "=r"(tmem) : "r"(sbase + OFF_TMEM));

    const uint32_t mbF = sbase + OFF_MBAR;
    const uint32_t mbE = sbase + OFF_MBAR + 24;
    const uint32_t mbD = sbase + OFF_MBAR + 48;
    const uint32_t mbR = sbase + OFF_MBAR + 64;

    if (w == 0 && elect_one()) {
        // ================= producer: continuous TMA across tiles =================
        uint32_t pE = 0, pDp = 0;
        int s = 0;
#pragma unroll 1
        for (int tt = 0;; ++tt) {
            const int T = cid + tt * NCLUST;
            if (T >= tot) break;
            const int rt = T / NXT, nt = T % NXT;
            const int e = g_tile_e[rt];
            const int arow = g_tile_r0[rt] + rank * 128;
            const int bcol = nt * 256 + rank * 128;
#pragma unroll 1
            for (int i = 0; i < NC; ++i, ++s) {
                const int b = s % 3;
                if (s >= 3) {
                    const int sp_ = s - 3;
                    if ((sp_ % NC) == NC - 1) {
                        const int d = (sp_ / NC) & 1;
                        mbar_wait(mbD + d * 8, (pDp >> d) & 1u); pDp ^= 1u << d;
                    } else {
                        mbar_wait(mbE + b * 8, (pE >> b) & 1u); pE ^= 1u << b;
                    }
                }
                if (rank == 0) mbar_expect(mbF + b * 8, 2u * STAGE_BYTES);
                const uint32_t bb = sbase + (uint32_t)b * BUF_STRIDE;
                const int k0 = i * 64;
                tma2d_cg2(bb,          (const void*)&tmAh, k0, arow, mbF + b * 8);
                tma2d_cg2(bb + OFF_AL, (const void*)&tmAl, k0, arow, mbF + b * 8);
                tma3d_cg2(bb + OFF_BH, (const void*)&tmBh, k0, bcol, e, mbF + b * 8);
                tma3d_cg2(bb + OFF_BL, (const void*)&tmBl, k0, bcol, e, mbF + b * 8);
            }
        }
    } else if (w == 1 && rank == 0 && elect_one()) {
        // ================= consumer: MMA =================
        uint64_t dA[3], dAl_[3], dB[3], dBl_[3];
#pragma unroll
        for (int s2 = 0; s2 < 3; ++s2) {
            uint32_t b = sbase + s2 * BUF_STRIDE;
            dA[s2]   = mk_desc(b);
            dAl_[s2] = mk_desc(b + OFF_AL);
            dB[s2]   = mk_desc(b + OFF_BH);
            dBl_[s2] = mk_desc(b + OFF_BL);
        }
        uint32_t pF = 0, pFree = 0;
        int s = 0, ttn = 0;
#pragma unroll 1
        for (int tt = 0;; ++tt) {
            const int T = cid + tt * NCLUST;
            if (T >= tot) break;
            ttn = tt + 1;
            const int d = tt & 1;
            if (tt >= 2) {
                mbar_wait(mbR + d * 8, (pFree >> d) & 1u); pFree ^= 1u << d;
                tc_fence_after();
            }
            const uint32_t dtm = tmem + d * 256;
#pragma unroll 1
            for (int i = 0; i < NC; ++i, ++s) {
                const int b = s % 3;
                mbar_wait(mbF + b * 8, (pF >> b) & 1u); pF ^= 1u << b;
#pragma unroll
                for (int ks = 0; ks < 4; ++ks) {
                    const uint64_t oa = (uint64_t)(ks * 2);
                    const uint32_t en0 = (i == 0 && ks == 0) ? 0u : 1u;
                    tc_mma_f16_ss2(dtm, dA[b] + oa,   dB[b] + oa,   GEMM_IDESC2, en0);
                    tc_mma_f16_ss2(dtm, dA[b] + oa,   dBl_[b] + oa, GEMM_IDESC2, 1u);
                    tc_mma_f16_ss2(dtm, dAl_[b] + oa, dB[b] + oa,   GEMM_IDESC2, 1u);
                }
                tc_commit_mc2((i == NC - 1) ? (mbD + d * 8) : (mbE + b * 8));
            }
        }
#pragma unroll 1
        for (int k = (ttn >= 2 ? ttn - 2 : 0); k < ttn; ++k) {
            const int d = k & 1;
            mbar_wait(mbR + d * 8, (pFree >> d) & 1u); pFree ^= 1u << d;
        }
    } else if (w >= 2) {
        // ================= epilogue: warps 2..7 (raw fp32 + bias only) =================
        const int sp_ = w & 3;
        const int rloc = sp_ * 32 + lane;
        int cstart, cnum;
        if (w == 4 || w == 5)      { cstart = 0;   cnum = 8; }
        else if (w == 2 || w == 3) { cstart = 0;   cnum = 4; }
        else                       { cstart = 128; cnum = 4; }

        uint32_t pDe = 0;
#pragma unroll 1
        for (int tt = 0;; ++tt) {
            const int T = cid + tt * NCLUST;
            if (T >= tot) break;
            const int d = tt & 1;
            mbar_wait(mbD + d * 8, (pDe >> d) & 1u); pDe ^= 1u << d;
            tc_fence_after();

            const int rt = T / NXT, nt = T % NXT;
            const int e = g_tile_e[rt];
            const int row0 = g_tile_r0[rt];
            const int n0 = nt * 256;
            int vr = g_tile_valid[rt] - rank * 128;
            vr = vr < 0 ? 0 : (vr > 128 ? 128 : vr);
            const bool valid = rloc < vr;
            const int rowg = row0 + rank * 128 + rloc;
            const uint32_t dtm = tmem + d * 256;
            const float* bb = bias + (size_t)e * NTOT + n0;
            float* oF = (FIRST ? g_Hf + (size_t)rowg * DF : g_Y + (size_t)rowg * DM) + n0;

#pragma unroll 1
            for (int j = 0; j < cnum; ++j) {
                const int col = cstart + j * 32;
                uint32_t dr[32];
                tc_ld_x32(dr, dtm + col);
                tc_wait_ld();
                if (valid) {
#pragma unroll
                    for (int c = 0; c < 32; c += 4) {
                        float4 o;
                        o.x = __uint_as_float(dr[c + 0]) + bb[col + c + 0];
                        o.y = __uint_as_float(dr[c + 1]) + bb[col + c + 1];
                        o.z = __uint_as_float(dr[c + 2]) + bb[col + c + 2];
                        o.w = __uint_as_float(dr[c + 3]) + bb[col + c + 3];
                        *reinterpret_cast<float4*>(oF + col + c) = o;
                    }
                }
            }
            tc_fence_before();
            asm volatile("bar.sync 1, 192;" ::: "memory");
            if (w == 2 && elect_one()) mbar_arrive_leader(mbR + d * 8);
        }
    }

    __syncthreads();
    if (t == 0) {
#pragma unroll
        for (int s = 0; s < 10; ++s) mbar_inval(sbase + OFF_MBAR + s * 8);
    }
    __syncthreads();
    cluster_sync_();
    if (w == 0) tc_dealloc2(tmem, 512);
    cluster_sync_();
#endif  // HAS_TC
}

// ---------------- fallback GEMM (mma.sync; 256-tiles split in half) ----------------
template <bool FIRST>
__global__ __launch_bounds__(256) void moe_gemm_fb(const float* __restrict__ W,
                                                   const float* __restrict__ bias) {
#if !HAS_TC
    constexpr int KTOT = FIRST ? DM : DF;
    constexpr int LDW  = FIRST ? DF : DM;
    const int tileIdx = blockIdx.y >> 1;
    if (tileIdx >= g_num_tiles) return;
    const int half = blockIdx.y & 1;
    const int e = g_tile_e[tileIdx];
    const int row0 = g_tile_r0[tileIdx] + half * 128;
    int vrows = g_tile_valid[tileIdx] - half * 128;
    vrows = vrows < 0 ? 0 : (vrows > 128 ? 128 : vrows);
    if (vrows == 0) return;
    const int n0 = blockIdx.x * 128;
    const float* Wn = W + (size_t)e * KTOT * LDW + n0;
    const float* bn = bias + (size_t)e * LDW + n0;

    __shared__ __align__(16) __nv_bfloat16 sAh[128 * 40];
    __shared__ __align__(16) __nv_bfloat16 sAl[128 * 40];
    __shared__ __align__(16) __nv_bfloat16 sBh[32 * 136];
    __shared__ __align__(16) __nv_bfloat16 sBl[32 * 136];

    const int t = threadIdx.x;
    float c[4][4][4];
#pragma unroll
    for (int a = 0; a < 4; ++a)
#pragma unroll
        for (int b = 0; b < 4; ++b)
#pragma unroll
            for (int q = 0; q < 4; ++q) c[a][b][q] = 0.f;

    const int lane = t & 31, warp = t >> 5;
    const int wm = warp >> 2, wn = warp & 3;
    const int m0 = wm * 64;
    const int sub = t & 15, rgrp = t >> 4;

    for (int k0 = 0; k0 < KTOT; k0 += 32) {
        __syncthreads();
#pragma unroll
        for (int rr = 0; rr < 8; ++rr) {
            int r = rr * 16 + rgrp;
            int rg = row0 + r; if (rg > PAIRS - 1) rg = PAIRS - 1;
            const uint32_t* ph = reinterpret_cast<const uint32_t*>(
                (FIRST ? g_Ah : g_Hh) + (size_t)rg * KTOT + k0);
            const uint32_t* pl = reinterpret_cast<const uint32_t*>(
                (FIRST ? g_Al : g_Hl) + (size_t)rg * KTOT + k0);
            *reinterpret_cast<uint32_t*>(&sAh[r * 40 + sub * 2]) = ph[sub];
            *reinterpret_cast<uint32_t*>(&sAl[r * 40 + sub * 2]) = pl[sub];
        }
#pragma unroll
        for (int i = 0; i < 4; ++i) {
            int lin = (i * 256 + t) * 4;
            int kr = lin >> 7;
            int nc = lin & 127;
            const float4 v = *reinterpret_cast<const float4*>(Wn + (size_t)(k0 + kr) * LDW + nc);
            __nv_bfloat16 h0 = __float2bfloat16_rn(v.x);
            __nv_bfloat16 h1 = __float2bfloat16_rn(v.y);
            __nv_bfloat16 h2 = __float2bfloat16_rn(v.z);
            __nv_bfloat16 h3 = __float2bfloat16_rn(v.w);
            __nv_bfloat16 l0 = __float2bfloat16_rn(v.x - __bfloat162float(h0));
            __nv_bfloat16 l1 = __float2bfloat16_rn(v.y - __bfloat162float(h1));
            __nv_bfloat16 l2 = __float2bfloat16_rn(v.z - __bfloat162float(h2));
            __nv_bfloat16 l3 = __float2bfloat16_rn(v.w - __bfloat162float(h3));
            *reinterpret_cast<uint2*>(&sBh[kr * 136 + nc]) = make_uint2(pack_bf16(h0, h1), pack_bf16(h2, h3));
            *reinterpret_cast<uint2*>(&sBl[kr * 136 + nc]) = make_uint2(pack_bf16(l0, l1), pack_bf16(l2, l3));
        }
        __syncthreads();

#pragma unroll
        for (int ks = 0; ks < 2; ++ks) {
            uint32_t ah[4][4], al[4][4], bh[4][2], bl[4][2];
            {
                int ar = lane & 15;
                int acol = ks * 16 + (lane >> 4) * 8;
#pragma unroll
                for (int fm = 0; fm < 4; ++fm) {
                    ldsm4(ah[fm], smaddr(&sAh[(m0 + fm * 16 + ar) * 40 + acol]));
                    ldsm4(al[fm], smaddr(&sAl[(m0 + fm * 16 + ar) * 40 + acol]));
                }
                int brow = ks * 16 + (lane & 15);
                int bcol = wn * 32 + (lane >> 4) * 8;
#pragma unroll
                for (int hb = 0; hb < 2; ++hb) {
                    uint32_t r[4];
                    ldsm4t(r, smaddr(&sBh[brow * 136 + bcol + hb * 16]));
                    bh[2 * hb][0] = r[0]; bh[2 * hb][1] = r[1];
                    bh[2 * hb + 1][0] = r[2]; bh[2 * hb + 1][1] = r[3];
                    ldsm4t(r, smaddr(&sBl[brow * 136 + bcol + hb * 16]));
                    bl[2 * hb][0] = r[0]; bl[2 * hb][1] = r[1];
                    bl[2 * hb + 1][0] = r[2]; bl[2 * hb + 1][1] = r[3];
                }
            }
#pragma unroll
            for (int fm = 0; fm < 4; ++fm)
#pragma unroll
                for (int fn = 0; fn < 4; ++fn) {
                    mma16816(c[fm][fn], ah[fm], bh[fn]);
                    mma16816(c[fm][fn], ah[fm], bl[fn]);
                    mma16816(c[fm][fn], al[fm], bh[fn]);
                }
        }
    }

    const int lgrp = lane >> 2, lq = lane & 3;
#pragma unroll
    for (int fm = 0; fm < 4; ++fm) {
        int rl = m0 + fm * 16 + lgrp;
#pragma unroll
        for (int fn = 0; fn < 4; ++fn) {
            int nc = wn * 32 + fn * 8 + lq * 2;
            float bv0 = bn[nc], bv1 = bn[nc + 1];
            float* cc = c[fm][fn];
#pragma unroll
            for (int h = 0; h < 2; ++h) {
                int rloc = rl + h * 8;
                if (rloc < vrows) {
                    int row = row0 + rloc;
                    float v0 = cc[h * 2 + 0] + bv0;
                    float v1 = cc[h * 2 + 1] + bv1;
                    if (FIRST) {
                        *reinterpret_cast<float2*>(&g_Hf[(size_t)row * DF + n0 + nc]) = make_float2(v0, v1);
                    } else {
                        *reinterpret_cast<float2*>(&g_Y[(size_t)row * DM + n0 + nc]) = make_float2(v0, v1);
                    }
                }
            }
        }
    }
#endif  // !HAS_TC
}

// ---------------- kernel: weighted combine ----------------
__global__ __launch_bounds__(256) void combine_kernel(float* __restrict__ out) {
    const int tk = blockIdx.x;
    const int d = threadIdx.x * 4;
    int s0 = g_pair_slot[2 * tk], s1 = g_pair_slot[2 * tk + 1];
    float w0 = g_pair_w[2 * tk], w1 = g_pair_w[2 * tk + 1];
    const float4 a = *reinterpret_cast<const float4*>(&g_Y[(size_t)s0 * DM + d]);
    const float4 b = *reinterpret_cast<const float4*>(&g_Y[(size_t)s1 * DM + d]);
    float4 o;
    o.x = w0 * a.x + w1 * b.x;
    o.y = w0 * a.y + w1 * b.y;
    o.z = w0 * a.z + w1 * b.z;
    o.w = w0 * a.w + w1 * b.w;
    *reinterpret_cast<float4*>(&out[(size_t)tk * DM + d]) = o;
}

// ---------------- host: tensor map construction ----------------
typedef CUresult (*TmEncodeFn)(CUtensorMap*, CUtensorMapDataType, cuuint32_t, void*,
                               const cuuint64_t*, const cuuint64_t*, const cuuint32_t*,
                               const cuuint32_t*, CUtensorMapInterleave, CUtensorMapSwizzle,
                               CUtensorMapL2promotion, CUtensorMapFloatOOBfill);

static void tm2d(TmEncodeFn enc, CUtensorMap* tm, void* base, unsigned long long K,
                 unsigned long long R) {
    cuuint64_t dims[2] = {K, R};
    cuuint64_t st[1] = {K * 2};
    cuuint32_t box[2] = {64, 128};
    cuuint32_t es[2] = {1, 1};
    enc(tm, CU_TENSOR_MAP_DATA_TYPE_BFLOAT16, 2, base, dims, st, box, es,
        CU_TENSOR_MAP_INTERLEAVE_NONE, CU_TENSOR_MAP_SWIZZLE_128B,
        CU_TENSOR_MAP_L2_PROMOTION_L2_128B, CU_TENSOR_MAP_FLOAT_OOB_FILL_NONE);
}
static void tm3d(TmEncodeFn enc, CUtensorMap* tm, void* base, unsigned long long K,
                 unsigned long long N) {
    cuuint64_t dims[3] = {K, N, NE};
    cuuint64_t st[2] = {K * 2, N * K * 2};
    cuuint32_t box[3] = {64, 128, 1};
    cuuint32_t es[3] = {1, 1, 1};
    enc(tm, CU_TENSOR_MAP_DATA_TYPE_BFLOAT16, 3, base, dims, st, box, es,
        CU_TENSOR_MAP_INTERLEAVE_NONE, CU_TENSOR_MAP_SWIZZLE_128B,
        CU_TENSOR_MAP_L2_PROMOTION_L2_128B, CU_TENSOR_MAP_FLOAT_OOB_FILL_NONE);
}

// ---------------- launch ----------------
extern "C" void kernel_launch(void* const* d_in, const int* in_sizes, int n_in,
                              void* d_out, int out_size) {
    const float* x  = (const float*)d_in[0];
    const float* gw = (const float*)d_in[1];
    const float* w1 = (const float*)d_in[2];
    const float* b1 = (const float*)d_in[3];
    const float* w2 = (const float*)d_in[4];
    const float* b2 = (const float*)d_in[5];
    float* out = (float*)d_out;

    cudaFuncSetAttribute(moe_gemm_tc<true>,  cudaFuncAttributeMaxDynamicSharedMemorySize, SMEM_DYN);
    cudaFuncSetAttribute(moe_gemm_tc<false>, cudaFuncAttributeMaxDynamicSharedMemorySize, SMEM_DYN);

    void *pAh, *pAl, *pHh, *pHl, *pW1h, *pW1l, *pW2h, *pW2l;
    cudaGetSymbolAddress(&pAh, g_Ah);
    cudaGetSymbolAddress(&pAl, g_Al);
    cudaGetSymbolAddress(&pHh, g_Hh);
    cudaGetSymbolAddress(&pHl, g_Hl);
    cudaGetSymbolAddress(&pW1h, g_w1h);
    cudaGetSymbolAddress(&pW1l, g_w1l);
    cudaGetSymbolAddress(&pW2h, g_w2h);
    cudaGetSymbolAddress(&pW2l, g_w2l);

    void* sym = nullptr;
    cudaDriverEntryPointQueryResult qr;
    cudaGetDriverEntryPoint("cuTensorMapEncodeTiled", &sym, cudaEnableDefault, &qr);
    TmEncodeFn enc = (TmEncodeFn)sym;

    CUtensorMap tAh, tAl, tB1h, tB1l, tHh, tHl, tB2h, tB2l;
    if (enc) {
        tm2d(enc, &tAh, pAh, DM, PAIRS);
        tm2d(enc, &tAl, pAl, DM, PAIRS);
        tm3d(enc, &tB1h, pW1h, DM, DF);
        tm3d(enc, &tB1l, pW1l, DM, DF);
        tm2d(enc, &tHh, pHh, DF, PAIRS);
        tm2d(enc, &tHl, pHl, DF, PAIRS);
        tm3d(enc, &tB2h, pW2h, DF, DM);
        tm3d(enc, &tB2l, pW2l, DF, DM);
    }

    gate_kernel<<<T_TOKENS, 256>>>(x, gw);                                     // idx 0
    sortscan_kernel<<<1, 256>>>();                                             // idx 1
    prep_kernel<<<dim3(64, 16, 17), 256>>>(x, w1, w2);                         // idx 2

    cudaLaunchAttribute cat[1];
    cat[0].id = cudaLaunchAttributeClusterDimension;
    cat[0].val.clusterDim.x = 2;
    cat[0].val.clusterDim.y = 1;
    cat[0].val.clusterDim.z = 1;

    {
        cudaLaunchConfig_t cfg = {};
        cfg.gridDim = dim3(2, NCLUST, 1);
        cfg.blockDim = dim3(256, 1, 1);
        cfg.dynamicSmemBytes = SMEM_DYN;
        cfg.stream = 0;
        cfg.attrs = cat;
        cfg.numAttrs = 1;
        cudaLaunchKernelEx(&cfg, moe_gemm_tc<true>, tAh, tAl, tB1h, tB1l, b1);  // idx 3
    }
    moe_gemm_fb<true><<<dim3(DF / 128, MAXT2 * 2), 256>>>(w1, b1);              // idx 4 (no-op on tc build)
    postgelu_kernel<<<PAIRS, 256>>>();                                          // idx 5
    {
        cudaLaunchConfig_t cfg = {};
        cfg.gridDim = dim3(2, NCLUST, 1);
        cfg.blockDim = dim3(256, 1, 1);
        cfg.dynamicSmemBytes = SMEM_DYN;
        cfg.stream = 0;
        cfg.attrs = cat;
        cfg.numAttrs = 1;
        cudaLaunchKernelEx(&cfg, moe_gemm_tc<false>, tHh, tHl, tB2h, tB2l, b2); // idx 6
    }
    moe_gemm_fb<false><<<dim3(DM / 128, MAXT2 * 2), 256>>>(w2, b2);             // idx 7
    combine_kernel<<<T_TOKENS, 256>>>(out);                                     // idx 8
}

// round 12
// speedup vs baseline: 1.5822x; 1.0019x over previous
#include <cuda_runtime.h>
#include <cuda.h>
#include <cuda_bf16.h>
#include <stdint.h>

#define T_TOKENS 8192
#define DM 1024
#define DF 4096
#define NE 8
#define PAIRS 16384
#define MAXTILES 144
#define MAXT2 72
#define NCLUST 74

// tcgen05 availability: only in the arch-SPECIFIC device pass (sm_103a / sm_100a).
#if defined(__CUDA_ARCH__) && (defined(__CUDA_ARCH_FEAT_SM103_ALL) || defined(__CUDA_ARCH_FEAT_SM100_ALL) || defined(__CUDA_ARCH_SPECIFIC__))
#define HAS_TC 1
#else
#define HAS_TC 0
#endif

// ---------------- scratch (device globals; no allocations) ----------------
__device__ __align__(128) __nv_bfloat16 g_Ah[(size_t)PAIRS * DM];
__device__ __align__(128) __nv_bfloat16 g_Al[(size_t)PAIRS * DM];
__device__ __align__(128) float         g_Hf[(size_t)PAIRS * DF];   // raw GEMM1 out (bias added)
__device__ __align__(128) __nv_bfloat16 g_Hh[(size_t)PAIRS * DF];
__device__ __align__(128) __nv_bfloat16 g_Hl[(size_t)PAIRS * DF];
__device__ __align__(128) float         g_Y[(size_t)PAIRS * DM];

__device__ __align__(128) __nv_bfloat16 g_w1h[(size_t)NE * DM * DF];
__device__ __align__(128) __nv_bfloat16 g_w1l[(size_t)NE * DM * DF];
__device__ __align__(128) __nv_bfloat16 g_w2h[(size_t)NE * DF * DM];
__device__ __align__(128) __nv_bfloat16 g_w2l[(size_t)NE * DF * DM];

__device__ int   g_pair_e[PAIRS];
__device__ float g_pair_w[PAIRS];
__device__ int   g_pair_slot[PAIRS];
__device__ int   g_rows_token[PAIRS];

__device__ int g_counts[NE];
__device__ int g_off[NE + 1];
__device__ int g_tile_e[MAXTILES];
__device__ int g_tile_r0[MAXTILES];
__device__ int g_tile_valid[MAXTILES];
__device__ int g_num_tiles;

// ---------------- shared helpers ----------------
__device__ __forceinline__ uint32_t smaddr(const void* p) {
    return (uint32_t)__cvta_generic_to_shared(p);
}
__device__ __forceinline__ uint32_t pack_bf16(__nv_bfloat16 a, __nv_bfloat16 b) {
    return (uint32_t)__bfloat16_as_ushort(a) | ((uint32_t)__bfloat16_as_ushort(b) << 16);
}
__device__ __forceinline__ float gelu_exact(float v) {
    return 0.5f * v * (1.0f + erff(v * 0.70710678118654752f));
}

#if HAS_TC
// ---------------- tcgen05 / cg2 helpers ----------------
__device__ __forceinline__ uint32_t elect_one() {
    uint32_t pred;
    asm volatile("{\n\t.reg .pred p;\n\telect.sync _|p, 0xFFFFFFFF;\n\tselp.b32 %0, 1, 0, p;\n\t}"
                 : "=r"(pred));
    return pred;
}
__device__ __forceinline__ void cluster_sync_() {
    asm volatile("barrier.cluster.arrive.aligned;" ::: "memory");
    asm volatile("barrier.cluster.wait.aligned;" ::: "memory");
}
__device__ __forceinline__ void mbar_init(uint32_t addr, uint32_t cnt) {
    asm volatile("mbarrier.init.shared.b64 [%0], %1;" :: "r"(addr), "r"(cnt) : "memory");
}
__device__ __forceinline__ void mbar_inval(uint32_t addr) {
    asm volatile("mbarrier.inval.shared.b64 [%0];" :: "r"(addr) : "memory");
}
__device__ __forceinline__ void mbar_expect(uint32_t addr, uint32_t bytes) {
    asm volatile("mbarrier.arrive.expect_tx.shared.b64 _, [%0], %1;"
                 :: "r"(addr), "r"(bytes) : "memory");
}
__device__ __forceinline__ void mbar_wait(uint32_t addr, uint32_t parity) {
    asm volatile(
        "{\n\t.reg .pred P1;\n"
        "WAIT_%=:\n\t"
        "mbarrier.try_wait.parity.acquire.cta.shared::cta.b64 P1, [%0], %1, 0x989680;\n\t"
        "@P1 bra.uni DONE_%=;\n\t"
        "bra.uni WAIT_%=;\n"
        "DONE_%=:\n\t}"
        :: "r"(addr), "r"(parity) : "memory");
}
// arrive on rank0's mbarrier (cg2 leader: clear bit 24)
__device__ __forceinline__ void mbar_arrive_leader(uint32_t addr) {
    asm volatile(
        "{\n\t.reg .b32 la;\n\t"
        "and.b32 la, %0, 0xFEFFFFFF;\n\t"
        "mbarrier.arrive.shared::cluster.b64 _, [la];\n\t}"
        :: "r"(addr) : "memory");
}
__device__ __forceinline__ void tma2d_cg2(uint32_t dst, const void* tm, int x, int y, uint32_t mbar) {
    asm volatile(
        "{\n\t.reg .b32 lb;\n\t"
        "and.b32 lb, %4, 0xFEFFFFFF;\n\t"
        "cp.async.bulk.tensor.2d.cta_group::2.shared::cluster.global.tile.mbarrier::complete_tx::bytes "
        "[%0], [%1, {%2, %3}], [lb];\n\t}"
        :: "r"(dst), "l"(tm), "r"(x), "r"(y), "r"(mbar) : "memory");
}
__device__ __forceinline__ void tma3d_cg2(uint32_t dst, const void* tm, int x, int y, int z, uint32_t mbar) {
    asm volatile(
        "{\n\t.reg .b32 lb;\n\t"
        "and.b32 lb, %5, 0xFEFFFFFF;\n\t"
        "cp.async.bulk.tensor.3d.cta_group::2.shared::cluster.global.tile.mbarrier::complete_tx::bytes "
        "[%0], [%1, {%2, %3, %4}], [lb];\n\t}"
        :: "r"(dst), "l"(tm), "r"(x), "r"(y), "r"(z), "r"(mbar) : "memory");
}
__device__ __forceinline__ void tc_mma_f16_ss2(uint32_t d, uint64_t a, uint64_t b,
                                               uint32_t idesc, uint32_t en) {
    asm volatile(
        "{\n\t.reg .pred p;\n\tsetp.ne.u32 p, %5, 0;\n\t"
        "tcgen05.mma.cta_group::2.kind::f16 [%0], %1, %2, %3, "
        "{%4, %4, %4, %4, %4, %4, %4, %4}, p;\n\t}"
        :: "r"(d), "l"(a), "l"(b), "r"(idesc), "r"(0u), "r"(en) : "memory");
}
__device__ __forceinline__ void tc_commit_mc2(uint32_t mbar) {
    asm volatile(
        "tcgen05.commit.cta_group::2.mbarrier::arrive::one.shared::cluster.multicast::cluster.b64 [%0], %1;"
        :: "r"(mbar), "h"((uint16_t)0x3) : "memory");
}
__device__ __forceinline__ void tc_alloc2(uint32_t smem_slot, uint32_t ncols) {
    asm volatile("tcgen05.alloc.cta_group::2.sync.aligned.shared::cta.b32 [%0], %1;"
                 :: "r"(smem_slot), "r"(ncols) : "memory");
}
__device__ __forceinline__ void tc_dealloc2(uint32_t tmem, uint32_t ncols) {
    asm volatile("tcgen05.dealloc.cta_group::2.sync.aligned.b32 %0, %1;" :: "r"(tmem), "r"(ncols));
}
__device__ __forceinline__ void tc_relinq2() {
    asm volatile("tcgen05.relinquish_alloc_permit.cta_group::2.sync.aligned;");
}
__device__ __forceinline__ void tc_fence_after() {
    asm volatile("tcgen05.fence::after_thread_sync;" ::: "memory");
}
__device__ __forceinline__ void tc_fence_before() {
    asm volatile("tcgen05.fence::before_thread_sync;" ::: "memory");
}
__device__ __forceinline__ void tc_wait_ld() {
    asm volatile("tcgen05.wait::ld.sync.aligned;" ::: "memory");
}
__device__ __forceinline__ void tc_ld_x32(uint32_t* r, uint32_t addr) {
    asm volatile(
        "tcgen05.ld.sync.aligned.32x32b.x32.b32 "
        "{%0, %1, %2, %3, %4, %5, %6, %7, %8, %9, %10, %11, %12, %13, %14, %15, "
        " %16, %17, %18, %19, %20, %21, %22, %23, %24, %25, %26, %27, %28, %29, %30, %31}, [%32];"
        : "=r"(r[0]), "=r"(r[1]), "=r"(r[2]), "=r"(r[3]), "=r"(r[4]), "=r"(r[5]), "=r"(r[6]), "=r"(r[7]),
          "=r"(r[8]), "=r"(r[9]), "=r"(r[10]), "=r"(r[11]), "=r"(r[12]), "=r"(r[13]), "=r"(r[14]), "=r"(r[15]),
          "=r"(r[16]), "=r"(r[17]), "=r"(r[18]), "=r"(r[19]), "=r"(r[20]), "=r"(r[21]), "=r"(r[22]), "=r"(r[23]),
          "=r"(r[24]), "=r"(r[25]), "=r"(r[26]), "=r"(r[27]), "=r"(r[28]), "=r"(r[29]), "=r"(r[30]), "=r"(r[31])
        : "r"(addr));
}
// SW128 K-major descriptor base (LBO=1, SBO=64, version=1, layout SW128)
__device__ __forceinline__ uint64_t mk_desc(uint32_t addr) {
    const uint64_t DBASE = (2ULL << 61) | (1ULL << 46) | (64ULL << 32) | (1ULL << 16);
    return DBASE | (uint64_t)((addr >> 4) & 0x3FFF);
}
#endif  // HAS_TC

#if !HAS_TC
// ---------------- fallback-path helpers (mma.sync) ----------------
__device__ __forceinline__ void ldsm4(uint32_t* r, uint32_t addr) {
    asm volatile("ldmatrix.sync.aligned.m8n8.x4.shared.b16 {%0,%1,%2,%3}, [%4];\n"
                 : "=r"(r[0]), "=r"(r[1]), "=r"(r[2]), "=r"(r[3]) : "r"(addr));
}
__device__ __forceinline__ void ldsm4t(uint32_t* r, uint32_t addr) {
    asm volatile("ldmatrix.sync.aligned.m8n8.x4.trans.shared.b16 {%0,%1,%2,%3}, [%4];\n"
                 : "=r"(r[0]), "=r"(r[1]), "=r"(r[2]), "=r"(r[3]) : "r"(addr));
}
__device__ __forceinline__ void mma16816(float* c, const uint32_t* a, const uint32_t* b) {
    asm volatile(
        "mma.sync.aligned.m16n8k16.row.col.f32.bf16.bf16.f32 "
        "{%0,%1,%2,%3}, {%4,%5,%6,%7}, {%8,%9}, {%0,%1,%2,%3};\n"
        : "+f"(c[0]), "+f"(c[1]), "+f"(c[2]), "+f"(c[3])
        : "r"(a[0]), "r"(a[1]), "r"(a[2]), "r"(a[3]), "r"(b[0]), "r"(b[1]));
}
#endif  // !HAS_TC

// ---------------- kernel: gating (routing only) ----------------
__global__ __launch_bounds__(256) void gate_kernel(const float* __restrict__ x,
                                                   const float* __restrict__ gw) {
    const int tk = blockIdx.x;
    const int tid = threadIdx.x;
    const float* xr = x + (size_t)tk * DM;

    float p[NE];
#pragma unroll
    for (int e = 0; e < NE; ++e) p[e] = 0.f;
#pragma unroll
    for (int j = 0; j < 4; ++j) {
        int i = j * 256 + tid;
        float v = xr[i];
#pragma unroll
        for (int e = 0; e < NE; ++e) p[e] += v * gw[e * DM + i];
    }
#pragma unroll
    for (int e = 0; e < NE; ++e)
#pragma unroll
        for (int o = 16; o > 0; o >>= 1) p[e] += __shfl_xor_sync(0xffffffffu, p[e], o);

    __shared__ float sRed[8][NE];
    int lane = tid & 31, w = tid >> 5;
    if (lane == 0) {
#pragma unroll
        for (int e = 0; e < NE; ++e) sRed[w][e] = p[e];
    }
    __syncthreads();
    if (tid == 0) {
        float lg[NE];
#pragma unroll
        for (int e = 0; e < NE; ++e) {
            float s = 0.f;
#pragma unroll
            for (int ww = 0; ww < 8; ++ww) s += sRed[ww][e];
            lg[e] = s;
        }
        float m = lg[0];
#pragma unroll
        for (int e = 1; e < NE; ++e) m = fmaxf(m, lg[e]);
        float ex[NE], S = 0.f;
#pragma unroll
        for (int e = 0; e < NE; ++e) { ex[e] = expf(lg[e] - m); S += ex[e]; }
        int i0 = 0;
#pragma unroll
        for (int e = 1; e < NE; ++e) if (ex[e] > ex[i0]) i0 = e;
        int i1 = (i0 == 0) ? 1 : 0;
#pragma unroll
        for (int e = 0; e < NE; ++e) if (e != i0 && ex[e] > ex[i1]) i1 = e;
        float p0 = ex[i0] / S, p1 = ex[i1] / S;
        float den = p0 + p1 + 1e-9f;
        g_pair_e[2 * tk] = i0;     g_pair_w[2 * tk] = p0 / den;
        g_pair_e[2 * tk + 1] = i1; g_pair_w[2 * tk + 1] = p1 / den;
    }
}

// ---------------- kernel: counting sort (counts + scan + 256-row tiles + scatter) ----------------
__global__ __launch_bounds__(256) void sortscan_kernel() {
    __shared__ uint16_t loc[256][NE];
    __shared__ int s_cnt[NE];
    __shared__ int s_off[NE];
    const int t = threadIdx.x;
    const int p0 = t * 64;

    int lc[NE];
#pragma unroll
    for (int e = 0; e < NE; ++e) lc[e] = 0;
    for (int i = 0; i < 64; ++i) lc[g_pair_e[p0 + i]]++;
#pragma unroll
    for (int e = 0; e < NE; ++e) loc[t][e] = (uint16_t)lc[e];
    __syncthreads();

    if (t < NE) {
        int run = 0;
        for (int i = 0; i < 256; ++i) {
            int c = loc[i][t];
            loc[i][t] = (uint16_t)run;
            run += c;
        }
        s_cnt[t] = run;
        g_counts[t] = run;
    }
    __syncthreads();

    if (t == 0) {
        int off = 0, nt = 0;
        for (int e = 0; e < NE; ++e) {
            g_off[e] = off;
            s_off[e] = off;
            int c = s_cnt[e];
            int tiles = (c + 255) >> 8;
            for (int i = 0; i < tiles; ++i) {
                g_tile_e[nt] = e;
                g_tile_r0[nt] = off + i * 256;
                int v = c - i * 256;
                g_tile_valid[nt] = v > 256 ? 256 : v;
                ++nt;
            }
            off += c;
        }
        g_off[NE] = off;
        g_num_tiles = nt;
    }
    __syncthreads();

    int run[NE];
#pragma unroll
    for (int e = 0; e < NE; ++e) run[e] = s_off[e] + (int)loc[t][e];
    for (int i = 0; i < 64; ++i) {
        int p = p0 + i;
        int e = g_pair_e[p];
        int slot = run[e]++;
        g_pair_slot[p] = slot;
        g_rows_token[slot] = p >> 1;
    }
}

// ---------------- kernel: A-gather (slot-ordered hi/lo split of x) ----------------
__global__ __launch_bounds__(256) void gather_kernel(const float* __restrict__ x) {
    const int b = blockIdx.y * 64 + blockIdx.x;
    const int t = threadIdx.x;
    for (int rr = 0; rr < 16; ++rr) {
        const int slot = b * 16 + rr;
        const int tok = g_rows_token[slot];
        const float4 v = reinterpret_cast<const float4*>(x + (size_t)tok * DM)[t];
        __nv_bfloat16 h0 = __float2bfloat16_rn(v.x), h1 = __float2bfloat16_rn(v.y);
        __nv_bfloat16 h2 = __float2bfloat16_rn(v.z), h3 = __float2bfloat16_rn(v.w);
        __nv_bfloat16 l0 = __float2bfloat16_rn(v.x - __bfloat162float(h0));
        __nv_bfloat16 l1 = __float2bfloat16_rn(v.y - __bfloat162float(h1));
        __nv_bfloat16 l2 = __float2bfloat16_rn(v.z - __bfloat162float(h2));
        __nv_bfloat16 l3 = __float2bfloat16_rn(v.w - __bfloat162float(h3));
        reinterpret_cast<uint2*>(g_Ah + (size_t)slot * DM)[t] =
            make_uint2(pack_bf16(h0, h1), pack_bf16(h2, h3));
        reinterpret_cast<uint2*>(g_Al + (size_t)slot * DM)[t] =
            make_uint2(pack_bf16(l0, l1), pack_bf16(l2, l3));
    }
}

// ---------------- kernel: weight split + transpose (tc path only; side stream) ----------------
// in:  W[e][k][n] fp32 (n contiguous); out: Wh/Wl[e][n][k] bf16 (k contiguous)
__global__ __launch_bounds__(256) void wsplit_kernel(const float* __restrict__ W,
                                                     __nv_bfloat16* __restrict__ Wh,
                                                     __nv_bfloat16* __restrict__ Wl,
                                                     int K, int N) {
#if HAS_TC
    __shared__ float tile[64][65];
    const int e = blockIdx.z;
    const int K0 = blockIdx.x * 64, N0 = blockIdx.y * 64;
    const float* src = W + ((size_t)e * K + K0) * N + N0;
    const int t = threadIdx.x;
    const int r = t >> 4, c4 = (t & 15) * 4;
#pragma unroll
    for (int j = 0; j < 4; ++j) {
        int rr = r + j * 16;
        const float4 v = *reinterpret_cast<const float4*>(src + (size_t)rr * N + c4);
        tile[rr][c4 + 0] = v.x; tile[rr][c4 + 1] = v.y;
        tile[rr][c4 + 2] = v.z; tile[rr][c4 + 3] = v.w;
    }
    __syncthreads();
#pragma unroll
    for (int j = 0; j < 4; ++j) {
        int nn = r + j * 16;
        float v0 = tile[c4 + 0][nn], v1 = tile[c4 + 1][nn];
        float v2 = tile[c4 + 2][nn], v3 = tile[c4 + 3][nn];
        __nv_bfloat16 h0 = __float2bfloat16_rn(v0), h1 = __float2bfloat16_rn(v1);
        __nv_bfloat16 h2 = __float2bfloat16_rn(v2), h3 = __float2bfloat16_rn(v3);
        __nv_bfloat16 l0 = __float2bfloat16_rn(v0 - __bfloat162float(h0));
        __nv_bfloat16 l1 = __float2bfloat16_rn(v1 - __bfloat162float(h1));
        __nv_bfloat16 l2 = __float2bfloat16_rn(v2 - __bfloat162float(h2));
        __nv_bfloat16 l3 = __float2bfloat16_rn(v3 - __bfloat162float(h3));
        size_t out = ((size_t)e * N + N0 + nn) * K + K0 + c4;
        *reinterpret_cast<uint2*>(Wh + out) = make_uint2(pack_bf16(h0, h1), pack_bf16(h2, h3));
        *reinterpret_cast<uint2*>(Wl + out) = make_uint2(pack_bf16(l0, l1), pack_bf16(l2, l3));
    }
#endif
}

// ---------------- kernel: post-GEMM1 GELU + hi/lo split (streaming) ----------------
__global__ __launch_bounds__(256) void postgelu_kernel() {
    const size_t base = (size_t)blockIdx.x * DF;
    const int t = threadIdx.x;
#pragma unroll
    for (int j = 0; j < 4; ++j) {
        const int i = (j * 256 + t) * 4;
        const float4 v = *reinterpret_cast<const float4*>(g_Hf + base + i);
        float a0 = gelu_exact(v.x);
        float a1 = gelu_exact(v.y);
        float a2 = gelu_exact(v.z);
        float a3 = gelu_exact(v.w);
        __nv_bfloat16 h0 = __float2bfloat16_rn(a0), h1 = __float2bfloat16_rn(a1);
        __nv_bfloat16 h2 = __float2bfloat16_rn(a2), h3 = __float2bfloat16_rn(a3);
        __nv_bfloat16 l0 = __float2bfloat16_rn(a0 - __bfloat162float(h0));
        __nv_bfloat16 l1 = __float2bfloat16_rn(a1 - __bfloat162float(h1));
        __nv_bfloat16 l2 = __float2bfloat16_rn(a2 - __bfloat162float(h2));
        __nv_bfloat16 l3 = __float2bfloat16_rn(a3 - __bfloat162float(h3));
        *reinterpret_cast<uint2*>(g_Hh + base + i) = make_uint2(pack_bf16(h0, h1), pack_bf16(h2, h3));
        *reinterpret_cast<uint2*>(g_Hl + base + i) = make_uint2(pack_bf16(l0, l1), pack_bf16(l2, l3));
    }
}

// ---------------- tcgen05 cg2 GEMM: persistent clusters, double-buffered TMEM D ----------------
#define BUF_STRIDE 65536
#define OFF_AL 16384
#define OFF_BH 32768
#define OFF_BL 49152
#define OFF_TMEM 196608
#define OFF_MBAR 196624
#define SMEM_DYN 198656
#define STAGE_BYTES 65536u
// mbar layout: full[0..2]@+0,8,16 ; empty[0..2]@+24,32,40 ; done[0..1]@+48,56 ; free[0..1]@+64,72

#define GEMM_IDESC2 ((1u << 4) | (1u << 7) | (1u << 10) | ((256u / 8) << 17) | ((256u / 16) << 24))

template <bool FIRST>
__global__ __launch_bounds__(256)
void moe_gemm_tc(const __grid_constant__ CUtensorMap tmAh,
                 const __grid_constant__ CUtensorMap tmAl,
                 const __grid_constant__ CUtensorMap tmBh,
                 const __grid_constant__ CUtensorMap tmBl,
                 const float* __restrict__ bias) {
#if HAS_TC
    constexpr int KTOT = FIRST ? DM : DF;
    constexpr int NTOT = FIRST ? DF : DM;
    constexpr int NC = KTOT / 64;
    constexpr int NXT = NTOT / 256;

    const int cid = blockIdx.y;
    const int rank = blockIdx.x & 1;
    const int tot = g_num_tiles * NXT;

    extern __shared__ char dyn[];
    const uint32_t raw = smaddr(dyn);
    const uint32_t sbase = (raw + 1023u) & ~1023u;
    const int t = threadIdx.x;
    const int w = t >> 5, lane = t & 31;

    if (w == 0) {
        tc_alloc2(sbase + OFF_TMEM, 512);
        tc_relinq2();
    }
    if (t == 0) {
#pragma unroll
        for (int s = 0; s < 8; ++s) mbar_init(sbase + OFF_MBAR + s * 8, 1);
        mbar_init(sbase + OFF_MBAR + 64, 2);
        mbar_init(sbase + OFF_MBAR + 72, 2);
    }
    __syncthreads();
    cluster_sync_();

    uint32_t tmem;
    asm volatile("ld.shared.b32 %0, [%1];" : "=r"(tmem) : "r"(sbase + OFF_TMEM));

    const uint32_t mbF = sbase + OFF_MBAR;
    const uint32_t mbE = sbase + OFF_MBAR + 24;
    const uint32_t mbD = sbase + OFF_MBAR + 48;
    const uint32_t mbR = sbase + OFF_MBAR + 64;

    if (w == 0 && elect_one()) {
        // ================= producer: continuous TMA across tiles =================
        uint32_t pE = 0, pDp = 0;
        int s = 0;
#pragma unroll 1
        for (int tt = 0;; ++tt) {
            const int T = cid + tt * NCLUST;
            if (T >= tot) break;
            const int rt = T / NXT, nt = T % NXT;
            const int e = g_tile_e[rt];
            const int arow = g_tile_r0[rt] + rank * 128;
            const int bcol = nt * 256 + rank * 128;
#pragma unroll 1
            for (int i = 0; i < NC; ++i, ++s) {
                const int b = s % 3;
                if (s >= 3) {
                    const int sp_ = s - 3;
                    if ((sp_ % NC) == NC - 1) {
                        const int d = (sp_ / NC) & 1;
                        mbar_wait(mbD + d * 8, (pDp >> d) & 1u); pDp ^= 1u << d;
                    } else {
                        mbar_wait(mbE + b * 8, (pE >> b) & 1u); pE ^= 1u << b;
                    }
                }
                if (rank == 0) mbar_expect(mbF + b * 8, 2u * STAGE_BYTES);
                const uint32_t bb = sbase + (uint32_t)b * BUF_STRIDE;
                const int k0 = i * 64;
                tma2d_cg2(bb,          (const void*)&tmAh, k0, arow, mbF + b * 8);
                tma2d_cg2(bb + OFF_AL, (const void*)&tmAl, k0, arow, mbF + b * 8);
                tma3d_cg2(bb + OFF_BH, (const void*)&tmBh, k0, bcol, e, mbF + b * 8);
                tma3d_cg2(bb + OFF_BL, (const void*)&tmBl, k0, bcol, e, mbF + b * 8);
            }
        }
    } else if (w == 1 && rank == 0 && elect_one()) {
        // ================= consumer: MMA =================
        uint64_t dA[3], dAl_[3], dB[3], dBl_[3];
#pragma unroll
        for (int s2 = 0; s2 < 3; ++s2) {
            uint32_t b = sbase + s2 * BUF_STRIDE;
            dA[s2]   = mk_desc(b);
            dAl_[s2] = mk_desc(b + OFF_AL);
            dB[s2]   = mk_desc(b + OFF_BH);
            dBl_[s2] = mk_desc(b + OFF_BL);
        }
        uint32_t pF = 0, pFree = 0;
        int s = 0, ttn = 0;
#pragma unroll 1
        for (int tt = 0;; ++tt) {
            const int T = cid + tt * NCLUST;
            if (T >= tot) break;
            ttn = tt + 1;
            const int d = tt & 1;
            if (tt >= 2) {
                mbar_wait(mbR + d * 8, (pFree >> d) & 1u); pFree ^= 1u << d;
                tc_fence_after();
            }
            const uint32_t dtm = tmem + d * 256;
#pragma unroll 1
            for (int i = 0; i < NC; ++i, ++s) {
                const int b = s % 3;
                mbar_wait(mbF + b * 8, (pF >> b) & 1u); pF ^= 1u << b;
#pragma unroll
                for (int ks = 0; ks < 4; ++ks) {
                    const uint64_t oa = (uint64_t)(ks * 2);
                    const uint32_t en0 = (i == 0 && ks == 0) ? 0u : 1u;
                    tc_mma_f16_ss2(dtm, dA[b] + oa,   dB[b] + oa,   GEMM_IDESC2, en0);
                    tc_mma_f16_ss2(dtm, dA[b] + oa,   dBl_[b] + oa, GEMM_IDESC2, 1u);
                    tc_mma_f16_ss2(dtm, dAl_[b] + oa, dB[b] + oa,   GEMM_IDESC2, 1u);
                }
                tc_commit_mc2((i == NC - 1) ? (mbD + d * 8) : (mbE + b * 8));
            }
        }
#pragma unroll 1
        for (int k = (ttn >= 2 ? ttn - 2 : 0); k < ttn; ++k) {
            const int d = k & 1;
            mbar_wait(mbR + d * 8, (pFree >> d) & 1u); pFree ^= 1u << d;
        }
    } else if (w >= 2) {
        // ================= epilogue: warps 2..7 (raw fp32 + bias only) =================
        const int sp_ = w & 3;
        const int rloc = sp_ * 32 + lane;
        int cstart, cnum;
        if (w == 4 || w == 5)      { cstart = 0;   cnum = 8; }
        else if (w == 2 || w == 3) { cstart = 0;   cnum = 4; }
        else                       { cstart = 128; cnum = 4; }

        uint32_t pDe = 0;
#pragma unroll 1
        for (int tt = 0;; ++tt) {
            const int T = cid + tt * NCLUST;
            if (T >= tot) break;
            const int d = tt & 1;
            mbar_wait(mbD + d * 8, (pDe >> d) & 1u); pDe ^= 1u << d;
            tc_fence_after();

            const int rt = T / NXT, nt = T % NXT;
            const int e = g_tile_e[rt];
            const int row0 = g_tile_r0[rt];
            const int n0 = nt * 256;
            int vr = g_tile_valid[rt] - rank * 128;
            vr = vr < 0 ? 0 : (vr > 128 ? 128 : vr);
            const bool valid = rloc < vr;
            const int rowg = row0 + rank * 128 + rloc;
            const uint32_t dtm = tmem + d * 256;
            const float* bb = bias + (size_t)e * NTOT + n0;
            float* oF = (FIRST ? g_Hf + (size_t)rowg * DF : g_Y + (size_t)rowg * DM) + n0;

#pragma unroll 1
            for (int j = 0; j < cnum; ++j) {
                const int col = cstart + j * 32;
                uint32_t dr[32];
                tc_ld_x32(dr, dtm + col);
                tc_wait_ld();
                if (valid) {
#pragma unroll
                    for (int c = 0; c < 32; c += 4) {
                        float4 o;
                        o.x = __uint_as_float(dr[c + 0]) + bb[col + c + 0];
                        o.y = __uint_as_float(dr[c + 1]) + bb[col + c + 1];
                        o.z = __uint_as_float(dr[c + 2]) + bb[col + c + 2];
                        o.w = __uint_as_float(dr[c + 3]) + bb[col + c + 3];
                        *reinterpret_cast<float4*>(oF + col + c) = o;
                    }
                }
            }
            tc_fence_before();
            asm volatile("bar.sync 1, 192;" ::: "memory");
            if (w == 2 && elect_one()) mbar_arrive_leader(mbR + d * 8);
        }
    }

    __syncthreads();
    if (t == 0) {
#pragma unroll
        for (int s = 0; s < 10; ++s) mbar_inval(sbase + OFF_MBAR + s * 8);
    }
    __syncthreads();
    cluster_sync_();
    if (w == 0) tc_dealloc2(tmem, 512);
    cluster_sync_();
#endif  // HAS_TC
}

// ---------------- fallback GEMM (mma.sync; 256-tiles split in half) ----------------
template <bool FIRST>
__global__ __launch_bounds__(256) void moe_gemm_fb(const float* __restrict__ W,
                                                   const float* __restrict__ bias) {
#if !HAS_TC
    constexpr int KTOT = FIRST ? DM : DF;
    constexpr int LDW  = FIRST ? DF : DM;
    const int tileIdx = blockIdx.y >> 1;
    if (tileIdx >= g_num_tiles) return;
    const int half = blockIdx.y & 1;
    const int e = g_tile_e[tileIdx];
    const int row0 = g_tile_r0[tileIdx] + half * 128;
    int vrows = g_tile_valid[tileIdx] - half * 128;
    vrows = vrows < 0 ? 0 : (vrows > 128 ? 128 : vrows);
    if (vrows == 0) return;
    const int n0 = blockIdx.x * 128;
    const float* Wn = W + (size_t)e * KTOT * LDW + n0;
    const float* bn = bias + (size_t)e * LDW + n0;

    __shared__ __align__(16) __nv_bfloat16 sAh[128 * 40];
    __shared__ __align__(16) __nv_bfloat16 sAl[128 * 40];
    __shared__ __align__(16) __nv_bfloat16 sBh[32 * 136];
    __shared__ __align__(16) __nv_bfloat16 sBl[32 * 136];

    const int t = threadIdx.x;
    float c[4][4][4];
#pragma unroll
    for (int a = 0; a < 4; ++a)
#pragma unroll
        for (int b = 0; b < 4; ++b)
#pragma unroll
            for (int q = 0; q < 4; ++q) c[a][b][q] = 0.f;

    const int lane = t & 31, warp = t >> 5;
    const int wm = warp >> 2, wn = warp & 3;
    const int m0 = wm * 64;
    const int sub = t & 15, rgrp = t >> 4;

    for (int k0 = 0; k0 < KTOT; k0 += 32) {
        __syncthreads();
#pragma unroll
        for (int rr = 0; rr < 8; ++rr) {
            int r = rr * 16 + rgrp;
            int rg = row0 + r; if (rg > PAIRS - 1) rg = PAIRS - 1;
            const uint32_t* ph = reinterpret_cast<const uint32_t*>(
                (FIRST ? g_Ah : g_Hh) + (size_t)rg * KTOT + k0);
            const uint32_t* pl = reinterpret_cast<const uint32_t*>(
                (FIRST ? g_Al : g_Hl) + (size_t)rg * KTOT + k0);
            *reinterpret_cast<uint32_t*>(&sAh[r * 40 + sub * 2]) = ph[sub];
            *reinterpret_cast<uint32_t*>(&sAl[r * 40 + sub * 2]) = pl[sub];
        }
#pragma unroll
        for (int i = 0; i < 4; ++i) {
            int lin = (i * 256 + t) * 4;
            int kr = lin >> 7;
            int nc = lin & 127;
            const float4 v = *reinterpret_cast<const float4*>(Wn + (size_t)(k0 + kr) * LDW + nc);
            __nv_bfloat16 h0 = __float2bfloat16_rn(v.x);
            __nv_bfloat16 h1 = __float2bfloat16_rn(v.y);
            __nv_bfloat16 h2 = __float2bfloat16_rn(v.z);
            __nv_bfloat16 h3 = __float2bfloat16_rn(v.w);
            __nv_bfloat16 l0 = __float2bfloat16_rn(v.x - __bfloat162float(h0));
            __nv_bfloat16 l1 = __float2bfloat16_rn(v.y - __bfloat162float(h1));
            __nv_bfloat16 l2 = __float2bfloat16_rn(v.z - __bfloat162float(h2));
            __nv_bfloat16 l3 = __float2bfloat16_rn(v.w - __bfloat162float(h3));
            *reinterpret_cast<uint2*>(&sBh[kr * 136 + nc]) = make_uint2(pack_bf16(h0, h1), pack_bf16(h2, h3));
            *reinterpret_cast<uint2*>(&sBl[kr * 136 + nc]) = make_uint2(pack_bf16(l0, l1), pack_bf16(l2, l3));
        }
        __syncthreads();

#pragma unroll
        for (int ks = 0; ks < 2; ++ks) {
            uint32_t ah[4][4], al[4][4], bh[4][2], bl[4][2];
            {
                int ar = lane & 15;
                int acol = ks * 16 + (lane >> 4) * 8;
#pragma unroll
                for (int fm = 0; fm < 4; ++fm) {
                    ldsm4(ah[fm], smaddr(&sAh[(m0 + fm * 16 + ar) * 40 + acol]));
                    ldsm4(al[fm], smaddr(&sAl[(m0 + fm * 16 + ar) * 40 + acol]));
                }
                int brow = ks * 16 + (lane & 15);
                int bcol = wn * 32 + (lane >> 4) * 8;
#pragma unroll
                for (int hb = 0; hb < 2; ++hb) {
                    uint32_t r[4];
                    ldsm4t(r, smaddr(&sBh[brow * 136 + bcol + hb * 16]));
                    bh[2 * hb][0] = r[0]; bh[2 * hb][1] = r[1];
                    bh[2 * hb + 1][0] = r[2]; bh[2 * hb + 1][1] = r[3];
                    ldsm4t(r, smaddr(&sBl[brow * 136 + bcol + hb * 16]));
                    bl[2 * hb][0] = r[0]; bl[2 * hb][1] = r[1];
                    bl[2 * hb + 1][0] = r[2]; bl[2 * hb + 1][1] = r[3];
                }
            }
#pragma unroll
            for (int fm = 0; fm < 4; ++fm)
#pragma unroll
                for (int fn = 0; fn < 4; ++fn) {
                    mma16816(c[fm][fn], ah[fm], bh[fn]);
                    mma16816(c[fm][fn], ah[fm], bl[fn]);
                    mma16816(c[fm][fn], al[fm], bh[fn]);
                }
        }
    }

    const int lgrp = lane >> 2, lq = lane & 3;
#pragma unroll
    for (int fm = 0; fm < 4; ++fm) {
        int rl = m0 + fm * 16 + lgrp;
#pragma unroll
        for (int fn = 0; fn < 4; ++fn) {
            int nc = wn * 32 + fn * 8 + lq * 2;
            float bv0 = bn[nc], bv1 = bn[nc + 1];
            float* cc = c[fm][fn];
#pragma unroll
            for (int h = 0; h < 2; ++h) {
                int rloc = rl + h * 8;
                if (rloc < vrows) {
                    int row = row0 + rloc;
                    float v0 = cc[h * 2 + 0] + bv0;
                    float v1 = cc[h * 2 + 1] + bv1;
                    if (FIRST) {
                        *reinterpret_cast<float2*>(&g_Hf[(size_t)row * DF + n0 + nc]) = make_float2(v0, v1);
                    } else {
                        *reinterpret_cast<float2*>(&g_Y[(size_t)row * DM + n0 + nc]) = make_float2(v0, v1);
                    }
                }
            }
        }
    }
#endif  // !HAS_TC
}

// ---------------- kernel: weighted combine ----------------
__global__ __launch_bounds__(256) void combine_kernel(float* __restrict__ out) {
    const int tk = blockIdx.x;
    const int d = threadIdx.x * 4;
    int s0 = g_pair_slot[2 * tk], s1 = g_pair_slot[2 * tk + 1];
    float w0 = g_pair_w[2 * tk], w1 = g_pair_w[2 * tk + 1];
    const float4 a = *reinterpret_cast<const float4*>(&g_Y[(size_t)s0 * DM + d]);
    const float4 b = *reinterpret_cast<const float4*>(&g_Y[(size_t)s1 * DM + d]);
    float4 o;
    o.x = w0 * a.x + w1 * b.x;
    o.y = w0 * a.y + w1 * b.y;
    o.z = w0 * a.z + w1 * b.z;
    o.w = w0 * a.w + w1 * b.w;
    *reinterpret_cast<float4*>(&out[(size_t)tk * DM + d]) = o;
}

// ---------------- host: tensor map construction ----------------
typedef CUresult (*TmEncodeFn)(CUtensorMap*, CUtensorMapDataType, cuuint32_t, void*,
                               const cuuint64_t*, const cuuint64_t*, const cuuint32_t*,
                               const cuuint32_t*, CUtensorMapInterleave, CUtensorMapSwizzle,
                               CUtensorMapL2promotion, CUtensorMapFloatOOBfill);

static void tm2d(TmEncodeFn enc, CUtensorMap* tm, void* base, unsigned long long K,
                 unsigned long long R) {
    cuuint64_t dims[2] = {K, R};
    cuuint64_t st[1] = {K * 2};
    cuuint32_t box[2] = {64, 128};
    cuuint32_t es[2] = {1, 1};
    enc(tm, CU_TENSOR_MAP_DATA_TYPE_BFLOAT16, 2, base, dims, st, box, es,
        CU_TENSOR_MAP_INTERLEAVE_NONE, CU_TENSOR_MAP_SWIZZLE_128B,
        CU_TENSOR_MAP_L2_PROMOTION_L2_128B, CU_TENSOR_MAP_FLOAT_OOB_FILL_NONE);
}
static void tm3d(TmEncodeFn enc, CUtensorMap* tm, void* base, unsigned long long K,
                 unsigned long long N) {
    cuuint64_t dims[3] = {K, N, NE};
    cuuint64_t st[2] = {K * 2, N * K * 2};
    cuuint32_t box[3] = {64, 128, 1};
    cuuint32_t es[3] = {1, 1, 1};
    enc(tm, CU_TENSOR_MAP_DATA_TYPE_BFLOAT16, 3, base, dims, st, box, es,
        CU_TENSOR_MAP_INTERLEAVE_NONE, CU_TENSOR_MAP_SWIZZLE_128B,
        CU_TENSOR_MAP_L2_PROMOTION_L2_128B, CU_TENSOR_MAP_FLOAT_OOB_FILL_NONE);
}

// ---------------- launch ----------------
extern "C" void kernel_launch(void* const* d_in, const int* in_sizes, int n_in,
                              void* d_out, int out_size) {
    const float* x  = (const float*)d_in[0];
    const float* gw = (const float*)d_in[1];
    const float* w1 = (const float*)d_in[2];
    const float* b1 = (const float*)d_in[3];
    const float* w2 = (const float*)d_in[4];
    const float* b2 = (const float*)d_in[5];
    float* out = (float*)d_out;

    cudaFuncSetAttribute(moe_gemm_tc<true>,  cudaFuncAttributeMaxDynamicSharedMemorySize, SMEM_DYN);
    cudaFuncSetAttribute(moe_gemm_tc<false>, cudaFuncAttributeMaxDynamicSharedMemorySize, SMEM_DYN);

    void *pAh, *pAl, *pHh, *pHl, *pW1h, *pW1l, *pW2h, *pW2l;
    cudaGetSymbolAddress(&pAh, g_Ah);
    cudaGetSymbolAddress(&pAl, g_Al);
    cudaGetSymbolAddress(&pHh, g_Hh);
    cudaGetSymbolAddress(&pHl, g_Hl);
    cudaGetSymbolAddress(&pW1h, g_w1h);
    cudaGetSymbolAddress(&pW1l, g_w1l);
    cudaGetSymbolAddress(&pW2h, g_w2h);
    cudaGetSymbolAddress(&pW2l, g_w2l);

    void* sym = nullptr;
    cudaDriverEntryPointQueryResult qr;
    cudaGetDriverEntryPoint("cuTensorMapEncodeTiled", &sym, cudaEnableDefault, &qr);
    TmEncodeFn enc = (TmEncodeFn)sym;

    CUtensorMap tAh, tAl, tB1h, tB1l, tHh, tHl, tB2h, tB2l;
    if (enc) {
        tm2d(enc, &tAh, pAh, DM, PAIRS);
        tm2d(enc, &tAl, pAl, DM, PAIRS);
        tm3d(enc, &tB1h, pW1h, DM, DF);
        tm3d(enc, &tB1l, pW1l, DM, DF);
        tm2d(enc, &tHh, pHh, DF, PAIRS);
        tm2d(enc, &tHl, pHl, DF, PAIRS);
        tm3d(enc, &tB2h, pW2h, DF, DM);
        tm3d(enc, &tB2l, pW2l, DF, DM);
    }

    // side stream + events (lazily created once; control-flow resources only)
    static cudaStream_t sSide = nullptr;
    static cudaEvent_t evFork = nullptr, evW1 = nullptr, evW2 = nullptr;
    if (!sSide) {
        cudaStreamCreateWithFlags(&sSide, cudaStreamNonBlocking);
        cudaEventCreateWithFlags(&evFork, cudaEventDisableTiming);
        cudaEventCreateWithFlags(&evW1, cudaEventDisableTiming);
        cudaEventCreateWithFlags(&evW2, cudaEventDisableTiming);
    }

    // fork: weight split runs on side stream, independent of routing
    cudaEventRecord(evFork, 0);
    cudaStreamWaitEvent(sSide, evFork, 0);
    wsplit_kernel<<<dim3(DM / 64, DF / 64, NE), 256, 0, sSide>>>(w1, (__nv_bfloat16*)pW1h, (__nv_bfloat16*)pW1l, DM, DF);
    cudaEventRecord(evW1, sSide);
    wsplit_kernel<<<dim3(DF / 64, DM / 64, NE), 256, 0, sSide>>>(w2, (__nv_bfloat16*)pW2h, (__nv_bfloat16*)pW2l, DF, DM);
    cudaEventRecord(evW2, sSide);

    // main stream: routing + gather
    gate_kernel<<<T_TOKENS, 256>>>(x, gw);
    sortscan_kernel<<<1, 256>>>();
    gather_kernel<<<dim3(64, 16), 256>>>(x);

    cudaLaunchAttribute cat[1];
    cat[0].id = cudaLaunchAttributeClusterDimension;
    cat[0].val.clusterDim.x = 2;
    cat[0].val.clusterDim.y = 1;
    cat[0].val.clusterDim.z = 1;

    cudaStreamWaitEvent(0, evW1, 0);  // join w1 split
    {
        cudaLaunchConfig_t cfg = {};
        cfg.gridDim = dim3(2, NCLUST, 1);
        cfg.blockDim = dim3(256, 1, 1);
        cfg.dynamicSmemBytes = SMEM_DYN;
        cfg.stream = 0;
        cfg.attrs = cat;
        cfg.numAttrs = 1;
        cudaLaunchKernelEx(&cfg, moe_gemm_tc<true>, tAh, tAl, tB1h, tB1l, b1);
    }
    moe_gemm_fb<true><<<dim3(DF / 128, MAXT2 * 2), 256>>>(w1, b1);   // no-op on tc build
    postgelu_kernel<<<PAIRS, 256>>>();
    cudaStreamWaitEvent(0, evW2, 0);  // join w2 split
    {
        cudaLaunchConfig_t cfg = {};
        cfg.gridDim = dim3(2, NCLUST, 1);
        cfg.blockDim = dim3(256, 1, 1);
        cfg.dynamicSmemBytes = SMEM_DYN;
        cfg.stream = 0;
        cfg.attrs = cat;
        cfg.numAttrs = 1;
        cudaLaunchKernelEx(&cfg, moe_gemm_tc<false>, tHh, tHl, tB2h, tB2l, b2);
    }
    moe_gemm_fb<false><<<dim3(DM / 128, MAXT2 * 2), 256>>>(w2, b2);  // no-op on tc build
    combine_kernel<<<T_TOKENS, 256>>>(out);
}

// round 13
// speedup vs baseline: 1.6394x; 1.0362x over previous
#include <cuda_runtime.h>
#include <cuda.h>
#include <cuda_bf16.h>
#include <stdint.h>

#define T_TOKENS 8192
#define DM 1024
#define DF 4096
#define NE 8
#define PAIRS 16384
#define MAXTILES 144
#define MAXT2 72
#define NCLUST 74

// tcgen05 availability: only in the arch-SPECIFIC device pass (sm_103a / sm_100a).
#if defined(__CUDA_ARCH__) && (defined(__CUDA_ARCH_FEAT_SM103_ALL) || defined(__CUDA_ARCH_FEAT_SM100_ALL) || defined(__CUDA_ARCH_SPECIFIC__))
#define HAS_TC 1
#else
#define HAS_TC 0
#endif

// ---------------- scratch (device globals; no allocations) ----------------
__device__ __align__(128) __nv_bfloat16 g_Ah[(size_t)PAIRS * DM];
__device__ __align__(128) __nv_bfloat16 g_Al[(size_t)PAIRS * DM];
__device__ __align__(128) float         g_Hf[(size_t)PAIRS * DF];   // raw GEMM1 out (bias added)
__device__ __align__(128) __nv_bfloat16 g_Hh[(size_t)PAIRS * DF];
__device__ __align__(128) __nv_bfloat16 g_Hl[(size_t)PAIRS * DF];
__device__ __align__(128) float         g_Y[(size_t)PAIRS * DM];

__device__ __align__(128) __nv_bfloat16 g_w1h[(size_t)NE * DM * DF];
__device__ __align__(128) __nv_bfloat16 g_w1l[(size_t)NE * DM * DF];
__device__ __align__(128) __nv_bfloat16 g_w2h[(size_t)NE * DF * DM];
__device__ __align__(128) __nv_bfloat16 g_w2l[(size_t)NE * DF * DM];

__device__ int   g_pair_e[PAIRS];
__device__ float g_pair_w[PAIRS];
__device__ int   g_pair_slot[PAIRS];
__device__ int   g_rows_token[PAIRS];

__device__ int g_counts[NE];
__device__ int g_off[NE + 1];
__device__ int g_tile_e[MAXTILES];
__device__ int g_tile_r0[MAXTILES];
__device__ int g_tile_valid[MAXTILES];
__device__ int g_num_tiles;

// ---------------- shared helpers ----------------
__device__ __forceinline__ uint32_t smaddr(const void* p) {
    return (uint32_t)__cvta_generic_to_shared(p);
}
__device__ __forceinline__ uint32_t pack_bf16(__nv_bfloat16 a, __nv_bfloat16 b) {
    return (uint32_t)__bfloat16_as_ushort(a) | ((uint32_t)__bfloat16_as_ushort(b) << 16);
}
__device__ __forceinline__ float gelu_exact(float v) {
    return 0.5f * v * (1.0f + erff(v * 0.70710678118654752f));
}

#if HAS_TC
// ---------------- tcgen05 / cg2 helpers ----------------
__device__ __forceinline__ uint32_t elect_one() {
    uint32_t pred;
    asm volatile("{\n\t.reg .pred p;\n\telect.sync _|p, 0xFFFFFFFF;\n\tselp.b32 %0, 1, 0, p;\n\t}"
                 : "=r"(pred));
    return pred;
}
__device__ __forceinline__ void cluster_sync_() {
    asm volatile("barrier.cluster.arrive.aligned;" ::: "memory");
    asm volatile("barrier.cluster.wait.aligned;" ::: "memory");
}
__device__ __forceinline__ void mbar_init(uint32_t addr, uint32_t cnt) {
    asm volatile("mbarrier.init.shared.b64 [%0], %1;" :: "r"(addr), "r"(cnt) : "memory");
}
__device__ __forceinline__ void mbar_inval(uint32_t addr) {
    asm volatile("mbarrier.inval.shared.b64 [%0];" :: "r"(addr) : "memory");
}
__device__ __forceinline__ void mbar_expect(uint32_t addr, uint32_t bytes) {
    asm volatile("mbarrier.arrive.expect_tx.shared.b64 _, [%0], %1;"
                 :: "r"(addr), "r"(bytes) : "memory");
}
__device__ __forceinline__ void mbar_wait(uint32_t addr, uint32_t parity) {
    asm volatile(
        "{\n\t.reg .pred P1;\n"
        "WAIT_%=:\n\t"
        "mbarrier.try_wait.parity.acquire.cta.shared::cta.b64 P1, [%0], %1, 0x989680;\n\t"
        "@P1 bra.uni DONE_%=;\n\t"
        "bra.uni WAIT_%=;\n"
        "DONE_%=:\n\t}"
        :: "r"(addr), "r"(parity) : "memory");
}
// arrive on rank0's mbarrier (cg2 leader: clear bit 24)
__device__ __forceinline__ void mbar_arrive_leader(uint32_t addr) {
    asm volatile(
        "{\n\t.reg .b32 la;\n\t"
        "and.b32 la, %0, 0xFEFFFFFF;\n\t"
        "mbarrier.arrive.shared::cluster.b64 _, [la];\n\t}"
        :: "r"(addr) : "memory");
}
__device__ __forceinline__ void tma2d_cg2(uint32_t dst, const void* tm, int x, int y, uint32_t mbar) {
    asm volatile(
        "{\n\t.reg .b32 lb;\n\t"
        "and.b32 lb, %4, 0xFEFFFFFF;\n\t"
        "cp.async.bulk.tensor.2d.cta_group::2.shared::cluster.global.tile.mbarrier::complete_tx::bytes "
        "[%0], [%1, {%2, %3}], [lb];\n\t}"
        :: "r"(dst), "l"(tm), "r"(x), "r"(y), "r"(mbar) : "memory");
}
__device__ __forceinline__ void tma3d_cg2(uint32_t dst, const void* tm, int x, int y, int z, uint32_t mbar) {
    asm volatile(
        "{\n\t.reg .b32 lb;\n\t"
        "and.b32 lb, %5, 0xFEFFFFFF;\n\t"
        "cp.async.bulk.tensor.3d.cta_group::2.shared::cluster.global.tile.mbarrier::complete_tx::bytes "
        "[%0], [%1, {%2, %3, %4}], [lb];\n\t}"
        :: "r"(dst), "l"(tm), "r"(x), "r"(y), "r"(z), "r"(mbar) : "memory");
}
__device__ __forceinline__ void tc_mma_f16_ss2(uint32_t d, uint64_t a, uint64_t b,
                                               uint32_t idesc, uint32_t en) {
    asm volatile(
        "{\n\t.reg .pred p;\n\tsetp.ne.u32 p, %5, 0;\n\t"
        "tcgen05.mma.cta_group::2.kind::f16 [%0], %1, %2, %3, "
        "{%4, %4, %4, %4, %4, %4, %4, %4}, p;\n\t}"
        :: "r"(d), "l"(a), "l"(b), "r"(idesc), "r"(0u), "r"(en) : "memory");
}
__device__ __forceinline__ void tc_commit_mc2(uint32_t mbar) {
    asm volatile(
        "tcgen05.commit.cta_group::2.mbarrier::arrive::one.shared::cluster.multicast::cluster.b64 [%0], %1;"
        :: "r"(mbar), "h"((uint16_t)0x3) : "memory");
}
__device__ __forceinline__ void tc_alloc2(uint32_t smem_slot, uint32_t ncols) {
    asm volatile("tcgen05.alloc.cta_group::2.sync.aligned.shared::cta.b32 [%0], %1;"
                 :: "r"(smem_slot), "r"(ncols) : "memory");
}
__device__ __forceinline__ void tc_dealloc2(uint32_t tmem, uint32_t ncols) {
    asm volatile("tcgen05.dealloc.cta_group::2.sync.aligned.b32 %0, %1;" :: "r"(tmem), "r"(ncols));
}
__device__ __forceinline__ void tc_relinq2() {
    asm volatile("tcgen05.relinquish_alloc_permit.cta_group::2.sync.aligned;");
}
__device__ __forceinline__ void tc_fence_after() {
    asm volatile("tcgen05.fence::after_thread_sync;" ::: "memory");
}
__device__ __forceinline__ void tc_fence_before() {
    asm volatile("tcgen05.fence::before_thread_sync;" ::: "memory");
}
__device__ __forceinline__ void tc_wait_ld() {
    asm volatile("tcgen05.wait::ld.sync.aligned;" ::: "memory");
}
__device__ __forceinline__ void tc_ld_x32(uint32_t* r, uint32_t addr) {
    asm volatile(
        "tcgen05.ld.sync.aligned.32x32b.x32.b32 "
        "{%0, %1, %2, %3, %4, %5, %6, %7, %8, %9, %10, %11, %12, %13, %14, %15, "
        " %16, %17, %18, %19, %20, %21, %22, %23, %24, %25, %26, %27, %28, %29, %30, %31}, [%32];"
        : "=r"(r[0]), "=r"(r[1]), "=r"(r[2]), "=r"(r[3]), "=r"(r[4]), "=r"(r[5]), "=r"(r[6]), "=r"(r[7]),
          "=r"(r[8]), "=r"(r[9]), "=r"(r[10]), "=r"(r[11]), "=r"(r[12]), "=r"(r[13]), "=r"(r[14]), "=r"(r[15]),
          "=r"(r[16]), "=r"(r[17]), "=r"(r[18]), "=r"(r[19]), "=r"(r[20]), "=r"(r[21]), "=r"(r[22]), "=r"(r[23]),
          "=r"(r[24]), "=r"(r[25]), "=r"(r[26]), "=r"(r[27]), "=r"(r[28]), "=r"(r[29]), "=r"(r[30]), "=r"(r[31])
        : "r"(addr));
}
// SW128 K-major descriptor base (LBO=1, SBO=64, version=1, layout SW128)
__device__ __forceinline__ uint64_t mk_desc(uint32_t addr) {
    const uint64_t DBASE = (2ULL << 61) | (1ULL << 46) | (64ULL << 32) | (1ULL << 16);
    return DBASE | (uint64_t)((addr >> 4) & 0x3FFF);
}
#endif  // HAS_TC

#if !HAS_TC
// ---------------- fallback-path helpers (mma.sync) ----------------
__device__ __forceinline__ void ldsm4(uint32_t* r, uint32_t addr) {
    asm volatile("ldmatrix.sync.aligned.m8n8.x4.shared.b16 {%0,%1,%2,%3}, [%4];\n"
                 : "=r"(r[0]), "=r"(r[1]), "=r"(r[2]), "=r"(r[3]) : "r"(addr));
}
__device__ __forceinline__ void ldsm4t(uint32_t* r, uint32_t addr) {
    asm volatile("ldmatrix.sync.aligned.m8n8.x4.trans.shared.b16 {%0,%1,%2,%3}, [%4];\n"
                 : "=r"(r[0]), "=r"(r[1]), "=r"(r[2]), "=r"(r[3]) : "r"(addr));
}
__device__ __forceinline__ void mma16816(float* c, const uint32_t* a, const uint32_t* b) {
    asm volatile(
        "mma.sync.aligned.m16n8k16.row.col.f32.bf16.bf16.f32 "
        "{%0,%1,%2,%3}, {%4,%5,%6,%7}, {%8,%9}, {%0,%1,%2,%3};\n"
        : "+f"(c[0]), "+f"(c[1]), "+f"(c[2]), "+f"(c[3])
        : "r"(a[0]), "r"(a[1]), "r"(a[2]), "r"(a[3]), "r"(b[0]), "r"(b[1]));
}
#endif  // !HAS_TC

// ---------------- kernel: gating (warp per token) ----------------
__global__ __launch_bounds__(256) void gate_kernel(const float* __restrict__ x,
                                                   const float* __restrict__ gw) {
    const int wid = threadIdx.x >> 5, lane = threadIdx.x & 31;
    const int tk = blockIdx.x * 8 + wid;
    const float* xr = x + (size_t)tk * DM;

    float p[NE];
#pragma unroll
    for (int e = 0; e < NE; ++e) p[e] = 0.f;
#pragma unroll 8
    for (int j = 0; j < 32; ++j) {
        const int i = j * 32 + lane;
        const float v = xr[i];
#pragma unroll
        for (int e = 0; e < NE; ++e) p[e] += v * gw[e * DM + i];
    }
#pragma unroll
    for (int e = 0; e < NE; ++e)
#pragma unroll
        for (int o = 16; o > 0; o >>= 1) p[e] += __shfl_xor_sync(0xffffffffu, p[e], o);

    if (lane == 0) {
        float m = p[0];
#pragma unroll
        for (int e = 1; e < NE; ++e) m = fmaxf(m, p[e]);
        float ex[NE], S = 0.f;
#pragma unroll
        for (int e = 0; e < NE; ++e) { ex[e] = expf(p[e] - m); S += ex[e]; }
        int i0 = 0;
#pragma unroll
        for (int e = 1; e < NE; ++e) if (ex[e] > ex[i0]) i0 = e;
        int i1 = (i0 == 0) ? 1 : 0;
#pragma unroll
        for (int e = 0; e < NE; ++e) if (e != i0 && ex[e] > ex[i1]) i1 = e;
        float p0 = ex[i0] / S, p1 = ex[i1] / S;
        float den = p0 + p1 + 1e-9f;
        g_pair_e[2 * tk] = i0;     g_pair_w[2 * tk] = p0 / den;
        g_pair_e[2 * tk + 1] = i1; g_pair_w[2 * tk + 1] = p1 / den;
    }
}

// ---------------- kernel: parallel counting sort (1024 threads) ----------------
// Deterministic slot assignment (not stable order, but a fixed bijection of the routing).
__global__ __launch_bounds__(1024) void sortscan_kernel() {
    __shared__ int cnt[1024][NE];   // 32 KB
    __shared__ int s_off[NE];
    const int t = threadIdx.x;

    int lc[NE];
#pragma unroll
    for (int e = 0; e < NE; ++e) lc[e] = 0;
    int le[16];
#pragma unroll
    for (int i = 0; i < 16; ++i) {
        const int e = g_pair_e[t + i * 1024];
        le[i] = e;
        lc[e]++;
    }
#pragma unroll
    for (int e = 0; e < NE; ++e) cnt[t][e] = lc[e];
    __syncthreads();

    // Hillis-Steele inclusive scan over threads (vector of 8 counts)
#pragma unroll 1
    for (int ofs = 1; ofs < 1024; ofs <<= 1) {
        int v[NE];
        const bool act = t >= ofs;
        if (act) {
#pragma unroll
            for (int e = 0; e < NE; ++e) v[e] = cnt[t - ofs][e];
        }
        __syncthreads();
        if (act) {
#pragma unroll
            for (int e = 0; e < NE; ++e) cnt[t][e] += v[e];
        }
        __syncthreads();
    }

    if (t == 0) {
        int off = 0, nt = 0;
#pragma unroll
        for (int e = 0; e < NE; ++e) {
            const int c = cnt[1023][e];
            g_counts[e] = c;
            g_off[e] = off;
            s_off[e] = off;
            const int tiles = (c + 255) >> 8;
            for (int i = 0; i < tiles; ++i) {
                g_tile_e[nt] = e;
                g_tile_r0[nt] = off + i * 256;
                int v = c - i * 256;
                g_tile_valid[nt] = v > 256 ? 256 : v;
                ++nt;
            }
            off += c;
        }
        g_off[NE] = off;
        g_num_tiles = nt;
    }
    __syncthreads();

    int run[NE];
#pragma unroll
    for (int e = 0; e < NE; ++e) run[e] = s_off[e] + cnt[t][e] - lc[e];
#pragma unroll
    for (int i = 0; i < 16; ++i) {
        const int p = t + i * 1024;
        const int e = le[i];
        const int slot = run[e]++;
        g_pair_slot[p] = slot;
        g_rows_token[slot] = p >> 1;
    }
}

// ---------------- kernel: A-gather (slot-ordered hi/lo split of x) ----------------
__global__ __launch_bounds__(256) void gather_kernel(const float* __restrict__ x) {
    const int b = blockIdx.y * 64 + blockIdx.x;
    const int t = threadIdx.x;
    for (int rr = 0; rr < 16; ++rr) {
        const int slot = b * 16 + rr;
        const int tok = g_rows_token[slot];
        const float4 v = reinterpret_cast<const float4*>(x + (size_t)tok * DM)[t];
        __nv_bfloat16 h0 = __float2bfloat16_rn(v.x), h1 = __float2bfloat16_rn(v.y);
        __nv_bfloat16 h2 = __float2bfloat16_rn(v.z), h3 = __float2bfloat16_rn(v.w);
        __nv_bfloat16 l0 = __float2bfloat16_rn(v.x - __bfloat162float(h0));
        __nv_bfloat16 l1 = __float2bfloat16_rn(v.y - __bfloat162float(h1));
        __nv_bfloat16 l2 = __float2bfloat16_rn(v.z - __bfloat162float(h2));
        __nv_bfloat16 l3 = __float2bfloat16_rn(v.w - __bfloat162float(h3));
        reinterpret_cast<uint2*>(g_Ah + (size_t)slot * DM)[t] =
            make_uint2(pack_bf16(h0, h1), pack_bf16(h2, h3));
        reinterpret_cast<uint2*>(g_Al + (size_t)slot * DM)[t] =
            make_uint2(pack_bf16(l0, l1), pack_bf16(l2, l3));
    }
}

// ---------------- kernel: weight split + transpose (tc path only; side stream) ----------------
// in:  W[e][k][n] fp32 (n contiguous); out: Wh/Wl[e][n][k] bf16 (k contiguous)
__global__ __launch_bounds__(256) void wsplit_kernel(const float* __restrict__ W,
                                                     __nv_bfloat16* __restrict__ Wh,
                                                     __nv_bfloat16* __restrict__ Wl,
                                                     int K, int N) {
#if HAS_TC
    __shared__ float tile[64][65];
    const int e = blockIdx.z;
    const int K0 = blockIdx.x * 64, N0 = blockIdx.y * 64;
    const float* src = W + ((size_t)e * K + K0) * N + N0;
    const int t = threadIdx.x;
    const int r = t >> 4, c4 = (t & 15) * 4;
#pragma unroll
    for (int j = 0; j < 4; ++j) {
        int rr = r + j * 16;
        const float4 v = *reinterpret_cast<const float4*>(src + (size_t)rr * N + c4);
        tile[rr][c4 + 0] = v.x; tile[rr][c4 + 1] = v.y;
        tile[rr][c4 + 2] = v.z; tile[rr][c4 + 3] = v.w;
    }
    __syncthreads();
#pragma unroll
    for (int j = 0; j < 4; ++j) {
        int nn = r + j * 16;
        float v0 = tile[c4 + 0][nn], v1 = tile[c4 + 1][nn];
        float v2 = tile[c4 + 2][nn], v3 = tile[c4 + 3][nn];
        __nv_bfloat16 h0 = __float2bfloat16_rn(v0), h1 = __float2bfloat16_rn(v1);
        __nv_bfloat16 h2 = __float2bfloat16_rn(v2), h3 = __float2bfloat16_rn(v3);
        __nv_bfloat16 l0 = __float2bfloat16_rn(v0 - __bfloat162float(h0));
        __nv_bfloat16 l1 = __float2bfloat16_rn(v1 - __bfloat162float(h1));
        __nv_bfloat16 l2 = __float2bfloat16_rn(v2 - __bfloat162float(h2));
        __nv_bfloat16 l3 = __float2bfloat16_rn(v3 - __bfloat162float(h3));
        size_t out = ((size_t)e * N + N0 + nn) * K + K0 + c4;
        *reinterpret_cast<uint2*>(Wh + out) = make_uint2(pack_bf16(h0, h1), pack_bf16(h2, h3));
        *reinterpret_cast<uint2*>(Wl + out) = make_uint2(pack_bf16(l0, l1), pack_bf16(l2, l3));
    }
#endif
}

// ---------------- kernel: post-GEMM1 GELU + hi/lo split (streaming) ----------------
__global__ __launch_bounds__(256) void postgelu_kernel() {
    const size_t base = (size_t)blockIdx.x * DF;
    const int t = threadIdx.x;
#pragma unroll
    for (int j = 0; j < 4; ++j) {
        const int i = (j * 256 + t) * 4;
        const float4 v = *reinterpret_cast<const float4*>(g_Hf + base + i);
        float a0 = gelu_exact(v.x);
        float a1 = gelu_exact(v.y);
        float a2 = gelu_exact(v.z);
        float a3 = gelu_exact(v.w);
        __nv_bfloat16 h0 = __float2bfloat16_rn(a0), h1 = __float2bfloat16_rn(a1);
        __nv_bfloat16 h2 = __float2bfloat16_rn(a2), h3 = __float2bfloat16_rn(a3);
        __nv_bfloat16 l0 = __float2bfloat16_rn(a0 - __bfloat162float(h0));
        __nv_bfloat16 l1 = __float2bfloat16_rn(a1 - __bfloat162float(h1));
        __nv_bfloat16 l2 = __float2bfloat16_rn(a2 - __bfloat162float(h2));
        __nv_bfloat16 l3 = __float2bfloat16_rn(a3 - __bfloat162float(h3));
        *reinterpret_cast<uint2*>(g_Hh + base + i) = make_uint2(pack_bf16(h0, h1), pack_bf16(h2, h3));
        *reinterpret_cast<uint2*>(g_Hl + base + i) = make_uint2(pack_bf16(l0, l1), pack_bf16(l2, l3));
    }
}

// ---------------- tcgen05 cg2 GEMM: persistent clusters, double-buffered TMEM D ----------------
#define BUF_STRIDE 65536
#define OFF_AL 16384
#define OFF_BH 32768
#define OFF_BL 49152
#define OFF_TMEM 196608
#define OFF_MBAR 196624
#define SMEM_DYN 198656
#define STAGE_BYTES 65536u
// mbar layout: full[0..2]@+0,8,16 ; empty[0..2]@+24,32,40 ; done[0..1]@+48,56 ; free[0..1]@+64,72

#define GEMM_IDESC2 ((1u << 4) | (1u << 7) | (1u << 10) | ((256u / 8) << 17) | ((256u / 16) << 24))

template <bool FIRST>
__global__ __launch_bounds__(256)
void moe_gemm_tc(const __grid_constant__ CUtensorMap tmAh,
                 const __grid_constant__ CUtensorMap tmAl,
                 const __grid_constant__ CUtensorMap tmBh,
                 const __grid_constant__ CUtensorMap tmBl,
                 const float* __restrict__ bias) {
#if HAS_TC
    constexpr int KTOT = FIRST ? DM : DF;
    constexpr int NTOT = FIRST ? DF : DM;
    constexpr int NC = KTOT / 64;
    constexpr int NXT = NTOT / 256;

    const int cid = blockIdx.y;
    const int rank = blockIdx.x & 1;
    const int tot = g_num_tiles * NXT;

    extern __shared__ char dyn[];
    const uint32_t raw = smaddr(dyn);
    const uint32_t sbase = (raw + 1023u) & ~1023u;
    const int t = threadIdx.x;
    const int w = t >> 5, lane = t & 31;

    if (w == 0) {
        tc_alloc2(sbase + OFF_TMEM, 512);
        tc_relinq2();
    }
    if (t == 0) {
#pragma unroll
        for (int s = 0; s < 8; ++s) mbar_init(sbase + OFF_MBAR + s * 8, 1);
        mbar_init(sbase + OFF_MBAR + 64, 2);
        mbar_init(sbase + OFF_MBAR + 72, 2);
    }
    __syncthreads();
    cluster_sync_();

    uint32_t tmem;
    asm volatile("ld.shared.b32 %0, [%1];" : "=r"(tmem) : "r"(sbase + OFF_TMEM));

    const uint32_t mbF = sbase + OFF_MBAR;
    const uint32_t mbE = sbase + OFF_MBAR + 24;
    const uint32_t mbD = sbase + OFF_MBAR + 48;
    const uint32_t mbR = sbase + OFF_MBAR + 64;

    if (w == 0 && elect_one()) {
        // ================= producer: continuous TMA across tiles =================
        uint32_t pE = 0, pDp = 0;
        int s = 0;
#pragma unroll 1
        for (int tt = 0;; ++tt) {
            const int T = cid + tt * NCLUST;
            if (T >= tot) break;
            const int rt = T / NXT, nt = T % NXT;
            const int e = g_tile_e[rt];
            const int arow = g_tile_r0[rt] + rank * 128;
            const int bcol = nt * 256 + rank * 128;
#pragma unroll 1
            for (int i = 0; i < NC; ++i, ++s) {
                const int b = s % 3;
                if (s >= 3) {
                    const int sp_ = s - 3;
                    if ((sp_ % NC) == NC - 1) {
                        const int d = (sp_ / NC) & 1;
                        mbar_wait(mbD + d * 8, (pDp >> d) & 1u); pDp ^= 1u << d;
                    } else {
                        mbar_wait(mbE + b * 8, (pE >> b) & 1u); pE ^= 1u << b;
                    }
                }
                if (rank == 0) mbar_expect(mbF + b * 8, 2u * STAGE_BYTES);
                const uint32_t bb = sbase + (uint32_t)b * BUF_STRIDE;
                const int k0 = i * 64;
                tma2d_cg2(bb,          (const void*)&tmAh, k0, arow, mbF + b * 8);
                tma2d_cg2(bb + OFF_AL, (const void*)&tmAl, k0, arow, mbF + b * 8);
                tma3d_cg2(bb + OFF_BH, (const void*)&tmBh, k0, bcol, e, mbF + b * 8);
                tma3d_cg2(bb + OFF_BL, (const void*)&tmBl, k0, bcol, e, mbF + b * 8);
            }
        }
    } else if (w == 1 && rank == 0 && elect_one()) {
        // ================= consumer: MMA =================
        uint64_t dA[3], dAl_[3], dB[3], dBl_[3];
#pragma unroll
        for (int s2 = 0; s2 < 3; ++s2) {
            uint32_t b = sbase + s2 * BUF_STRIDE;
            dA[s2]   = mk_desc(b);
            dAl_[s2] = mk_desc(b + OFF_AL);
            dB[s2]   = mk_desc(b + OFF_BH);
            dBl_[s2] = mk_desc(b + OFF_BL);
        }
        uint32_t pF = 0, pFree = 0;
        int s = 0, ttn = 0;
#pragma unroll 1
        for (int tt = 0;; ++tt) {
            const int T = cid + tt * NCLUST;
            if (T >= tot) break;
            ttn = tt + 1;
            const int d = tt & 1;
            if (tt >= 2) {
                mbar_wait(mbR + d * 8, (pFree >> d) & 1u); pFree ^= 1u << d;
                tc_fence_after();
            }
            const uint32_t dtm = tmem + d * 256;
#pragma unroll 1
            for (int i = 0; i < NC; ++i, ++s) {
                const int b = s % 3;
                mbar_wait(mbF + b * 8, (pF >> b) & 1u); pF ^= 1u << b;
#pragma unroll
                for (int ks = 0; ks < 4; ++ks) {
                    const uint64_t oa = (uint64_t)(ks * 2);
                    const uint32_t en0 = (i == 0 && ks == 0) ? 0u : 1u;
                    tc_mma_f16_ss2(dtm, dA[b] + oa,   dB[b] + oa,   GEMM_IDESC2, en0);
                    tc_mma_f16_ss2(dtm, dA[b] + oa,   dBl_[b] + oa, GEMM_IDESC2, 1u);
                    tc_mma_f16_ss2(dtm, dAl_[b] + oa, dB[b] + oa,   GEMM_IDESC2, 1u);
                }
                tc_commit_mc2((i == NC - 1) ? (mbD + d * 8) : (mbE + b * 8));
            }
        }
#pragma unroll 1
        for (int k = (ttn >= 2 ? ttn - 2 : 0); k < ttn; ++k) {
            const int d = k & 1;
            mbar_wait(mbR + d * 8, (pFree >> d) & 1u); pFree ^= 1u << d;
        }
    } else if (w >= 2) {
        // ================= epilogue: warps 2..7 (raw fp32 + bias only) =================
        const int sp_ = w & 3;
        const int rloc = sp_ * 32 + lane;
        int cstart, cnum;
        if (w == 4 || w == 5)      { cstart = 0;   cnum = 8; }
        else if (w == 2 || w == 3) { cstart = 0;   cnum = 4; }
        else                       { cstart = 128; cnum = 4; }

        uint32_t pDe = 0;
#pragma unroll 1
        for (int tt = 0;; ++tt) {
            const int T = cid + tt * NCLUST;
            if (T >= tot) break;
            const int d = tt & 1;
            mbar_wait(mbD + d * 8, (pDe >> d) & 1u); pDe ^= 1u << d;
            tc_fence_after();

            const int rt = T / NXT, nt = T % NXT;
            const int e = g_tile_e[rt];
            const int row0 = g_tile_r0[rt];
            const int n0 = nt * 256;
            int vr = g_tile_valid[rt] - rank * 128;
            vr = vr < 0 ? 0 : (vr > 128 ? 128 : vr);
            const bool valid = rloc < vr;
            const int rowg = row0 + rank * 128 + rloc;
            const uint32_t dtm = tmem + d * 256;
            const float* bb = bias + (size_t)e * NTOT + n0;
            float* oF = (FIRST ? g_Hf + (size_t)rowg * DF : g_Y + (size_t)rowg * DM) + n0;

#pragma unroll 1
            for (int j = 0; j < cnum; ++j) {
                const int col = cstart + j * 32;
                uint32_t dr[32];
                tc_ld_x32(dr, dtm + col);
                tc_wait_ld();
                if (valid) {
#pragma unroll
                    for (int c = 0; c < 32; c += 4) {
                        float4 o;
                        o.x = __uint_as_float(dr[c + 0]) + bb[col + c + 0];
                        o.y = __uint_as_float(dr[c + 1]) + bb[col + c + 1];
                        o.z = __uint_as_float(dr[c + 2]) + bb[col + c + 2];
                        o.w = __uint_as_float(dr[c + 3]) + bb[col + c + 3];
                        *reinterpret_cast<float4*>(oF + col + c) = o;
                    }
                }
            }
            tc_fence_before();
            asm volatile("bar.sync 1, 192;" ::: "memory");
            if (w == 2 && elect_one()) mbar_arrive_leader(mbR + d * 8);
        }
    }

    __syncthreads();
    if (t == 0) {
#pragma unroll
        for (int s = 0; s < 10; ++s) mbar_inval(sbase + OFF_MBAR + s * 8);
    }
    __syncthreads();
    cluster_sync_();
    if (w == 0) tc_dealloc2(tmem, 512);
    cluster_sync_();
#endif  // HAS_TC
}

// ---------------- fallback GEMM (mma.sync; 256-tiles split in half) ----------------
template <bool FIRST>
__global__ __launch_bounds__(256) void moe_gemm_fb(const float* __restrict__ W,
                                                   const float* __restrict__ bias) {
#if !HAS_TC
    constexpr int KTOT = FIRST ? DM : DF;
    constexpr int LDW  = FIRST ? DF : DM;
    const int tileIdx = blockIdx.y >> 1;
    if (tileIdx >= g_num_tiles) return;
    const int half = blockIdx.y & 1;
    const int e = g_tile_e[tileIdx];
    const int row0 = g_tile_r0[tileIdx] + half * 128;
    int vrows = g_tile_valid[tileIdx] - half * 128;
    vrows = vrows < 0 ? 0 : (vrows > 128 ? 128 : vrows);
    if (vrows == 0) return;
    const int n0 = blockIdx.x * 128;
    const float* Wn = W + (size_t)e * KTOT * LDW + n0;
    const float* bn = bias + (size_t)e * LDW + n0;

    __shared__ __align__(16) __nv_bfloat16 sAh[128 * 40];
    __shared__ __align__(16) __nv_bfloat16 sAl[128 * 40];
    __shared__ __align__(16) __nv_bfloat16 sBh[32 * 136];
    __shared__ __align__(16) __nv_bfloat16 sBl[32 * 136];

    const int t = threadIdx.x;
    float c[4][4][4];
#pragma unroll
    for (int a = 0; a < 4; ++a)
#pragma unroll
        for (int b = 0; b < 4; ++b)
#pragma unroll
            for (int q = 0; q < 4; ++q) c[a][b][q] = 0.f;

    const int lane = t & 31, warp = t >> 5;
    const int wm = warp >> 2, wn = warp & 3;
    const int m0 = wm * 64;
    const int sub = t & 15, rgrp = t >> 4;

    for (int k0 = 0; k0 < KTOT; k0 += 32) {
        __syncthreads();
#pragma unroll
        for (int rr = 0; rr < 8; ++rr) {
            int r = rr * 16 + rgrp;
            int rg = row0 + r; if (rg > PAIRS - 1) rg = PAIRS - 1;
            const uint32_t* ph = reinterpret_cast<const uint32_t*>(
                (FIRST ? g_Ah : g_Hh) + (size_t)rg * KTOT + k0);
            const uint32_t* pl = reinterpret_cast<const uint32_t*>(
                (FIRST ? g_Al : g_Hl) + (size_t)rg * KTOT + k0);
            *reinterpret_cast<uint32_t*>(&sAh[r * 40 + sub * 2]) = ph[sub];
            *reinterpret_cast<uint32_t*>(&sAl[r * 40 + sub * 2]) = pl[sub];
        }
#pragma unroll
        for (int i = 0; i < 4; ++i) {
            int lin = (i * 256 + t) * 4;
            int kr = lin >> 7;
            int nc = lin & 127;
            const float4 v = *reinterpret_cast<const float4*>(Wn + (size_t)(k0 + kr) * LDW + nc);
            __nv_bfloat16 h0 = __float2bfloat16_rn(v.x);
            __nv_bfloat16 h1 = __float2bfloat16_rn(v.y);
            __nv_bfloat16 h2 = __float2bfloat16_rn(v.z);
            __nv_bfloat16 h3 = __float2bfloat16_rn(v.w);
            __nv_bfloat16 l0 = __float2bfloat16_rn(v.x - __bfloat162float(h0));
            __nv_bfloat16 l1 = __float2bfloat16_rn(v.y - __bfloat162float(h1));
            __nv_bfloat16 l2 = __float2bfloat16_rn(v.z - __bfloat162float(h2));
            __nv_bfloat16 l3 = __float2bfloat16_rn(v.w - __bfloat162float(h3));
            *reinterpret_cast<uint2*>(&sBh[kr * 136 + nc]) = make_uint2(pack_bf16(h0, h1), pack_bf16(h2, h3));
            *reinterpret_cast<uint2*>(&sBl[kr * 136 + nc]) = make_uint2(pack_bf16(l0, l1), pack_bf16(l2, l3));
        }
        __syncthreads();

#pragma unroll
        for (int ks = 0; ks < 2; ++ks) {
            uint32_t ah[4][4], al[4][4], bh[4][2], bl[4][2];
            {
                int ar = lane & 15;
                int acol = ks * 16 + (lane >> 4) * 8;
#pragma unroll
                for (int fm = 0; fm < 4; ++fm) {
                    ldsm4(ah[fm], smaddr(&sAh[(m0 + fm * 16 + ar) * 40 + acol]));
                    ldsm4(al[fm], smaddr(&sAl[(m0 + fm * 16 + ar) * 40 + acol]));
                }
                int brow = ks * 16 + (lane & 15);
                int bcol = wn * 32 + (lane >> 4) * 8;
#pragma unroll
                for (int hb = 0; hb < 2; ++hb) {
                    uint32_t r[4];
                    ldsm4t(r, smaddr(&sBh[brow * 136 + bcol + hb * 16]));
                    bh[2 * hb][0] = r[0]; bh[2 * hb][1] = r[1];
                    bh[2 * hb + 1][0] = r[2]; bh[2 * hb + 1][1] = r[3];
                    ldsm4t(r, smaddr(&sBl[brow * 136 + bcol + hb * 16]));
                    bl[2 * hb][0] = r[0]; bl[2 * hb][1] = r[1];
                    bl[2 * hb + 1][0] = r[2]; bl[2 * hb + 1][1] = r[3];
                }
            }
#pragma unroll
            for (int fm = 0; fm < 4; ++fm)
#pragma unroll
                for (int fn = 0; fn < 4; ++fn) {
                    mma16816(c[fm][fn], ah[fm], bh[fn]);
                    mma16816(c[fm][fn], ah[fm], bl[fn]);
                    mma16816(c[fm][fn], al[fm], bh[fn]);
                }
        }
    }

    const int lgrp = lane >> 2, lq = lane & 3;
#pragma unroll
    for (int fm = 0; fm < 4; ++fm) {
        int rl = m0 + fm * 16 + lgrp;
#pragma unroll
        for (int fn = 0; fn < 4; ++fn) {
            int nc = wn * 32 + fn * 8 + lq * 2;
            float bv0 = bn[nc], bv1 = bn[nc + 1];
            float* cc = c[fm][fn];
#pragma unroll
            for (int h = 0; h < 2; ++h) {
                int rloc = rl + h * 8;
                if (rloc < vrows) {
                    int row = row0 + rloc;
                    float v0 = cc[h * 2 + 0] + bv0;
                    float v1 = cc[h * 2 + 1] + bv1;
                    if (FIRST) {
                        *reinterpret_cast<float2*>(&g_Hf[(size_t)row * DF + n0 + nc]) = make_float2(v0, v1);
                    } else {
                        *reinterpret_cast<float2*>(&g_Y[(size_t)row * DM + n0 + nc]) = make_float2(v0, v1);
                    }
                }
            }
        }
    }
#endif  // !HAS_TC
}

// ---------------- kernel: weighted combine ----------------
__global__ __launch_bounds__(256) void combine_kernel(float* __restrict__ out) {
    const int tk = blockIdx.x;
    const int d = threadIdx.x * 4;
    int s0 = g_pair_slot[2 * tk], s1 = g_pair_slot[2 * tk + 1];
    float w0 = g_pair_w[2 * tk], w1 = g_pair_w[2 * tk + 1];
    const float4 a = *reinterpret_cast<const float4*>(&g_Y[(size_t)s0 * DM + d]);
    const float4 b = *reinterpret_cast<const float4*>(&g_Y[(size_t)s1 * DM + d]);
    float4 o;
    o.x = w0 * a.x + w1 * b.x;
    o.y = w0 * a.y + w1 * b.y;
    o.z = w0 * a.z + w1 * b.z;
    o.w = w0 * a.w + w1 * b.w;
    *reinterpret_cast<float4*>(&out[(size_t)tk * DM + d]) = o;
}

// ---------------- host: tensor map construction ----------------
typedef CUresult (*TmEncodeFn)(CUtensorMap*, CUtensorMapDataType, cuuint32_t, void*,
                               const cuuint64_t*, const cuuint64_t*, const cuuint32_t*,
                               const cuuint32_t*, CUtensorMapInterleave, CUtensorMapSwizzle,
                               CUtensorMapL2promotion, CUtensorMapFloatOOBfill);

static void tm2d(TmEncodeFn enc, CUtensorMap* tm, void* base, unsigned long long K,
                 unsigned long long R) {
    cuuint64_t dims[2] = {K, R};
    cuuint64_t st[1] = {K * 2};
    cuuint32_t box[2] = {64, 128};
    cuuint32_t es[2] = {1, 1};
    enc(tm, CU_TENSOR_MAP_DATA_TYPE_BFLOAT16, 2, base, dims, st, box, es,
        CU_TENSOR_MAP_INTERLEAVE_NONE, CU_TENSOR_MAP_SWIZZLE_128B,
        CU_TENSOR_MAP_L2_PROMOTION_L2_128B, CU_TENSOR_MAP_FLOAT_OOB_FILL_NONE);
}
static void tm3d(TmEncodeFn enc, CUtensorMap* tm, void* base, unsigned long long K,
                 unsigned long long N) {
    cuuint64_t dims[3] = {K, N, NE};
    cuuint64_t st[2] = {K * 2, N * K * 2};
    cuuint32_t box[3] = {64, 128, 1};
    cuuint32_t es[3] = {1, 1, 1};
    enc(tm, CU_TENSOR_MAP_DATA_TYPE_BFLOAT16, 3, base, dims, st, box, es,
        CU_TENSOR_MAP_INTERLEAVE_NONE, CU_TENSOR_MAP_SWIZZLE_128B,
        CU_TENSOR_MAP_L2_PROMOTION_L2_128B, CU_TENSOR_MAP_FLOAT_OOB_FILL_NONE);
}

// ---------------- launch ----------------
extern "C" void kernel_launch(void* const* d_in, const int* in_sizes, int n_in,
                              void* d_out, int out_size) {
    const float* x  = (const float*)d_in[0];
    const float* gw = (const float*)d_in[1];
    const float* w1 = (const float*)d_in[2];
    const float* b1 = (const float*)d_in[3];
    const float* w2 = (const float*)d_in[4];
    const float* b2 = (const float*)d_in[5];
    float* out = (float*)d_out;

    cudaFuncSetAttribute(moe_gemm_tc<true>,  cudaFuncAttributeMaxDynamicSharedMemorySize, SMEM_DYN);
    cudaFuncSetAttribute(moe_gemm_tc<false>, cudaFuncAttributeMaxDynamicSharedMemorySize, SMEM_DYN);

    void *pAh, *pAl, *pHh, *pHl, *pW1h, *pW1l, *pW2h, *pW2l;
    cudaGetSymbolAddress(&pAh, g_Ah);
    cudaGetSymbolAddress(&pAl, g_Al);
    cudaGetSymbolAddress(&pHh, g_Hh);
    cudaGetSymbolAddress(&pHl, g_Hl);
    cudaGetSymbolAddress(&pW1h, g_w1h);
    cudaGetSymbolAddress(&pW1l, g_w1l);
    cudaGetSymbolAddress(&pW2h, g_w2h);
    cudaGetSymbolAddress(&pW2l, g_w2l);

    void* sym = nullptr;
    cudaDriverEntryPointQueryResult qr;
    cudaGetDriverEntryPoint("cuTensorMapEncodeTiled", &sym, cudaEnableDefault, &qr);
    TmEncodeFn enc = (TmEncodeFn)sym;

    CUtensorMap tAh, tAl, tB1h, tB1l, tHh, tHl, tB2h, tB2l;
    if (enc) {
        tm2d(enc, &tAh, pAh, DM, PAIRS);
        tm2d(enc, &tAl, pAl, DM, PAIRS);
        tm3d(enc, &tB1h, pW1h, DM, DF);
        tm3d(enc, &tB1l, pW1l, DM, DF);
        tm2d(enc, &tHh, pHh, DF, PAIRS);
        tm2d(enc, &tHl, pHl, DF, PAIRS);
        tm3d(enc, &tB2h, pW2h, DF, DM);
        tm3d(enc, &tB2l, pW2l, DF, DM);
    }

    // side stream + events (lazily created once; control-flow resources only)
    static cudaStream_t sSide = nullptr;
    static cudaEvent_t evFork = nullptr, evW1 = nullptr, evW2 = nullptr;
    if (!sSide) {
        cudaStreamCreateWithFlags(&sSide, cudaStreamNonBlocking);
        cudaEventCreateWithFlags(&evFork, cudaEventDisableTiming);
        cudaEventCreateWithFlags(&evW1, cudaEventDisableTiming);
        cudaEventCreateWithFlags(&evW2, cudaEventDisableTiming);
    }

    // fork: weight split runs on side stream, independent of routing
    cudaEventRecord(evFork, 0);
    cudaStreamWaitEvent(sSide, evFork, 0);
    wsplit_kernel<<<dim3(DM / 64, DF / 64, NE), 256, 0, sSide>>>(w1, (__nv_bfloat16*)pW1h, (__nv_bfloat16*)pW1l, DM, DF);
    cudaEventRecord(evW1, sSide);
    wsplit_kernel<<<dim3(DF / 64, DM / 64, NE), 256, 0, sSide>>>(w2, (__nv_bfloat16*)pW2h, (__nv_bfloat16*)pW2l, DF, DM);
    cudaEventRecord(evW2, sSide);

    // main stream: routing + gather
    gate_kernel<<<T_TOKENS / 8, 256>>>(x, gw);
    sortscan_kernel<<<1, 1024>>>();
    gather_kernel<<<dim3(64, 16), 256>>>(x);

    cudaLaunchAttribute cat[1];
    cat[0].id = cudaLaunchAttributeClusterDimension;
    cat[0].val.clusterDim.x = 2;
    cat[0].val.clusterDim.y = 1;
    cat[0].val.clusterDim.z = 1;

    cudaStreamWaitEvent(0, evW1, 0);  // join w1 split
    {
        cudaLaunchConfig_t cfg = {};
        cfg.gridDim = dim3(2, NCLUST, 1);
        cfg.blockDim = dim3(256, 1, 1);
        cfg.dynamicSmemBytes = SMEM_DYN;
        cfg.stream = 0;
        cfg.attrs = cat;
        cfg.numAttrs = 1;
        cudaLaunchKernelEx(&cfg, moe_gemm_tc<true>, tAh, tAl, tB1h, tB1l, b1);
    }
    moe_gemm_fb<true><<<dim3(DF / 128, MAXT2 * 2), 256>>>(w1, b1);   // no-op on tc build
    postgelu_kernel<<<PAIRS, 256>>>();
    cudaStreamWaitEvent(0, evW2, 0);  // join w2 split
    {
        cudaLaunchConfig_t cfg = {};
        cfg.gridDim = dim3(2, NCLUST, 1);
        cfg.blockDim = dim3(256, 1, 1);
        cfg.dynamicSmemBytes = SMEM_DYN;
        cfg.stream = 0;
        cfg.attrs = cat;
        cfg.numAttrs = 1;
        cudaLaunchKernelEx(&cfg, moe_gemm_tc<false>, tHh, tHl, tB2h, tB2l, b2);
    }
    moe_gemm_fb<false><<<dim3(DM / 128, MAXT2 * 2), 256>>>(w2, b2);  // no-op on tc build
    combine_kernel<<<T_TOKENS, 256>>>(out);
}

// round 14
// speedup vs baseline: 1.6719x; 1.0198x over previous
#include <cuda_runtime.h>
#include <cuda.h>
#include <cuda_bf16.h>
#include <stdint.h>

#define T_TOKENS 8192
#define DM 1024
#define DF 4096
#define NE 8
#define PAIRS 16384
#define MAXTILES 144
#define MAXT2 72
#define NCLUST 74

// tcgen05 availability: only in the arch-SPECIFIC device pass (sm_103a / sm_100a).
#if defined(__CUDA_ARCH__) && (defined(__CUDA_ARCH_FEAT_SM103_ALL) || defined(__CUDA_ARCH_FEAT_SM100_ALL) || defined(__CUDA_ARCH_SPECIFIC__))
#define HAS_TC 1
#else
#define HAS_TC 0
#endif

// ---------------- scratch (device globals; no allocations) ----------------
__device__ __align__(128) __nv_bfloat16 g_Ah[(size_t)PAIRS * DM];
__device__ __align__(128) __nv_bfloat16 g_Al[(size_t)PAIRS * DM];
__device__ __align__(128) float         g_Hf[(size_t)PAIRS * DF];   // raw GEMM1 out (bias added)
__device__ __align__(128) __nv_bfloat16 g_Hh[(size_t)PAIRS * DF];
__device__ __align__(128) __nv_bfloat16 g_Hl[(size_t)PAIRS * DF];
__device__ __align__(128) float         g_Y[(size_t)PAIRS * DM];

__device__ __align__(128) __nv_bfloat16 g_w1h[(size_t)NE * DM * DF];
__device__ __align__(128) __nv_bfloat16 g_w1l[(size_t)NE * DM * DF];
__device__ __align__(128) __nv_bfloat16 g_w2h[(size_t)NE * DF * DM];
__device__ __align__(128) __nv_bfloat16 g_w2l[(size_t)NE * DF * DM];

__device__ int   g_pair_e[PAIRS];
__device__ float g_pair_w[PAIRS];
__device__ int   g_pair_slot[PAIRS];
__device__ int   g_rows_token[PAIRS];

__device__ int g_counts[NE];
__device__ int g_off[NE + 1];
__device__ int g_tile_e[MAXTILES];
__device__ int g_tile_r0[MAXTILES];
__device__ int g_tile_valid[MAXTILES];
__device__ int g_num_tiles;

// ---------------- shared helpers ----------------
__device__ __forceinline__ uint32_t smaddr(const void* p) {
    return (uint32_t)__cvta_generic_to_shared(p);
}
__device__ __forceinline__ uint32_t pack_bf16(__nv_bfloat16 a, __nv_bfloat16 b) {
    return (uint32_t)__bfloat16_as_ushort(a) | ((uint32_t)__bfloat16_as_ushort(b) << 16);
}
__device__ __forceinline__ float gelu_exact(float v) {
    return 0.5f * v * (1.0f + erff(v * 0.70710678118654752f));
}

#if HAS_TC
// ---------------- tcgen05 / cg2 helpers ----------------
__device__ __forceinline__ uint32_t elect_one() {
    uint32_t pred;
    asm volatile("{\n\t.reg .pred p;\n\telect.sync _|p, 0xFFFFFFFF;\n\tselp.b32 %0, 1, 0, p;\n\t}"
                 : "=r"(pred));
    return pred;
}
__device__ __forceinline__ void cluster_sync_() {
    asm volatile("barrier.cluster.arrive.aligned;" ::: "memory");
    asm volatile("barrier.cluster.wait.aligned;" ::: "memory");
}
__device__ __forceinline__ void mbar_init(uint32_t addr, uint32_t cnt) {
    asm volatile("mbarrier.init.shared.b64 [%0], %1;" :: "r"(addr), "r"(cnt) : "memory");
}
__device__ __forceinline__ void mbar_inval(uint32_t addr) {
    asm volatile("mbarrier.inval.shared.b64 [%0];" :: "r"(addr) : "memory");
}
__device__ __forceinline__ void mbar_expect(uint32_t addr, uint32_t bytes) {
    asm volatile("mbarrier.arrive.expect_tx.shared.b64 _, [%0], %1;"
                 :: "r"(addr), "r"(bytes) : "memory");
}
__device__ __forceinline__ void mbar_wait(uint32_t addr, uint32_t parity) {
    asm volatile(
        "{\n\t.reg .pred P1;\n"
        "WAIT_%=:\n\t"
        "mbarrier.try_wait.parity.acquire.cta.shared::cta.b64 P1, [%0], %1, 0x989680;\n\t"
        "@P1 bra.uni DONE_%=;\n\t"
        "bra.uni WAIT_%=;\n"
        "DONE_%=:\n\t}"
        :: "r"(addr), "r"(parity) : "memory");
}
// arrive on rank0's mbarrier (cg2 leader: clear bit 24)
__device__ __forceinline__ void mbar_arrive_leader(uint32_t addr) {
    asm volatile(
        "{\n\t.reg .b32 la;\n\t"
        "and.b32 la, %0, 0xFEFFFFFF;\n\t"
        "mbarrier.arrive.shared::cluster.b64 _, [la];\n\t}"
        :: "r"(addr) : "memory");
}
__device__ __forceinline__ void tma2d_cg2(uint32_t dst, const void* tm, int x, int y, uint32_t mbar) {
    asm volatile(
        "{\n\t.reg .b32 lb;\n\t"
        "and.b32 lb, %4, 0xFEFFFFFF;\n\t"
        "cp.async.bulk.tensor.2d.cta_group::2.shared::cluster.global.tile.mbarrier::complete_tx::bytes "
        "[%0], [%1, {%2, %3}], [lb];\n\t}"
        :: "r"(dst), "l"(tm), "r"(x), "r"(y), "r"(mbar) : "memory");
}
__device__ __forceinline__ void tma3d_cg2(uint32_t dst, const void* tm, int x, int y, int z, uint32_t mbar) {
    asm volatile(
        "{\n\t.reg .b32 lb;\n\t"
        "and.b32 lb, %5, 0xFEFFFFFF;\n\t"
        "cp.async.bulk.tensor.3d.cta_group::2.shared::cluster.global.tile.mbarrier::complete_tx::bytes "
        "[%0], [%1, {%2, %3, %4}], [lb];\n\t}"
        :: "r"(dst), "l"(tm), "r"(x), "r"(y), "r"(z), "r"(mbar) : "memory");
}
__device__ __forceinline__ void tc_mma_f16_ss2(uint32_t d, uint64_t a, uint64_t b,
                                               uint32_t idesc, uint32_t en) {
    asm volatile(
        "{\n\t.reg .pred p;\n\tsetp.ne.u32 p, %5, 0;\n\t"
        "tcgen05.mma.cta_group::2.kind::f16 [%0], %1, %2, %3, "
        "{%4, %4, %4, %4, %4, %4, %4, %4}, p;\n\t}"
        :: "r"(d), "l"(a), "l"(b), "r"(idesc), "r"(0u), "r"(en) : "memory");
}
__device__ __forceinline__ void tc_commit_mc2(uint32_t mbar) {
    asm volatile(
        "tcgen05.commit.cta_group::2.mbarrier::arrive::one.shared::cluster.multicast::cluster.b64 [%0], %1;"
        :: "r"(mbar), "h"((uint16_t)0x3) : "memory");
}
__device__ __forceinline__ void tc_alloc2(uint32_t smem_slot, uint32_t ncols) {
    asm volatile("tcgen05.alloc.cta_group::2.sync.aligned.shared::cta.b32 [%0], %1;"
                 :: "r"(smem_slot), "r"(ncols) : "memory");
}
__device__ __forceinline__ void tc_dealloc2(uint32_t tmem, uint32_t ncols) {
    asm volatile("tcgen05.dealloc.cta_group::2.sync.aligned.b32 %0, %1;" :: "r"(tmem), "r"(ncols));
}
__device__ __forceinline__ void tc_relinq2() {
    asm volatile("tcgen05.relinquish_alloc_permit.cta_group::2.sync.aligned;");
}
__device__ __forceinline__ void tc_fence_after() {
    asm volatile("tcgen05.fence::after_thread_sync;" ::: "memory");
}
__device__ __forceinline__ void tc_fence_before() {
    asm volatile("tcgen05.fence::before_thread_sync;" ::: "memory");
}
__device__ __forceinline__ void tc_wait_ld() {
    asm volatile("tcgen05.wait::ld.sync.aligned;" ::: "memory");
}
__device__ __forceinline__ void tc_ld_x32(uint32_t* r, uint32_t addr) {
    asm volatile(
        "tcgen05.ld.sync.aligned.32x32b.x32.b32 "
        "{%0, %1, %2, %3, %4, %5, %6, %7, %8, %9, %10, %11, %12, %13, %14, %15, "
        " %16, %17, %18, %19, %20, %21, %22, %23, %24, %25, %26, %27, %28, %29, %30, %31}, [%32];"
        : "=r"(r[0]), "=r"(r[1]), "=r"(r[2]), "=r"(r[3]), "=r"(r[4]), "=r"(r[5]), "=r"(r[6]), "=r"(r[7]),
          "=r"(r[8]), "=r"(r[9]), "=r"(r[10]), "=r"(r[11]), "=r"(r[12]), "=r"(r[13]), "=r"(r[14]), "=r"(r[15]),
          "=r"(r[16]), "=r"(r[17]), "=r"(r[18]), "=r"(r[19]), "=r"(r[20]), "=r"(r[21]), "=r"(r[22]), "=r"(r[23]),
          "=r"(r[24]), "=r"(r[25]), "=r"(r[26]), "=r"(r[27]), "=r"(r[28]), "=r"(r[29]), "=r"(r[30]), "=r"(r[31])
        : "r"(addr));
}
// SW128 K-major descriptor base (LBO=1, SBO=64, version=1, layout SW128)
__device__ __forceinline__ uint64_t mk_desc(uint32_t addr) {
    const uint64_t DBASE = (2ULL << 61) | (1ULL << 46) | (64ULL << 32) | (1ULL << 16);
    return DBASE | (uint64_t)((addr >> 4) & 0x3FFF);
}
#endif  // HAS_TC

#if !HAS_TC
// ---------------- fallback-path helpers (mma.sync) ----------------
__device__ __forceinline__ void ldsm4(uint32_t* r, uint32_t addr) {
    asm volatile("ldmatrix.sync.aligned.m8n8.x4.shared.b16 {%0,%1,%2,%3}, [%4];\n"
                 : "=r"(r[0]), "=r"(r[1]), "=r"(r[2]), "=r"(r[3]) : "r"(addr));
}
__device__ __forceinline__ void ldsm4t(uint32_t* r, uint32_t addr) {
    asm volatile("ldmatrix.sync.aligned.m8n8.x4.trans.shared.b16 {%0,%1,%2,%3}, [%4];\n"
                 : "=r"(r[0]), "=r"(r[1]), "=r"(r[2]), "=r"(r[3]) : "r"(addr));
}
__device__ __forceinline__ void mma16816(float* c, const uint32_t* a, const uint32_t* b) {
    asm volatile(
        "mma.sync.aligned.m16n8k16.row.col.f32.bf16.bf16.f32 "
        "{%0,%1,%2,%3}, {%4,%5,%6,%7}, {%8,%9}, {%0,%1,%2,%3};\n"
        : "+f"(c[0]), "+f"(c[1]), "+f"(c[2]), "+f"(c[3])
        : "r"(a[0]), "r"(a[1]), "r"(a[2]), "r"(a[3]), "r"(b[0]), "r"(b[1]));
}
#endif  // !HAS_TC

// ---------------- kernel: gating (warp per token) ----------------
__global__ __launch_bounds__(256) void gate_kernel(const float* __restrict__ x,
                                                   const float* __restrict__ gw) {
    const int wid = threadIdx.x >> 5, lane = threadIdx.x & 31;
    const int tk = blockIdx.x * 8 + wid;
    const float* xr = x + (size_t)tk * DM;

    float p[NE];
#pragma unroll
    for (int e = 0; e < NE; ++e) p[e] = 0.f;
#pragma unroll 8
    for (int j = 0; j < 32; ++j) {
        const int i = j * 32 + lane;
        const float v = xr[i];
#pragma unroll
        for (int e = 0; e < NE; ++e) p[e] += v * gw[e * DM + i];
    }
#pragma unroll
    for (int e = 0; e < NE; ++e)
#pragma unroll
        for (int o = 16; o > 0; o >>= 1) p[e] += __shfl_xor_sync(0xffffffffu, p[e], o);

    if (lane == 0) {
        float m = p[0];
#pragma unroll
        for (int e = 1; e < NE; ++e) m = fmaxf(m, p[e]);
        float ex[NE], S = 0.f;
#pragma unroll
        for (int e = 0; e < NE; ++e) { ex[e] = expf(p[e] - m); S += ex[e]; }
        int i0 = 0;
#pragma unroll
        for (int e = 1; e < NE; ++e) if (ex[e] > ex[i0]) i0 = e;
        int i1 = (i0 == 0) ? 1 : 0;
#pragma unroll
        for (int e = 0; e < NE; ++e) if (e != i0 && ex[e] > ex[i1]) i1 = e;
        float p0 = ex[i0] / S, p1 = ex[i1] / S;
        float den = p0 + p1 + 1e-9f;
        g_pair_e[2 * tk] = i0;     g_pair_w[2 * tk] = p0 / den;
        g_pair_e[2 * tk + 1] = i1; g_pair_w[2 * tk + 1] = p1 / den;
    }
}

// ---------------- kernel: counting sort via warp shfl scan (1024 threads, 2 barriers) ----------------
__global__ __launch_bounds__(1024) void sortscan_kernel() {
    __shared__ int wsum[32][NE];    // warp totals -> warp inclusive prefixes
    const int t = threadIdx.x;
    const int w = t >> 5, lane = t & 31;

    int lc[NE];
#pragma unroll
    for (int e = 0; e < NE; ++e) lc[e] = 0;
    int le[16];
#pragma unroll
    for (int i = 0; i < 16; ++i) {
        const int e = g_pair_e[t + i * 1024];
        le[i] = e;
        lc[e]++;
    }

    // warp-level inclusive scan of the 8-vector
    int sc[NE];
#pragma unroll
    for (int e = 0; e < NE; ++e) sc[e] = lc[e];
#pragma unroll
    for (int o = 1; o < 32; o <<= 1) {
#pragma unroll
        for (int e = 0; e < NE; ++e) {
            const int v = __shfl_up_sync(0xffffffffu, sc[e], o);
            if (lane >= o) sc[e] += v;
        }
    }
    if (lane == 31) {
#pragma unroll
        for (int e = 0; e < NE; ++e) wsum[w][e] = sc[e];
    }
    __syncthreads();

    // warp 0: inclusive scan over the 32 warp totals
    if (w == 0) {
        int v[NE];
#pragma unroll
        for (int e = 0; e < NE; ++e) v[e] = wsum[lane][e];
#pragma unroll
        for (int o = 1; o < 32; o <<= 1) {
#pragma unroll
            for (int e = 0; e < NE; ++e) {
                const int u = __shfl_up_sync(0xffffffffu, v[e], o);
                if (lane >= o) v[e] += u;
            }
        }
#pragma unroll
        for (int e = 0; e < NE; ++e) wsum[lane][e] = v[e];
    }
    __syncthreads();

    // totals + expert offsets (computed redundantly per thread; no extra barrier)
    int off[NE];
    {
        int run = 0;
#pragma unroll
        for (int e = 0; e < NE; ++e) { off[e] = run; run += wsum[31][e]; }
    }
    if (t == 0) {
        int nt = 0;
#pragma unroll
        for (int e = 0; e < NE; ++e) {
            const int c = wsum[31][e];
            g_counts[e] = c;
            g_off[e] = off[e];
            const int tiles = (c + 255) >> 8;
            for (int i = 0; i < tiles; ++i) {
                g_tile_e[nt] = e;
                g_tile_r0[nt] = off[e] + i * 256;
                int v = c - i * 256;
                g_tile_valid[nt] = v > 256 ? 256 : v;
                ++nt;
            }
        }
        g_off[NE] = PAIRS;
        g_num_tiles = nt;
    }

    // exclusive rank = expert offset + prev-warps total + warp-exclusive
    int run[NE];
#pragma unroll
    for (int e = 0; e < NE; ++e) {
        const int wprev = (w > 0) ? wsum[w - 1][e] : 0;
        run[e] = off[e] + wprev + sc[e] - lc[e];
    }
#pragma unroll
    for (int i = 0; i < 16; ++i) {
        const int p = t + i * 1024;
        const int e = le[i];
        const int slot = run[e]++;
        g_pair_slot[p] = slot;
        g_rows_token[slot] = p >> 1;
    }
}

// ---------------- kernel: A-gather (slot-ordered hi/lo split of x) ----------------
__global__ __launch_bounds__(256) void gather_kernel(const float* __restrict__ x) {
    const int b = blockIdx.y * 64 + blockIdx.x;
    const int t = threadIdx.x;
    for (int rr = 0; rr < 16; ++rr) {
        const int slot = b * 16 + rr;
        const int tok = g_rows_token[slot];
        const float4 v = reinterpret_cast<const float4*>(x + (size_t)tok * DM)[t];
        __nv_bfloat16 h0 = __float2bfloat16_rn(v.x), h1 = __float2bfloat16_rn(v.y);
        __nv_bfloat16 h2 = __float2bfloat16_rn(v.z), h3 = __float2bfloat16_rn(v.w);
        __nv_bfloat16 l0 = __float2bfloat16_rn(v.x - __bfloat162float(h0));
        __nv_bfloat16 l1 = __float2bfloat16_rn(v.y - __bfloat162float(h1));
        __nv_bfloat16 l2 = __float2bfloat16_rn(v.z - __bfloat162float(h2));
        __nv_bfloat16 l3 = __float2bfloat16_rn(v.w - __bfloat162float(h3));
        reinterpret_cast<uint2*>(g_Ah + (size_t)slot * DM)[t] =
            make_uint2(pack_bf16(h0, h1), pack_bf16(h2, h3));
        reinterpret_cast<uint2*>(g_Al + (size_t)slot * DM)[t] =
            make_uint2(pack_bf16(l0, l1), pack_bf16(l2, l3));
    }
}

// ---------------- kernel: weight split + transpose (tc path only; side stream) ----------------
__global__ __launch_bounds__(256) void wsplit_kernel(const float* __restrict__ W,
                                                     __nv_bfloat16* __restrict__ Wh,
                                                     __nv_bfloat16* __restrict__ Wl,
                                                     int K, int N) {
#if HAS_TC
    __shared__ float tile[64][65];
    const int e = blockIdx.z;
    const int K0 = blockIdx.x * 64, N0 = blockIdx.y * 64;
    const float* src = W + ((size_t)e * K + K0) * N + N0;
    const int t = threadIdx.x;
    const int r = t >> 4, c4 = (t & 15) * 4;
#pragma unroll
    for (int j = 0; j < 4; ++j) {
        int rr = r + j * 16;
        const float4 v = *reinterpret_cast<const float4*>(src + (size_t)rr * N + c4);
        tile[rr][c4 + 0] = v.x; tile[rr][c4 + 1] = v.y;
        tile[rr][c4 + 2] = v.z; tile[rr][c4 + 3] = v.w;
    }
    __syncthreads();
#pragma unroll
    for (int j = 0; j < 4; ++j) {
        int nn = r + j * 16;
        float v0 = tile[c4 + 0][nn], v1 = tile[c4 + 1][nn];
        float v2 = tile[c4 + 2][nn], v3 = tile[c4 + 3][nn];
        __nv_bfloat16 h0 = __float2bfloat16_rn(v0), h1 = __float2bfloat16_rn(v1);
        __nv_bfloat16 h2 = __float2bfloat16_rn(v2), h3 = __float2bfloat16_rn(v3);
        __nv_bfloat16 l0 = __float2bfloat16_rn(v0 - __bfloat162float(h0));
        __nv_bfloat16 l1 = __float2bfloat16_rn(v1 - __bfloat162float(h1));
        __nv_bfloat16 l2 = __float2bfloat16_rn(v2 - __bfloat162float(h2));
        __nv_bfloat16 l3 = __float2bfloat16_rn(v3 - __bfloat162float(h3));
        size_t out = ((size_t)e * N + N0 + nn) * K + K0 + c4;
        *reinterpret_cast<uint2*>(Wh + out) = make_uint2(pack_bf16(h0, h1), pack_bf16(h2, h3));
        *reinterpret_cast<uint2*>(Wl + out) = make_uint2(pack_bf16(l0, l1), pack_bf16(l2, l3));
    }
#endif
}

// ---------------- kernel: post-GEMM1 GELU + hi/lo split (half-row per block) ----------------
__global__ __launch_bounds__(256) void postgelu_kernel(int colbase) {
    const size_t base = (size_t)blockIdx.x * DF + colbase;
    const int t = threadIdx.x;
#pragma unroll
    for (int j = 0; j < 2; ++j) {
        const int i = (j * 256 + t) * 4;
        const float4 v = *reinterpret_cast<const float4*>(g_Hf + base + i);
        float a0 = gelu_exact(v.x);
        float a1 = gelu_exact(v.y);
        float a2 = gelu_exact(v.z);
        float a3 = gelu_exact(v.w);
        __nv_bfloat16 h0 = __float2bfloat16_rn(a0), h1 = __float2bfloat16_rn(a1);
        __nv_bfloat16 h2 = __float2bfloat16_rn(a2), h3 = __float2bfloat16_rn(a3);
        __nv_bfloat16 l0 = __float2bfloat16_rn(a0 - __bfloat162float(h0));
        __nv_bfloat16 l1 = __float2bfloat16_rn(a1 - __bfloat162float(h1));
        __nv_bfloat16 l2 = __float2bfloat16_rn(a2 - __bfloat162float(h2));
        __nv_bfloat16 l3 = __float2bfloat16_rn(a3 - __bfloat162float(h3));
        *reinterpret_cast<uint2*>(g_Hh + base + i) = make_uint2(pack_bf16(h0, h1), pack_bf16(h2, h3));
        *reinterpret_cast<uint2*>(g_Hl + base + i) = make_uint2(pack_bf16(l0, l1), pack_bf16(l2, l3));
    }
}

// ---------------- tcgen05 cg2 GEMM: persistent clusters, double-buffered TMEM D ----------------
#define BUF_STRIDE 65536
#define OFF_AL 16384
#define OFF_BH 32768
#define OFF_BL 49152
#define OFF_TMEM 196608
#define OFF_MBAR 196624
#define SMEM_DYN 198656
#define STAGE_BYTES 65536u
// mbar layout: full[0..2]@+0,8,16 ; empty[0..2]@+24,32,40 ; done[0..1]@+48,56 ; free[0..1]@+64,72

#define GEMM_IDESC2 ((1u << 4) | (1u << 7) | (1u << 10) | ((256u / 8) << 17) | ((256u / 16) << 24))

// nofs = N-tile window offset, nlg = log2(window N-tile count)
template <bool FIRST>
__global__ __launch_bounds__(256)
void moe_gemm_tc(const __grid_constant__ CUtensorMap tmAh,
                 const __grid_constant__ CUtensorMap tmAl,
                 const __grid_constant__ CUtensorMap tmBh,
                 const __grid_constant__ CUtensorMap tmBl,
                 const float* __restrict__ bias, int nofs, int nlg) {
#if HAS_TC
    constexpr int KTOT = FIRST ? DM : DF;
    constexpr int NTOT = FIRST ? DF : DM;
    constexpr int NC = KTOT / 64;

    const int cid = blockIdx.y;
    const int rank = blockIdx.x & 1;
    const int nmsk = (1 << nlg) - 1;
    const int tot = g_num_tiles << nlg;

    extern __shared__ char dyn[];
    const uint32_t raw = smaddr(dyn);
    const uint32_t sbase = (raw + 1023u) & ~1023u;
    const int t = threadIdx.x;
    const int w = t >> 5, lane = t & 31;

    if (w == 0) {
        tc_alloc2(sbase + OFF_TMEM, 512);
        tc_relinq2();
    }
    if (t == 0) {
#pragma unroll
        for (int s = 0; s < 8; ++s) mbar_init(sbase + OFF_MBAR + s * 8, 1);
        mbar_init(sbase + OFF_MBAR + 64, 2);
        mbar_init(sbase + OFF_MBAR + 72, 2);
    }
    __syncthreads();
    cluster_sync_();

    uint32_t tmem;
    asm volatile("ld.shared.b32 %0, [%1];" : "=r"(tmem) : "r"(sbase + OFF_TMEM));

    const uint32_t mbF = sbase + OFF_MBAR;
    const uint32_t mbE = sbase + OFF_MBAR + 24;
    const uint32_t mbD = sbase + OFF_MBAR + 48;
    const uint32_t mbR = sbase + OFF_MBAR + 64;

    if (w == 0 && elect_one()) {
        // ================= producer: continuous TMA across tiles =================
        uint32_t pE = 0, pDp = 0;
        int s = 0;
#pragma unroll 1
        for (int tt = 0;; ++tt) {
            const int T = cid + tt * NCLUST;
            if (T >= tot) break;
            const int rt = T >> nlg, nt = (T & nmsk) + nofs;
            const int e = g_tile_e[rt];
            const int arow = g_tile_r0[rt] + rank * 128;
            const int bcol = nt * 256 + rank * 128;
#pragma unroll 1
            for (int i = 0; i < NC; ++i, ++s) {
                const int b = s % 3;
                if (s >= 3) {
                    const int sp_ = s - 3;
                    if ((sp_ % NC) == NC - 1) {
                        const int d = (sp_ / NC) & 1;
                        mbar_wait(mbD + d * 8, (pDp >> d) & 1u); pDp ^= 1u << d;
                    } else {
                        mbar_wait(mbE + b * 8, (pE >> b) & 1u); pE ^= 1u << b;
                    }
                }
                if (rank == 0) mbar_expect(mbF + b * 8, 2u * STAGE_BYTES);
                const uint32_t bb = sbase + (uint32_t)b * BUF_STRIDE;
                const int k0 = i * 64;
                tma2d_cg2(bb,          (const void*)&tmAh, k0, arow, mbF + b * 8);
                tma2d_cg2(bb + OFF_AL, (const void*)&tmAl, k0, arow, mbF + b * 8);
                tma3d_cg2(bb + OFF_BH, (const void*)&tmBh, k0, bcol, e, mbF + b * 8);
                tma3d_cg2(bb + OFF_BL, (const void*)&tmBl, k0, bcol, e, mbF + b * 8);
            }
        }
    } else if (w == 1 && rank == 0 && elect_one()) {
        // ================= consumer: MMA =================
        uint64_t dA[3], dAl_[3], dB[3], dBl_[3];
#pragma unroll
        for (int s2 = 0; s2 < 3; ++s2) {
            uint32_t b = sbase + s2 * BUF_STRIDE;
            dA[s2]   = mk_desc(b);
            dAl_[s2] = mk_desc(b + OFF_AL);
            dB[s2]   = mk_desc(b + OFF_BH);
            dBl_[s2] = mk_desc(b + OFF_BL);
        }
        uint32_t pF = 0, pFree = 0;
        int s = 0, ttn = 0;
#pragma unroll 1
        for (int tt = 0;; ++tt) {
            const int T = cid + tt * NCLUST;
            if (T >= tot) break;
            ttn = tt + 1;
            const int d = tt & 1;
            if (tt >= 2) {
                mbar_wait(mbR + d * 8, (pFree >> d) & 1u); pFree ^= 1u << d;
                tc_fence_after();
            }
            const uint32_t dtm = tmem + d * 256;
#pragma unroll 1
            for (int i = 0; i < NC; ++i, ++s) {
                const int b = s % 3;
                mbar_wait(mbF + b * 8, (pF >> b) & 1u); pF ^= 1u << b;
#pragma unroll
                for (int ks = 0; ks < 4; ++ks) {
                    const uint64_t oa = (uint64_t)(ks * 2);
                    const uint32_t en0 = (i == 0 && ks == 0) ? 0u : 1u;
                    tc_mma_f16_ss2(dtm, dA[b] + oa,   dB[b] + oa,   GEMM_IDESC2, en0);
                    tc_mma_f16_ss2(dtm, dA[b] + oa,   dBl_[b] + oa, GEMM_IDESC2, 1u);
                    tc_mma_f16_ss2(dtm, dAl_[b] + oa, dB[b] + oa,   GEMM_IDESC2, 1u);
                }
                tc_commit_mc2((i == NC - 1) ? (mbD + d * 8) : (mbE + b * 8));
            }
        }
#pragma unroll 1
        for (int k = (ttn >= 2 ? ttn - 2 : 0); k < ttn; ++k) {
            const int d = k & 1;
            mbar_wait(mbR + d * 8, (pFree >> d) & 1u); pFree ^= 1u << d;
        }
    } else if (w >= 2) {
        // ================= epilogue: warps 2..7 (raw fp32 + bias only) =================
        const int sp_ = w & 3;
        const int rloc = sp_ * 32 + lane;
        int cstart, cnum;
        if (w == 4 || w == 5)      { cstart = 0;   cnum = 8; }
        else if (w == 2 || w == 3) { cstart = 0;   cnum = 4; }
        else                       { cstart = 128; cnum = 4; }

        uint32_t pDe = 0;
#pragma unroll 1
        for (int tt = 0;; ++tt) {
            const int T = cid + tt * NCLUST;
            if (T >= tot) break;
            const int d = tt & 1;
            mbar_wait(mbD + d * 8, (pDe >> d) & 1u); pDe ^= 1u << d;
            tc_fence_after();

            const int rt = T >> nlg, nt = (T & nmsk) + nofs;
            const int e = g_tile_e[rt];
            const int row0 = g_tile_r0[rt];
            const int n0 = nt * 256;
            int vr = g_tile_valid[rt] - rank * 128;
            vr = vr < 0 ? 0 : (vr > 128 ? 128 : vr);
            const bool valid = rloc < vr;
            const int rowg = row0 + rank * 128 + rloc;
            const uint32_t dtm = tmem + d * 256;
            const float* bb = bias + (size_t)e * NTOT + n0;
            float* oF = (FIRST ? g_Hf + (size_t)rowg * DF : g_Y + (size_t)rowg * DM) + n0;

#pragma unroll 1
            for (int j = 0; j < cnum; ++j) {
                const int col = cstart + j * 32;
                uint32_t dr[32];
                tc_ld_x32(dr, dtm + col);
                tc_wait_ld();
                if (valid) {
#pragma unroll
                    for (int c = 0; c < 32; c += 4) {
                        float4 o;
                        o.x = __uint_as_float(dr[c + 0]) + bb[col + c + 0];
                        o.y = __uint_as_float(dr[c + 1]) + bb[col + c + 1];
                        o.z = __uint_as_float(dr[c + 2]) + bb[col + c + 2];
                        o.w = __uint_as_float(dr[c + 3]) + bb[col + c + 3];
                        *reinterpret_cast<float4*>(oF + col + c) = o;
                    }
                }
            }
            tc_fence_before();
            asm volatile("bar.sync 1, 192;" ::: "memory");
            if (w == 2 && elect_one()) mbar_arrive_leader(mbR + d * 8);
        }
    }

    __syncthreads();
    if (t == 0) {
#pragma unroll
        for (int s = 0; s < 10; ++s) mbar_inval(sbase + OFF_MBAR + s * 8);
    }
    __syncthreads();
    cluster_sync_();
    if (w == 0) tc_dealloc2(tmem, 512);
    cluster_sync_();
#endif  // HAS_TC
}

// ---------------- fallback GEMM (mma.sync; 256-tiles split in half) ----------------
template <bool FIRST>
__global__ __launch_bounds__(256) void moe_gemm_fb(const float* __restrict__ W,
                                                   const float* __restrict__ bias) {
#if !HAS_TC
    constexpr int KTOT = FIRST ? DM : DF;
    constexpr int LDW  = FIRST ? DF : DM;
    const int tileIdx = blockIdx.y >> 1;
    if (tileIdx >= g_num_tiles) return;
    const int half = blockIdx.y & 1;
    const int e = g_tile_e[tileIdx];
    const int row0 = g_tile_r0[tileIdx] + half * 128;
    int vrows = g_tile_valid[tileIdx] - half * 128;
    vrows = vrows < 0 ? 0 : (vrows > 128 ? 128 : vrows);
    if (vrows == 0) return;
    const int n0 = blockIdx.x * 128;
    const float* Wn = W + (size_t)e * KTOT * LDW + n0;
    const float* bn = bias + (size_t)e * LDW + n0;

    __shared__ __align__(16) __nv_bfloat16 sAh[128 * 40];
    __shared__ __align__(16) __nv_bfloat16 sAl[128 * 40];
    __shared__ __align__(16) __nv_bfloat16 sBh[32 * 136];
    __shared__ __align__(16) __nv_bfloat16 sBl[32 * 136];

    const int t = threadIdx.x;
    float c[4][4][4];
#pragma unroll
    for (int a = 0; a < 4; ++a)
#pragma unroll
        for (int b = 0; b < 4; ++b)
#pragma unroll
            for (int q = 0; q < 4; ++q) c[a][b][q] = 0.f;

    const int lane = t & 31, warp = t >> 5;
    const int wm = warp >> 2, wn = warp & 3;
    const int m0 = wm * 64;
    const int sub = t & 15, rgrp = t >> 4;

    for (int k0 = 0; k0 < KTOT; k0 += 32) {
        __syncthreads();
#pragma unroll
        for (int rr = 0; rr < 8; ++rr) {
            int r = rr * 16 + rgrp;
            int rg = row0 + r; if (rg > PAIRS - 1) rg = PAIRS - 1;
            const uint32_t* ph = reinterpret_cast<const uint32_t*>(
                (FIRST ? g_Ah : g_Hh) + (size_t)rg * KTOT + k0);
            const uint32_t* pl = reinterpret_cast<const uint32_t*>(
                (FIRST ? g_Al : g_Hl) + (size_t)rg * KTOT + k0);
            *reinterpret_cast<uint32_t*>(&sAh[r * 40 + sub * 2]) = ph[sub];
            *reinterpret_cast<uint32_t*>(&sAl[r * 40 + sub * 2]) = pl[sub];
        }
#pragma unroll
        for (int i = 0; i < 4; ++i) {
            int lin = (i * 256 + t) * 4;
            int kr = lin >> 7;
            int nc = lin & 127;
            const float4 v = *reinterpret_cast<const float4*>(Wn + (size_t)(k0 + kr) * LDW + nc);
            __nv_bfloat16 h0 = __float2bfloat16_rn(v.x);
            __nv_bfloat16 h1 = __float2bfloat16_rn(v.y);
            __nv_bfloat16 h2 = __float2bfloat16_rn(v.z);
            __nv_bfloat16 h3 = __float2bfloat16_rn(v.w);
            __nv_bfloat16 l0 = __float2bfloat16_rn(v.x - __bfloat162float(h0));
            __nv_bfloat16 l1 = __float2bfloat16_rn(v.y - __bfloat162float(h1));
            __nv_bfloat16 l2 = __float2bfloat16_rn(v.z - __bfloat162float(h2));
            __nv_bfloat16 l3 = __float2bfloat16_rn(v.w - __bfloat162float(h3));
            *reinterpret_cast<uint2*>(&sBh[kr * 136 + nc]) = make_uint2(pack_bf16(h0, h1), pack_bf16(h2, h3));
            *reinterpret_cast<uint2*>(&sBl[kr * 136 + nc]) = make_uint2(pack_bf16(l0, l1), pack_bf16(l2, l3));
        }
        __syncthreads();

#pragma unroll
        for (int ks = 0; ks < 2; ++ks) {
            uint32_t ah[4][4], al[4][4], bh[4][2], bl[4][2];
            {
                int ar = lane & 15;
                int acol = ks * 16 + (lane >> 4) * 8;
#pragma unroll
                for (int fm = 0; fm < 4; ++fm) {
                    ldsm4(ah[fm], smaddr(&sAh[(m0 + fm * 16 + ar) * 40 + acol]));
                    ldsm4(al[fm], smaddr(&sAl[(m0 + fm * 16 + ar) * 40 + acol]));
                }
                int brow = ks * 16 + (lane & 15);
                int bcol = wn * 32 + (lane >> 4) * 8;
#pragma unroll
                for (int hb = 0; hb < 2; ++hb) {
                    uint32_t r[4];
                    ldsm4t(r, smaddr(&sBh[brow * 136 + bcol + hb * 16]));
                    bh[2 * hb][0] = r[0]; bh[2 * hb][1] = r[1];
                    bh[2 * hb + 1][0] = r[2]; bh[2 * hb + 1][1] = r[3];
                    ldsm4t(r, smaddr(&sBl[brow * 136 + bcol + hb * 16]));
                    bl[2 * hb][0] = r[0]; bl[2 * hb][1] = r[1];
                    bl[2 * hb + 1][0] = r[2]; bl[2 * hb + 1][1] = r[3];
                }
            }
#pragma unroll
            for (int fm = 0; fm < 4; ++fm)
#pragma unroll
                for (int fn = 0; fn < 4; ++fn) {
                    mma16816(c[fm][fn], ah[fm], bh[fn]);
                    mma16816(c[fm][fn], ah[fm], bl[fn]);
                    mma16816(c[fm][fn], al[fm], bh[fn]);
                }
        }
    }

    const int lgrp = lane >> 2, lq = lane & 3;
#pragma unroll
    for (int fm = 0; fm < 4; ++fm) {
        int rl = m0 + fm * 16 + lgrp;
#pragma unroll
        for (int fn = 0; fn < 4; ++fn) {
            int nc = wn * 32 + fn * 8 + lq * 2;
            float bv0 = bn[nc], bv1 = bn[nc + 1];
            float* cc = c[fm][fn];
#pragma unroll
            for (int h = 0; h < 2; ++h) {
                int rloc = rl + h * 8;
                if (rloc < vrows) {
                    int row = row0 + rloc;
                    float v0 = cc[h * 2 + 0] + bv0;
                    float v1 = cc[h * 2 + 1] + bv1;
                    if (FIRST) {
                        *reinterpret_cast<float2*>(&g_Hf[(size_t)row * DF + n0 + nc]) = make_float2(v0, v1);
                    } else {
                        *reinterpret_cast<float2*>(&g_Y[(size_t)row * DM + n0 + nc]) = make_float2(v0, v1);
                    }
                }
            }
        }
    }
#endif  // !HAS_TC
}

// ---------------- kernel: weighted combine ----------------
__global__ __launch_bounds__(256) void combine_kernel(float* __restrict__ out) {
    const int tk = blockIdx.x;
    const int d = threadIdx.x * 4;
    int s0 = g_pair_slot[2 * tk], s1 = g_pair_slot[2 * tk + 1];
    float w0 = g_pair_w[2 * tk], w1 = g_pair_w[2 * tk + 1];
    const float4 a = *reinterpret_cast<const float4*>(&g_Y[(size_t)s0 * DM + d]);
    const float4 b = *reinterpret_cast<const float4*>(&g_Y[(size_t)s1 * DM + d]);
    float4 o;
    o.x = w0 * a.x + w1 * b.x;
    o.y = w0 * a.y + w1 * b.y;
    o.z = w0 * a.z + w1 * b.z;
    o.w = w0 * a.w + w1 * b.w;
    *reinterpret_cast<float4*>(&out[(size_t)tk * DM + d]) = o;
}

// ---------------- host: tensor map construction ----------------
typedef CUresult (*TmEncodeFn)(CUtensorMap*, CUtensorMapDataType, cuuint32_t, void*,
                               const cuuint64_t*, const cuuint64_t*, const cuuint32_t*,
                               const cuuint32_t*, CUtensorMapInterleave, CUtensorMapSwizzle,
                               CUtensorMapL2promotion, CUtensorMapFloatOOBfill);

static void tm2d(TmEncodeFn enc, CUtensorMap* tm, void* base, unsigned long long K,
                 unsigned long long R) {
    cuuint64_t dims[2] = {K, R};
    cuuint64_t st[1] = {K * 2};
    cuuint32_t box[2] = {64, 128};
    cuuint32_t es[2] = {1, 1};
    enc(tm, CU_TENSOR_MAP_DATA_TYPE_BFLOAT16, 2, base, dims, st, box, es,
        CU_TENSOR_MAP_INTERLEAVE_NONE, CU_TENSOR_MAP_SWIZZLE_128B,
        CU_TENSOR_MAP_L2_PROMOTION_L2_128B, CU_TENSOR_MAP_FLOAT_OOB_FILL_NONE);
}
static void tm3d(TmEncodeFn enc, CUtensorMap* tm, void* base, unsigned long long K,
                 unsigned long long N) {
    cuuint64_t dims[3] = {K, N, NE};
    cuuint64_t st[2] = {K * 2, N * K * 2};
    cuuint32_t box[3] = {64, 128, 1};
    cuuint32_t es[3] = {1, 1, 1};
    enc(tm, CU_TENSOR_MAP_DATA_TYPE_BFLOAT16, 3, base, dims, st, box, es,
        CU_TENSOR_MAP_INTERLEAVE_NONE, CU_TENSOR_MAP_SWIZZLE_128B,
        CU_TENSOR_MAP_L2_PROMOTION_L2_128B, CU_TENSOR_MAP_FLOAT_OOB_FILL_NONE);
}

// ---------------- launch ----------------
extern "C" void kernel_launch(void* const* d_in, const int* in_sizes, int n_in,
                              void* d_out, int out_size) {
    const float* x  = (const float*)d_in[0];
    const float* gw = (const float*)d_in[1];
    const float* w1 = (const float*)d_in[2];
    const float* b1 = (const float*)d_in[3];
    const float* w2 = (const float*)d_in[4];
    const float* b2 = (const float*)d_in[5];
    float* out = (float*)d_out;

    cudaFuncSetAttribute(moe_gemm_tc<true>,  cudaFuncAttributeMaxDynamicSharedMemorySize, SMEM_DYN);
    cudaFuncSetAttribute(moe_gemm_tc<false>, cudaFuncAttributeMaxDynamicSharedMemorySize, SMEM_DYN);

    void *pAh, *pAl, *pHh, *pHl, *pW1h, *pW1l, *pW2h, *pW2l;
    cudaGetSymbolAddress(&pAh, g_Ah);
    cudaGetSymbolAddress(&pAl, g_Al);
    cudaGetSymbolAddress(&pHh, g_Hh);
    cudaGetSymbolAddress(&pHl, g_Hl);
    cudaGetSymbolAddress(&pW1h, g_w1h);
    cudaGetSymbolAddress(&pW1l, g_w1l);
    cudaGetSymbolAddress(&pW2h, g_w2h);
    cudaGetSymbolAddress(&pW2l, g_w2l);

    void* sym = nullptr;
    cudaDriverEntryPointQueryResult qr;
    cudaGetDriverEntryPoint("cuTensorMapEncodeTiled", &sym, cudaEnableDefault, &qr);
    TmEncodeFn enc = (TmEncodeFn)sym;

    CUtensorMap tAh, tAl, tB1h, tB1l, tHh, tHl, tB2h, tB2l;
    if (enc) {
        tm2d(enc, &tAh, pAh, DM, PAIRS);
        tm2d(enc, &tAl, pAl, DM, PAIRS);
        tm3d(enc, &tB1h, pW1h, DM, DF);
        tm3d(enc, &tB1l, pW1l, DM, DF);
        tm2d(enc, &tHh, pHh, DF, PAIRS);
        tm2d(enc, &tHl, pHl, DF, PAIRS);
        tm3d(enc, &tB2h, pW2h, DF, DM);
        tm3d(enc, &tB2l, pW2l, DF, DM);
    }

    // side stream + events (lazily created once; control-flow resources only)
    static cudaStream_t sSide = nullptr;
    static cudaEvent_t evFork = nullptr, evW1 = nullptr, evW2 = nullptr, evG1a = nullptr, evPa = nullptr;
    if (!sSide) {
        cudaStreamCreateWithFlags(&sSide, cudaStreamNonBlocking);
        cudaEventCreateWithFlags(&evFork, cudaEventDisableTiming);
        cudaEventCreateWithFlags(&evW1, cudaEventDisableTiming);
        cudaEventCreateWithFlags(&evW2, cudaEventDisableTiming);
        cudaEventCreateWithFlags(&evG1a, cudaEventDisableTiming);
        cudaEventCreateWithFlags(&evPa, cudaEventDisableTiming);
    }

    // fork: weight split runs on side stream, independent of routing
    cudaEventRecord(evFork, 0);
    cudaStreamWaitEvent(sSide, evFork, 0);
    wsplit_kernel<<<dim3(DM / 64, DF / 64, NE), 256, 0, sSide>>>(w1, (__nv_bfloat16*)pW1h, (__nv_bfloat16*)pW1l, DM, DF);
    cudaEventRecord(evW1, sSide);
    wsplit_kernel<<<dim3(DF / 64, DM / 64, NE), 256, 0, sSide>>>(w2, (__nv_bfloat16*)pW2h, (__nv_bfloat16*)pW2l, DF, DM);
    cudaEventRecord(evW2, sSide);

    // main stream: routing + gather
    gate_kernel<<<T_TOKENS / 8, 256>>>(x, gw);
    sortscan_kernel<<<1, 1024>>>();
    gather_kernel<<<dim3(64, 16), 256>>>(x);

    cudaLaunchAttribute cat[1];
    cat[0].id = cudaLaunchAttributeClusterDimension;
    cat[0].val.clusterDim.x = 2;
    cat[0].val.clusterDim.y = 1;
    cat[0].val.clusterDim.z = 1;

    cudaStreamWaitEvent(0, evW1, 0);  // join w1 split
    {
        // GEMM1 first N-half (columns 0..2047)
        cudaLaunchConfig_t cfg = {};
        cfg.gridDim = dim3(2, NCLUST, 1);
        cfg.blockDim = dim3(256, 1, 1);
        cfg.dynamicSmemBytes = SMEM_DYN;
        cfg.stream = 0;
        cfg.attrs = cat;
        cfg.numAttrs = 1;
        cudaLaunchKernelEx(&cfg, moe_gemm_tc<true>, tAh, tAl, tB1h, tB1l, b1, 0, 3);
    }
    moe_gemm_fb<true><<<dim3(DF / 128, MAXT2 * 2), 256>>>(w1, b1);   // no-op on tc build (full GEMM1 on fallback)
    cudaEventRecord(evG1a, 0);
    {
        // GEMM1 second N-half (columns 2048..4095)
        cudaLaunchConfig_t cfg = {};
        cfg.gridDim = dim3(2, NCLUST, 1);
        cfg.blockDim = dim3(256, 1, 1);
        cfg.dynamicSmemBytes = SMEM_DYN;
        cfg.stream = 0;
        cfg.attrs = cat;
        cfg.numAttrs = 1;
        cudaLaunchKernelEx(&cfg, moe_gemm_tc<true>, tAh, tAl, tB1h, tB1l, b1, 8, 3);
    }
    // side: postgelu on first half, overlapping GEMM1 second half
    cudaStreamWaitEvent(sSide, evG1a, 0);
    postgelu_kernel<<<PAIRS, 256, 0, sSide>>>(0);
    cudaEventRecord(evPa, sSide);
    // main: postgelu on second half
    postgelu_kernel<<<PAIRS, 256>>>(2048);
    cudaStreamWaitEvent(0, evPa, 0);
    cudaStreamWaitEvent(0, evW2, 0);  // join w2 split
    {
        cudaLaunchConfig_t cfg = {};
        cfg.gridDim = dim3(2, NCLUST, 1);
        cfg.blockDim = dim3(256, 1, 1);
        cfg.dynamicSmemBytes = SMEM_DYN;
        cfg.stream = 0;
        cfg.attrs = cat;
        cfg.numAttrs = 1;
        cudaLaunchKernelEx(&cfg, moe_gemm_tc<false>, tHh, tHl, tB2h, tB2l, b2, 0, 2);
    }
    moe_gemm_fb<false><<<dim3(DM / 128, MAXT2 * 2), 256>>>(w2, b2);  // no-op on tc build
    combine_kernel<<<T_TOKENS, 256>>>(out);
}

// round 15
// speedup vs baseline: 1.7013x; 1.0175x over previous
#include <cuda_runtime.h>
#include <cuda.h>
#include <cuda_bf16.h>
#include <stdint.h>

#define T_TOKENS 8192
#define DM 1024
#define DF 4096
#define NE 8
#define PAIRS 16384
#define MAXTILES 144
#define MAXT2 72
#define NCLUST 74

// tcgen05 availability: only in the arch-SPECIFIC device pass (sm_103a / sm_100a).
#if defined(__CUDA_ARCH__) && (defined(__CUDA_ARCH_FEAT_SM103_ALL) || defined(__CUDA_ARCH_FEAT_SM100_ALL) || defined(__CUDA_ARCH_SPECIFIC__))
#define HAS_TC 1
#else
#define HAS_TC 0
#endif

// ---------------- scratch (device globals; no allocations) ----------------
__device__ __align__(128) __nv_bfloat16 g_Ah[(size_t)PAIRS * DM];
__device__ __align__(128) __nv_bfloat16 g_Al[(size_t)PAIRS * DM];
__device__ __align__(128) float         g_Hf[(size_t)PAIRS * DF];   // raw GEMM1 out (bias added)
__device__ __align__(128) __nv_bfloat16 g_Hh[(size_t)PAIRS * DF];
__device__ __align__(128) __nv_bfloat16 g_Hl[(size_t)PAIRS * DF];
__device__ __align__(128) float         g_Y[(size_t)PAIRS * DM];

__device__ __align__(128) __nv_bfloat16 g_w1h[(size_t)NE * DM * DF];
__device__ __align__(128) __nv_bfloat16 g_w1l[(size_t)NE * DM * DF];
__device__ __align__(128) __nv_bfloat16 g_w2h[(size_t)NE * DF * DM];
__device__ __align__(128) __nv_bfloat16 g_w2l[(size_t)NE * DF * DM];

__device__ int   g_pair_e[PAIRS];
__device__ float g_pair_w[PAIRS];
__device__ int   g_pair_slot[PAIRS];

__device__ int g_counts[NE];
__device__ int g_cursor[NE];
__device__ int g_off[NE + 1];
__device__ int g_tile_e[MAXTILES];
__device__ int g_tile_r0[MAXTILES];
__device__ int g_tile_valid[MAXTILES];
__device__ int g_num_tiles;

// ---------------- shared helpers ----------------
__device__ __forceinline__ uint32_t smaddr(const void* p) {
    return (uint32_t)__cvta_generic_to_shared(p);
}
__device__ __forceinline__ uint32_t pack_bf16(__nv_bfloat16 a, __nv_bfloat16 b) {
    return (uint32_t)__bfloat16_as_ushort(a) | ((uint32_t)__bfloat16_as_ushort(b) << 16);
}
__device__ __forceinline__ float gelu_exact(float v) {
    return 0.5f * v * (1.0f + erff(v * 0.70710678118654752f));
}

#if HAS_TC
// ---------------- tcgen05 / cg2 helpers ----------------
__device__ __forceinline__ uint32_t elect_one() {
    uint32_t pred;
    asm volatile("{\n\t.reg .pred p;\n\telect.sync _|p, 0xFFFFFFFF;\n\tselp.b32 %0, 1, 0, p;\n\t}"
                 : "=r"(pred));
    return pred;
}
__device__ __forceinline__ void cluster_sync_() {
    asm volatile("barrier.cluster.arrive.aligned;" ::: "memory");
    asm volatile("barrier.cluster.wait.aligned;" ::: "memory");
}
__device__ __forceinline__ void mbar_init(uint32_t addr, uint32_t cnt) {
    asm volatile("mbarrier.init.shared.b64 [%0], %1;" :: "r"(addr), "r"(cnt) : "memory");
}
__device__ __forceinline__ void mbar_inval(uint32_t addr) {
    asm volatile("mbarrier.inval.shared.b64 [%0];" :: "r"(addr) : "memory");
}
__device__ __forceinline__ void mbar_expect(uint32_t addr, uint32_t bytes) {
    asm volatile("mbarrier.arrive.expect_tx.shared.b64 _, [%0], %1;"
                 :: "r"(addr), "r"(bytes) : "memory");
}
__device__ __forceinline__ void mbar_wait(uint32_t addr, uint32_t parity) {
    asm volatile(
        "{\n\t.reg .pred P1;\n"
        "WAIT_%=:\n\t"
        "mbarrier.try_wait.parity.acquire.cta.shared::cta.b64 P1, [%0], %1, 0x989680;\n\t"
        "@P1 bra.uni DONE_%=;\n\t"
        "bra.uni WAIT_%=;\n"
        "DONE_%=:\n\t}"
        :: "r"(addr), "r"(parity) : "memory");
}
// arrive on rank0's mbarrier (cg2 leader: clear bit 24)
__device__ __forceinline__ void mbar_arrive_leader(uint32_t addr) {
    asm volatile(
        "{\n\t.reg .b32 la;\n\t"
        "and.b32 la, %0, 0xFEFFFFFF;\n\t"
        "mbarrier.arrive.shared::cluster.b64 _, [la];\n\t}"
        :: "r"(addr) : "memory");
}
__device__ __forceinline__ void tma2d_cg2(uint32_t dst, const void* tm, int x, int y, uint32_t mbar) {
    asm volatile(
        "{\n\t.reg .b32 lb;\n\t"
        "and.b32 lb, %4, 0xFEFFFFFF;\n\t"
        "cp.async.bulk.tensor.2d.cta_group::2.shared::cluster.global.tile.mbarrier::complete_tx::bytes "
        "[%0], [%1, {%2, %3}], [lb];\n\t}"
        :: "r"(dst), "l"(tm), "r"(x), "r"(y), "r"(mbar) : "memory");
}
__device__ __forceinline__ void tma3d_cg2(uint32_t dst, const void* tm, int x, int y, int z, uint32_t mbar) {
    asm volatile(
        "{\n\t.reg .b32 lb;\n\t"
        "and.b32 lb, %5, 0xFEFFFFFF;\n\t"
        "cp.async.bulk.tensor.3d.cta_group::2.shared::cluster.global.tile.mbarrier::complete_tx::bytes "
        "[%0], [%1, {%2, %3, %4}], [lb];\n\t}"
        :: "r"(dst), "l"(tm), "r"(x), "r"(y), "r"(z), "r"(mbar) : "memory");
}
__device__ __forceinline__ void tc_mma_f16_ss2(uint32_t d, uint64_t a, uint64_t b,
                                               uint32_t idesc, uint32_t en) {
    asm volatile(
        "{\n\t.reg .pred p;\n\tsetp.ne.u32 p, %5, 0;\n\t"
        "tcgen05.mma.cta_group::2.kind::f16 [%0], %1, %2, %3, "
        "{%4, %4, %4, %4, %4, %4, %4, %4}, p;\n\t}"
        :: "r"(d), "l"(a), "l"(b), "r"(idesc), "r"(0u), "r"(en) : "memory");
}
__device__ __forceinline__ void tc_commit_mc2(uint32_t mbar) {
    asm volatile(
        "tcgen05.commit.cta_group::2.mbarrier::arrive::one.shared::cluster.multicast::cluster.b64 [%0], %1;"
        :: "r"(mbar), "h"((uint16_t)0x3) : "memory");
}
__device__ __forceinline__ void tc_alloc2(uint32_t smem_slot, uint32_t ncols) {
    asm volatile("tcgen05.alloc.cta_group::2.sync.aligned.shared::cta.b32 [%0], %1;"
                 :: "r"(smem_slot), "r"(ncols) : "memory");
}
__device__ __forceinline__ void tc_dealloc2(uint32_t tmem, uint32_t ncols) {
    asm volatile("tcgen05.dealloc.cta_group::2.sync.aligned.b32 %0, %1;" :: "r"(tmem), "r"(ncols));
}
__device__ __forceinline__ void tc_relinq2() {
    asm volatile("tcgen05.relinquish_alloc_permit.cta_group::2.sync.aligned;");
}
__device__ __forceinline__ void tc_fence_after() {
    asm volatile("tcgen05.fence::after_thread_sync;" ::: "memory");
}
__device__ __forceinline__ void tc_fence_before() {
    asm volatile("tcgen05.fence::before_thread_sync;" ::: "memory");
}
__device__ __forceinline__ void tc_wait_ld() {
    asm volatile("tcgen05.wait::ld.sync.aligned;" ::: "memory");
}
__device__ __forceinline__ void tc_ld_x32(uint32_t* r, uint32_t addr) {
    asm volatile(
        "tcgen05.ld.sync.aligned.32x32b.x32.b32 "
        "{%0, %1, %2, %3, %4, %5, %6, %7, %8, %9, %10, %11, %12, %13, %14, %15, "
        " %16, %17, %18, %19, %20, %21, %22, %23, %24, %25, %26, %27, %28, %29, %30, %31}, [%32];"
        : "=r"(r[0]), "=r"(r[1]), "=r"(r[2]), "=r"(r[3]), "=r"(r[4]), "=r"(r[5]), "=r"(r[6]), "=r"(r[7]),
          "=r"(r[8]), "=r"(r[9]), "=r"(r[10]), "=r"(r[11]), "=r"(r[12]), "=r"(r[13]), "=r"(r[14]), "=r"(r[15]),
          "=r"(r[16]), "=r"(r[17]), "=r"(r[18]), "=r"(r[19]), "=r"(r[20]), "=r"(r[21]), "=r"(r[22]), "=r"(r[23]),
          "=r"(r[24]), "=r"(r[25]), "=r"(r[26]), "=r"(r[27]), "=r"(r[28]), "=r"(r[29]), "=r"(r[30]), "=r"(r[31])
        : "r"(addr));
}
// SW128 K-major descriptor base (LBO=1, SBO=64, version=1, layout SW128)
__device__ __forceinline__ uint64_t mk_desc(uint32_t addr) {
    const uint64_t DBASE = (2ULL << 61) | (1ULL << 46) | (64ULL << 32) | (1ULL << 16);
    return DBASE | (uint64_t)((addr >> 4) & 0x3FFF);
}
#endif  // HAS_TC

#if !HAS_TC
// ---------------- fallback-path helpers (mma.sync) ----------------
__device__ __forceinline__ void ldsm4(uint32_t* r, uint32_t addr) {
    asm volatile("ldmatrix.sync.aligned.m8n8.x4.shared.b16 {%0,%1,%2,%3}, [%4];\n"
                 : "=r"(r[0]), "=r"(r[1]), "=r"(r[2]), "=r"(r[3]) : "r"(addr));
}
__device__ __forceinline__ void ldsm4t(uint32_t* r, uint32_t addr) {
    asm volatile("ldmatrix.sync.aligned.m8n8.x4.trans.shared.b16 {%0,%1,%2,%3}, [%4];\n"
                 : "=r"(r[0]), "=r"(r[1]), "=r"(r[2]), "=r"(r[3]) : "r"(addr));
}
__device__ __forceinline__ void mma16816(float* c, const uint32_t* a, const uint32_t* b) {
    asm volatile(
        "mma.sync.aligned.m16n8k16.row.col.f32.bf16.bf16.f32 "
        "{%0,%1,%2,%3}, {%4,%5,%6,%7}, {%8,%9}, {%0,%1,%2,%3};\n"
        : "+f"(c[0]), "+f"(c[1]), "+f"(c[2]), "+f"(c[3])
        : "r"(a[0]), "r"(a[1]), "r"(a[2]), "r"(a[3]), "r"(b[0]), "r"(b[1]));
}
#endif  // !HAS_TC

// ---------------- kernel: zero routing counters ----------------
__global__ void zero_kernel() {
    const int t = threadIdx.x;
    if (t < NE) { g_counts[t] = 0; g_cursor[t] = 0; }
}

// ---------------- kernel: gating (warp per token; counts via atomics) ----------------
__global__ __launch_bounds__(256) void gate_kernel(const float* __restrict__ x,
                                                   const float* __restrict__ gw) {
    const int wid = threadIdx.x >> 5, lane = threadIdx.x & 31;
    const int tk = blockIdx.x * 8 + wid;
    const float* xr = x + (size_t)tk * DM;

    float p[NE];
#pragma unroll
    for (int e = 0; e < NE; ++e) p[e] = 0.f;
#pragma unroll 8
    for (int j = 0; j < 32; ++j) {
        const int i = j * 32 + lane;
        const float v = xr[i];
#pragma unroll
        for (int e = 0; e < NE; ++e) p[e] += v * gw[e * DM + i];
    }
#pragma unroll
    for (int e = 0; e < NE; ++e)
#pragma unroll
        for (int o = 16; o > 0; o >>= 1) p[e] += __shfl_xor_sync(0xffffffffu, p[e], o);

    if (lane == 0) {
        float m = p[0];
#pragma unroll
        for (int e = 1; e < NE; ++e) m = fmaxf(m, p[e]);
        float ex[NE], S = 0.f;
#pragma unroll
        for (int e = 0; e < NE; ++e) { ex[e] = expf(p[e] - m); S += ex[e]; }
        int i0 = 0;
#pragma unroll
        for (int e = 1; e < NE; ++e) if (ex[e] > ex[i0]) i0 = e;
        int i1 = (i0 == 0) ? 1 : 0;
#pragma unroll
        for (int e = 0; e < NE; ++e) if (e != i0 && ex[e] > ex[i1]) i1 = e;
        float p0 = ex[i0] / S, p1 = ex[i1] / S;
        float den = p0 + p1 + 1e-9f;
        g_pair_e[2 * tk] = i0;     g_pair_w[2 * tk] = p0 / den;
        g_pair_e[2 * tk + 1] = i1; g_pair_w[2 * tk + 1] = p1 / den;
        atomicAdd(&g_counts[i0], 1);
        atomicAdd(&g_counts[i1], 1);
    }
}

// ---------------- kernel: scan + tile map (tiny) ----------------
__global__ void scan_kernel() {
    if (threadIdx.x == 0) {
        int off = 0, nt = 0;
#pragma unroll
        for (int e = 0; e < NE; ++e) {
            const int c = g_counts[e];
            g_off[e] = off;
            const int tiles = (c + 255) >> 8;
            for (int i = 0; i < tiles; ++i) {
                g_tile_e[nt] = e;
                g_tile_r0[nt] = off + i * 256;
                int v = c - i * 256;
                g_tile_valid[nt] = v > 256 ? 256 : v;
                ++nt;
            }
            off += c;
        }
        g_off[NE] = off;
        g_num_tiles = nt;
    }
}

// ---------------- kernel: fused scatter + A-gather ----------------
// Each block: 16 pairs. Slots assigned via atomic cursor; rows copied+split to Ah/Al[slot].
__global__ __launch_bounds__(256) void scattergather_kernel(const float* __restrict__ x) {
    __shared__ int s_slot[16];
    const int b = blockIdx.y * 64 + blockIdx.x;
    const int t = threadIdx.x;
    if (t < 16) {
        const int p = b * 16 + t;
        const int e = g_pair_e[p];
        s_slot[t] = g_off[e] + atomicAdd(&g_cursor[e], 1);
        g_pair_slot[p] = s_slot[t];
    }
    __syncthreads();
    for (int rr = 0; rr < 16; ++rr) {
        const int tok = (b * 16 + rr) >> 1;
        const int slot = s_slot[rr];
        const float4 v = reinterpret_cast<const float4*>(x + (size_t)tok * DM)[t];
        __nv_bfloat16 h0 = __float2bfloat16_rn(v.x), h1 = __float2bfloat16_rn(v.y);
        __nv_bfloat16 h2 = __float2bfloat16_rn(v.z), h3 = __float2bfloat16_rn(v.w);
        __nv_bfloat16 l0 = __float2bfloat16_rn(v.x - __bfloat162float(h0));
        __nv_bfloat16 l1 = __float2bfloat16_rn(v.y - __bfloat162float(h1));
        __nv_bfloat16 l2 = __float2bfloat16_rn(v.z - __bfloat162float(h2));
        __nv_bfloat16 l3 = __float2bfloat16_rn(v.w - __bfloat16_as_ushort(h3) * 0.0f - __bfloat162float(h3));
        reinterpret_cast<uint2*>(g_Ah + (size_t)slot * DM)[t] =
            make_uint2(pack_bf16(h0, h1), pack_bf16(h2, h3));
        reinterpret_cast<uint2*>(g_Al + (size_t)slot * DM)[t] =
            make_uint2(pack_bf16(l0, l1), pack_bf16(l2, l3));
    }
}

// ---------------- kernel: weight split + transpose (tc path only; side stream) ----------------
__global__ __launch_bounds__(256) void wsplit_kernel(const float* __restrict__ W,
                                                     __nv_bfloat16* __restrict__ Wh,
                                                     __nv_bfloat16* __restrict__ Wl,
                                                     int K, int N) {
#if HAS_TC
    __shared__ float tile[64][65];
    const int e = blockIdx.z;
    const int K0 = blockIdx.x * 64, N0 = blockIdx.y * 64;
    const float* src = W + ((size_t)e * K + K0) * N + N0;
    const int t = threadIdx.x;
    const int r = t >> 4, c4 = (t & 15) * 4;
#pragma unroll
    for (int j = 0; j < 4; ++j) {
        int rr = r + j * 16;
        const float4 v = *reinterpret_cast<const float4*>(src + (size_t)rr * N + c4);
        tile[rr][c4 + 0] = v.x; tile[rr][c4 + 1] = v.y;
        tile[rr][c4 + 2] = v.z; tile[rr][c4 + 3] = v.w;
    }
    __syncthreads();
#pragma unroll
    for (int j = 0; j < 4; ++j) {
        int nn = r + j * 16;
        float v0 = tile[c4 + 0][nn], v1 = tile[c4 + 1][nn];
        float v2 = tile[c4 + 2][nn], v3 = tile[c4 + 3][nn];
        __nv_bfloat16 h0 = __float2bfloat16_rn(v0), h1 = __float2bfloat16_rn(v1);
        __nv_bfloat16 h2 = __float2bfloat16_rn(v2), h3 = __float2bfloat16_rn(v3);
        __nv_bfloat16 l0 = __float2bfloat16_rn(v0 - __bfloat162float(h0));
        __nv_bfloat16 l1 = __float2bfloat16_rn(v1 - __bfloat162float(h1));
        __nv_bfloat16 l2 = __float2bfloat16_rn(v2 - __bfloat162float(h2));
        __nv_bfloat16 l3 = __float2bfloat16_rn(v3 - __bfloat162float(h3));
        size_t out = ((size_t)e * N + N0 + nn) * K + K0 + c4;
        *reinterpret_cast<uint2*>(Wh + out) = make_uint2(pack_bf16(h0, h1), pack_bf16(h2, h3));
        *reinterpret_cast<uint2*>(Wl + out) = make_uint2(pack_bf16(l0, l1), pack_bf16(l2, l3));
    }
#endif
}

// ---------------- kernel: post-GEMM1 GELU + hi/lo split (half-row per block) ----------------
__global__ __launch_bounds__(256) void postgelu_kernel(int colbase) {
    const size_t base = (size_t)blockIdx.x * DF + colbase;
    const int t = threadIdx.x;
#pragma unroll
    for (int j = 0; j < 2; ++j) {
        const int i = (j * 256 + t) * 4;
        const float4 v = *reinterpret_cast<const float4*>(g_Hf + base + i);
        float a0 = gelu_exact(v.x);
        float a1 = gelu_exact(v.y);
        float a2 = gelu_exact(v.z);
        float a3 = gelu_exact(v.w);
        __nv_bfloat16 h0 = __float2bfloat16_rn(a0), h1 = __float2bfloat16_rn(a1);
        __nv_bfloat16 h2 = __float2bfloat16_rn(a2), h3 = __float2bfloat16_rn(a3);
        __nv_bfloat16 l0 = __float2bfloat16_rn(a0 - __bfloat162float(h0));
        __nv_bfloat16 l1 = __float2bfloat16_rn(a1 - __bfloat162float(h1));
        __nv_bfloat16 l2 = __float2bfloat16_rn(a2 - __bfloat162float(h2));
        __nv_bfloat16 l3 = __float2bfloat16_rn(a3 - __bfloat162float(h3));
        *reinterpret_cast<uint2*>(g_Hh + base + i) = make_uint2(pack_bf16(h0, h1), pack_bf16(h2, h3));
        *reinterpret_cast<uint2*>(g_Hl + base + i) = make_uint2(pack_bf16(l0, l1), pack_bf16(l2, l3));
    }
}

// ---------------- tcgen05 cg2 GEMM: persistent clusters, double-buffered TMEM D ----------------
#define BUF_STRIDE 65536
#define OFF_AL 16384
#define OFF_BH 32768
#define OFF_BL 49152
#define OFF_TMEM 196608
#define OFF_MBAR 196624
#define SMEM_DYN 198656
#define STAGE_BYTES 65536u
// mbar layout: full[0..2]@+0,8,16 ; empty[0..2]@+24,32,40 ; done[0..1]@+48,56 ; free[0..1]@+64,72

#define GEMM_IDESC2 ((1u << 4) | (1u << 7) | (1u << 10) | ((256u / 8) << 17) | ((256u / 16) << 24))

// nofs = N-tile window offset, nlg = log2(window N-tile count)
template <bool FIRST>
__global__ __launch_bounds__(256)
void moe_gemm_tc(const __grid_constant__ CUtensorMap tmAh,
                 const __grid_constant__ CUtensorMap tmAl,
                 const __grid_constant__ CUtensorMap tmBh,
                 const __grid_constant__ CUtensorMap tmBl,
                 const float* __restrict__ bias, int nofs, int nlg) {
#if HAS_TC
    constexpr int KTOT = FIRST ? DM : DF;
    constexpr int NTOT = FIRST ? DF : DM;
    constexpr int NC = KTOT / 64;

    const int cid = blockIdx.y;
    const int rank = blockIdx.x & 1;
    const int nmsk = (1 << nlg) - 1;
    const int tot = g_num_tiles << nlg;

    extern __shared__ char dyn[];
    const uint32_t raw = smaddr(dyn);
    const uint32_t sbase = (raw + 1023u) & ~1023u;
    const int t = threadIdx.x;
    const int w = t >> 5, lane = t & 31;

    if (w == 0) {
        tc_alloc2(sbase + OFF_TMEM, 512);
        tc_relinq2();
    }
    if (t == 0) {
#pragma unroll
        for (int s = 0; s < 8; ++s) mbar_init(sbase + OFF_MBAR + s * 8, 1);
        mbar_init(sbase + OFF_MBAR + 64, 2);
        mbar_init(sbase + OFF_MBAR + 72, 2);
    }
    __syncthreads();
    cluster_sync_();

    uint32_t tmem;
    asm volatile("ld.shared.b32 %0, [%1];" : "=r"(tmem) : "r"(sbase + OFF_TMEM));

    const uint32_t mbF = sbase + OFF_MBAR;
    const uint32_t mbE = sbase + OFF_MBAR + 24;
    const uint32_t mbD = sbase + OFF_MBAR + 48;
    const uint32_t mbR = sbase + OFF_MBAR + 64;

    if (w == 0 && elect_one()) {
        // ================= producer: continuous TMA across tiles =================
        uint32_t pE = 0, pDp = 0;
        int s = 0;
#pragma unroll 1
        for (int tt = 0;; ++tt) {
            const int T = cid + tt * NCLUST;
            if (T >= tot) break;
            const int rt = T >> nlg, nt = (T & nmsk) + nofs;
            const int e = g_tile_e[rt];
            const int arow = g_tile_r0[rt] + rank * 128;
            const int bcol = nt * 256 + rank * 128;
#pragma unroll 1
            for (int i = 0; i < NC; ++i, ++s) {
                const int b = s % 3;
                if (s >= 3) {
                    const int sp_ = s - 3;
                    if ((sp_ % NC) == NC - 1) {
                        const int d = (sp_ / NC) & 1;
                        mbar_wait(mbD + d * 8, (pDp >> d) & 1u); pDp ^= 1u << d;
                    } else {
                        mbar_wait(mbE + b * 8, (pE >> b) & 1u); pE ^= 1u << b;
                    }
                }
                if (rank == 0) mbar_expect(mbF + b * 8, 2u * STAGE_BYTES);
                const uint32_t bb = sbase + (uint32_t)b * BUF_STRIDE;
                const int k0 = i * 64;
                tma2d_cg2(bb,          (const void*)&tmAh, k0, arow, mbF + b * 8);
                tma2d_cg2(bb + OFF_AL, (const void*)&tmAl, k0, arow, mbF + b * 8);
                tma3d_cg2(bb + OFF_BH, (const void*)&tmBh, k0, bcol, e, mbF + b * 8);
                tma3d_cg2(bb + OFF_BL, (const void*)&tmBl, k0, bcol, e, mbF + b * 8);
            }
        }
    } else if (w == 1 && rank == 0 && elect_one()) {
        // ================= consumer: MMA =================
        uint64_t dA[3], dAl_[3], dB[3], dBl_[3];
#pragma unroll
        for (int s2 = 0; s2 < 3; ++s2) {
            uint32_t b = sbase + s2 * BUF_STRIDE;
            dA[s2]   = mk_desc(b);
            dAl_[s2] = mk_desc(b + OFF_AL);
            dB[s2]   = mk_desc(b + OFF_BH);
            dBl_[s2] = mk_desc(b + OFF_BL);
        }
        uint32_t pF = 0, pFree = 0;
        int s = 0, ttn = 0;
#pragma unroll 1
        for (int tt = 0;; ++tt) {
            const int T = cid + tt * NCLUST;
            if (T >= tot) break;
            ttn = tt + 1;
            const int d = tt & 1;
            if (tt >= 2) {
                mbar_wait(mbR + d * 8, (pFree >> d) & 1u); pFree ^= 1u << d;
                tc_fence_after();
            }
            const uint32_t dtm = tmem + d * 256;
#pragma unroll 1
            for (int i = 0; i < NC; ++i, ++s) {
                const int b = s % 3;
                mbar_wait(mbF + b * 8, (pF >> b) & 1u); pF ^= 1u << b;
#pragma unroll
                for (int ks = 0; ks < 4; ++ks) {
                    const uint64_t oa = (uint64_t)(ks * 2);
                    const uint32_t en0 = (i == 0 && ks == 0) ? 0u : 1u;
                    tc_mma_f16_ss2(dtm, dA[b] + oa,   dB[b] + oa,   GEMM_IDESC2, en0);
                    tc_mma_f16_ss2(dtm, dA[b] + oa,   dBl_[b] + oa, GEMM_IDESC2, 1u);
                    tc_mma_f16_ss2(dtm, dAl_[b] + oa, dB[b] + oa,   GEMM_IDESC2, 1u);
                }
                tc_commit_mc2((i == NC - 1) ? (mbD + d * 8) : (mbE + b * 8));
            }
        }
#pragma unroll 1
        for (int k = (ttn >= 2 ? ttn - 2 : 0); k < ttn; ++k) {
            const int d = k & 1;
            mbar_wait(mbR + d * 8, (pFree >> d) & 1u); pFree ^= 1u << d;
        }
    } else if (w >= 2) {
        // ================= epilogue: warps 2..7 (raw fp32 + bias only) =================
        const int sp_ = w & 3;
        const int rloc = sp_ * 32 + lane;
        int cstart, cnum;
        if (w == 4 || w == 5)      { cstart = 0;   cnum = 8; }
        else if (w == 2 || w == 3) { cstart = 0;   cnum = 4; }
        else                       { cstart = 128; cnum = 4; }

        uint32_t pDe = 0;
#pragma unroll 1
        for (int tt = 0;; ++tt) {
            const int T = cid + tt * NCLUST;
            if (T >= tot) break;
            const int d = tt & 1;
            mbar_wait(mbD + d * 8, (pDe >> d) & 1u); pDe ^= 1u << d;
            tc_fence_after();

            const int rt = T >> nlg, nt = (T & nmsk) + nofs;
            const int e = g_tile_e[rt];
            const int row0 = g_tile_r0[rt];
            const int n0 = nt * 256;
            int vr = g_tile_valid[rt] - rank * 128;
            vr = vr < 0 ? 0 : (vr > 128 ? 128 : vr);
            const bool valid = rloc < vr;
            const int rowg = row0 + rank * 128 + rloc;
            const uint32_t dtm = tmem + d * 256;
            const float* bb = bias + (size_t)e * NTOT + n0;
            float* oF = (FIRST ? g_Hf + (size_t)rowg * DF : g_Y + (size_t)rowg * DM) + n0;

#pragma unroll 1
            for (int j = 0; j < cnum; ++j) {
                const int col = cstart + j * 32;
                uint32_t dr[32];
                tc_ld_x32(dr, dtm + col);
                tc_wait_ld();
                if (valid) {
#pragma unroll
                    for (int c = 0; c < 32; c += 4) {
                        float4 o;
                        o.x = __uint_as_float(dr[c + 0]) + bb[col + c + 0];
                        o.y = __uint_as_float(dr[c + 1]) + bb[col + c + 1];
                        o.z = __uint_as_float(dr[c + 2]) + bb[col + c + 2];
                        o.w = __uint_as_float(dr[c + 3]) + bb[col + c + 3];
                        *reinterpret_cast<float4*>(oF + col + c) = o;
                    }
                }
            }
            tc_fence_before();
            asm volatile("bar.sync 1, 192;" ::: "memory");
            if (w == 2 && elect_one()) mbar_arrive_leader(mbR + d * 8);
        }
    }

    __syncthreads();
    if (t == 0) {
#pragma unroll
        for (int s = 0; s < 10; ++s) mbar_inval(sbase + OFF_MBAR + s * 8);
    }
    __syncthreads();
    cluster_sync_();
    if (w == 0) tc_dealloc2(tmem, 512);
    cluster_sync_();
#endif  // HAS_TC
}

// ---------------- fallback GEMM (mma.sync; 256-tiles split in half) ----------------
template <bool FIRST>
__global__ __launch_bounds__(256) void moe_gemm_fb(const float* __restrict__ W,
                                                   const float* __restrict__ bias) {
#if !HAS_TC
    constexpr int KTOT = FIRST ? DM : DF;
    constexpr int LDW  = FIRST ? DF : DM;
    const int tileIdx = blockIdx.y >> 1;
    if (tileIdx >= g_num_tiles) return;
    const int half = blockIdx.y & 1;
    const int e = g_tile_e[tileIdx];
    const int row0 = g_tile_r0[tileIdx] + half * 128;
    int vrows = g_tile_valid[tileIdx] - half * 128;
    vrows = vrows < 0 ? 0 : (vrows > 128 ? 128 : vrows);
    if (vrows == 0) return;
    const int n0 = blockIdx.x * 128;
    const float* Wn = W + (size_t)e * KTOT * LDW + n0;
    const float* bn = bias + (size_t)e * LDW + n0;

    __shared__ __align__(16) __nv_bfloat16 sAh[128 * 40];
    __shared__ __align__(16) __nv_bfloat16 sAl[128 * 40];
    __shared__ __align__(16) __nv_bfloat16 sBh[32 * 136];
    __shared__ __align__(16) __nv_bfloat16 sBl[32 * 136];

    const int t = threadIdx.x;
    float c[4][4][4];
#pragma unroll
    for (int a = 0; a < 4; ++a)
#pragma unroll
        for (int b = 0; b < 4; ++b)
#pragma unroll
            for (int q = 0; q < 4; ++q) c[a][b][q] = 0.f;

    const int lane = t & 31, warp = t >> 5;
    const int wm = warp >> 2, wn = warp & 3;
    const int m0 = wm * 64;
    const int sub = t & 15, rgrp = t >> 4;

    for (int k0 = 0; k0 < KTOT; k0 += 32) {
        __syncthreads();
#pragma unroll
        for (int rr = 0; rr < 8; ++rr) {
            int r = rr * 16 + rgrp;
            int rg = row0 + r; if (rg > PAIRS - 1) rg = PAIRS - 1;
            const uint32_t* ph = reinterpret_cast<const uint32_t*>(
                (FIRST ? g_Ah : g_Hh) + (size_t)rg * KTOT + k0);
            const uint32_t* pl = reinterpret_cast<const uint32_t*>(
                (FIRST ? g_Al : g_Hl) + (size_t)rg * KTOT + k0);
            *reinterpret_cast<uint32_t*>(&sAh[r * 40 + sub * 2]) = ph[sub];
            *reinterpret_cast<uint32_t*>(&sAl[r * 40 + sub * 2]) = pl[sub];
        }
#pragma unroll
        for (int i = 0; i < 4; ++i) {
            int lin = (i * 256 + t) * 4;
            int kr = lin >> 7;
            int nc = lin & 127;
            const float4 v = *reinterpret_cast<const float4*>(Wn + (size_t)(k0 + kr) * LDW + nc);
            __nv_bfloat16 h0 = __float2bfloat16_rn(v.x);
            __nv_bfloat16 h1 = __float2bfloat16_rn(v.y);
            __nv_bfloat16 h2 = __float2bfloat16_rn(v.z);
            __nv_bfloat16 h3 = __float2bfloat16_rn(v.w);
            __nv_bfloat16 l0 = __float2bfloat16_rn(v.x - __bfloat162float(h0));
            __nv_bfloat16 l1 = __float2bfloat16_rn(v.y - __bfloat162float(h1));
            __nv_bfloat16 l2 = __float2bfloat16_rn(v.z - __bfloat162float(h2));
            __nv_bfloat16 l3 = __float2bfloat16_rn(v.w - __bfloat162float(h3));
            *reinterpret_cast<uint2*>(&sBh[kr * 136 + nc]) = make_uint2(pack_bf16(h0, h1), pack_bf16(h2, h3));
            *reinterpret_cast<uint2*>(&sBl[kr * 136 + nc]) = make_uint2(pack_bf16(l0, l1), pack_bf16(l2, l3));
        }
        __syncthreads();

#pragma unroll
        for (int ks = 0; ks < 2; ++ks) {
            uint32_t ah[4][4], al[4][4], bh[4][2], bl[4][2];
            {
                int ar = lane & 15;
                int acol = ks * 16 + (lane >> 4) * 8;
#pragma unroll
                for (int fm = 0; fm < 4; ++fm) {
                    ldsm4(ah[fm], smaddr(&sAh[(m0 + fm * 16 + ar) * 40 + acol]));
                    ldsm4(al[fm], smaddr(&sAl[(m0 + fm * 16 + ar) * 40 + acol]));
                }
                int brow = ks * 16 + (lane & 15);
                int bcol = wn * 32 + (lane >> 4) * 8;
#pragma unroll
                for (int hb = 0; hb < 2; ++hb) {
                    uint32_t r[4];
                    ldsm4t(r, smaddr(&sBh[brow * 136 + bcol + hb * 16]));
                    bh[2 * hb][0] = r[0]; bh[2 * hb][1] = r[1];
                    bh[2 * hb + 1][0] = r[2]; bh[2 * hb + 1][1] = r[3];
                    ldsm4t(r, smaddr(&sBl[brow * 136 + bcol + hb * 16]));
                    bl[2 * hb][0] = r[0]; bl[2 * hb][1] = r[1];
                    bl[2 * hb + 1][0] = r[2]; bl[2 * hb + 1][1] = r[3];
                }
            }
#pragma unroll
            for (int fm = 0; fm < 4; ++fm)
#pragma unroll
                for (int fn = 0; fn < 4; ++fn) {
                    mma16816(c[fm][fn], ah[fm], bh[fn]);
                    mma16816(c[fm][fn], ah[fm], bl[fn]);
                    mma16816(c[fm][fn], al[fm], bh[fn]);
                }
        }
    }

    const int lgrp = lane >> 2, lq = lane & 3;
#pragma unroll
    for (int fm = 0; fm < 4; ++fm) {
        int rl = m0 + fm * 16 + lgrp;
#pragma unroll
        for (int fn = 0; fn < 4; ++fn) {
            int nc = wn * 32 + fn * 8 + lq * 2;
            float bv0 = bn[nc], bv1 = bn[nc + 1];
            float* cc = c[fm][fn];
#pragma unroll
            for (int h = 0; h < 2; ++h) {
                int rloc = rl + h * 8;
                if (rloc < vrows) {
                    int row = row0 + rloc;
                    float v0 = cc[h * 2 + 0] + bv0;
                    float v1 = cc[h * 2 + 1] + bv1;
                    if (FIRST) {
                        *reinterpret_cast<float2*>(&g_Hf[(size_t)row * DF + n0 + nc]) = make_float2(v0, v1);
                    } else {
                        *reinterpret_cast<float2*>(&g_Y[(size_t)row * DM + n0 + nc]) = make_float2(v0, v1);
                    }
                }
            }
        }
    }
#endif  // !HAS_TC
}

// ---------------- kernel: weighted combine ----------------
__global__ __launch_bounds__(256) void combine_kernel(float* __restrict__ out) {
    const int tk = blockIdx.x;
    const int d = threadIdx.x * 4;
    int s0 = g_pair_slot[2 * tk], s1 = g_pair_slot[2 * tk + 1];
    float w0 = g_pair_w[2 * tk], w1 = g_pair_w[2 * tk + 1];
    const float4 a = *reinterpret_cast<const float4*>(&g_Y[(size_t)s0 * DM + d]);
    const float4 b = *reinterpret_cast<const float4*>(&g_Y[(size_t)s1 * DM + d]);
    float4 o;
    o.x = w0 * a.x + w1 * b.x;
    o.y = w0 * a.y + w1 * b.y;
    o.z = w0 * a.z + w1 * b.z;
    o.w = w0 * a.w + w1 * b.w;
    *reinterpret_cast<float4*>(&out[(size_t)tk * DM + d]) = o;
}

// ---------------- host: tensor map construction ----------------
typedef CUresult (*TmEncodeFn)(CUtensorMap*, CUtensorMapDataType, cuuint32_t, void*,
                               const cuuint64_t*, const cuuint64_t*, const cuuint32_t*,
                               const cuuint32_t*, CUtensorMapInterleave, CUtensorMapSwizzle,
                               CUtensorMapL2promotion, CUtensorMapFloatOOBfill);

static void tm2d(TmEncodeFn enc, CUtensorMap* tm, void* base, unsigned long long K,
                 unsigned long long R) {
    cuuint64_t dims[2] = {K, R};
    cuuint64_t st[1] = {K * 2};
    cuuint32_t box[2] = {64, 128};
    cuuint32_t es[2] = {1, 1};
    enc(tm, CU_TENSOR_MAP_DATA_TYPE_BFLOAT16, 2, base, dims, st, box, es,
        CU_TENSOR_MAP_INTERLEAVE_NONE, CU_TENSOR_MAP_SWIZZLE_128B,
        CU_TENSOR_MAP_L2_PROMOTION_L2_128B, CU_TENSOR_MAP_FLOAT_OOB_FILL_NONE);
}
static void tm3d(TmEncodeFn enc, CUtensorMap* tm, void* base, unsigned long long K,
                 unsigned long long N) {
    cuuint64_t dims[3] = {K, N, NE};
    cuuint64_t st[2] = {K * 2, N * K * 2};
    cuuint32_t box[3] = {64, 128, 1};
    cuuint32_t es[3] = {1, 1, 1};
    enc(tm, CU_TENSOR_MAP_DATA_TYPE_BFLOAT16, 3, base, dims, st, box, es,
        CU_TENSOR_MAP_INTERLEAVE_NONE, CU_TENSOR_MAP_SWIZZLE_128B,
        CU_TENSOR_MAP_L2_PROMOTION_L2_128B, CU_TENSOR_MAP_FLOAT_OOB_FILL_NONE);
}

// ---------------- launch ----------------
extern "C" void kernel_launch(void* const* d_in, const int* in_sizes, int n_in,
                              void* d_out, int out_size) {
    const float* x  = (const float*)d_in[0];
    const float* gw = (const float*)d_in[1];
    const float* w1 = (const float*)d_in[2];
    const float* b1 = (const float*)d_in[3];
    const float* w2 = (const float*)d_in[4];
    const float* b2 = (const float*)d_in[5];
    float* out = (float*)d_out;

    cudaFuncSetAttribute(moe_gemm_tc<true>,  cudaFuncAttributeMaxDynamicSharedMemorySize, SMEM_DYN);
    cudaFuncSetAttribute(moe_gemm_tc<false>, cudaFuncAttributeMaxDynamicSharedMemorySize, SMEM_DYN);

    void *pAh, *pAl, *pHh, *pHl, *pW1h, *pW1l, *pW2h, *pW2l;
    cudaGetSymbolAddress(&pAh, g_Ah);
    cudaGetSymbolAddress(&pAl, g_Al);
    cudaGetSymbolAddress(&pHh, g_Hh);
    cudaGetSymbolAddress(&pHl, g_Hl);
    cudaGetSymbolAddress(&pW1h, g_w1h);
    cudaGetSymbolAddress(&pW1l, g_w1l);
    cudaGetSymbolAddress(&pW2h, g_w2h);
    cudaGetSymbolAddress(&pW2l, g_w2l);

    void* sym = nullptr;
    cudaDriverEntryPointQueryResult qr;
    cudaGetDriverEntryPoint("cuTensorMapEncodeTiled", &sym, cudaEnableDefault, &qr);
    TmEncodeFn enc = (TmEncodeFn)sym;

    CUtensorMap tAh, tAl, tB1h, tB1l, tHh, tHl, tB2h, tB2l;
    if (enc) {
        tm2d(enc, &tAh, pAh, DM, PAIRS);
        tm2d(enc, &tAl, pAl, DM, PAIRS);
        tm3d(enc, &tB1h, pW1h, DM, DF);
        tm3d(enc, &tB1l, pW1l, DM, DF);
        tm2d(enc, &tHh, pHh, DF, PAIRS);
        tm2d(enc, &tHl, pHl, DF, PAIRS);
        tm3d(enc, &tB2h, pW2h, DF, DM);
        tm3d(enc, &tB2l, pW2l, DF, DM);
    }

    // side stream + events (lazily created once; control-flow resources only)
    static cudaStream_t sSide = nullptr;
    static cudaEvent_t evFork = nullptr, evW1 = nullptr, evW2 = nullptr, evG1a = nullptr, evPa = nullptr;
    if (!sSide) {
        cudaStreamCreateWithFlags(&sSide, cudaStreamNonBlocking);
        cudaEventCreateWithFlags(&evFork, cudaEventDisableTiming);
        cudaEventCreateWithFlags(&evW1, cudaEventDisableTiming);
        cudaEventCreateWithFlags(&evW2, cudaEventDisableTiming);
        cudaEventCreateWithFlags(&evG1a, cudaEventDisableTiming);
        cudaEventCreateWithFlags(&evPa, cudaEventDisableTiming);
    }

    // fork: weight split runs on side stream, independent of routing
    cudaEventRecord(evFork, 0);
    cudaStreamWaitEvent(sSide, evFork, 0);
    wsplit_kernel<<<dim3(DM / 64, DF / 64, NE), 256, 0, sSide>>>(w1, (__nv_bfloat16*)pW1h, (__nv_bfloat16*)pW1l, DM, DF);
    cudaEventRecord(evW1, sSide);
    wsplit_kernel<<<dim3(DF / 64, DM / 64, NE), 256, 0, sSide>>>(w2, (__nv_bfloat16*)pW2h, (__nv_bfloat16*)pW2l, DF, DM);
    cudaEventRecord(evW2, sSide);

    // main stream: routing + fused scatter/gather
    zero_kernel<<<1, 32>>>();
    gate_kernel<<<T_TOKENS / 8, 256>>>(x, gw);
    scan_kernel<<<1, 32>>>();
    scattergather_kernel<<<dim3(64, 16), 256>>>(x);

    cudaLaunchAttribute cat[1];
    cat[0].id = cudaLaunchAttributeClusterDimension;
    cat[0].val.clusterDim.x = 2;
    cat[0].val.clusterDim.y = 1;
    cat[0].val.clusterDim.z = 1;

    cudaStreamWaitEvent(0, evW1, 0);  // join w1 split
    {
        // GEMM1 first N-half (columns 0..2047)
        cudaLaunchConfig_t cfg = {};
        cfg.gridDim = dim3(2, NCLUST, 1);
        cfg.blockDim = dim3(256, 1, 1);
        cfg.dynamicSmemBytes = SMEM_DYN;
        cfg.stream = 0;
        cfg.attrs = cat;
        cfg.numAttrs = 1;
        cudaLaunchKernelEx(&cfg, moe_gemm_tc<true>, tAh, tAl, tB1h, tB1l, b1, 0, 3);
    }
    moe_gemm_fb<true><<<dim3(DF / 128, MAXT2 * 2), 256>>>(w1, b1);   // no-op on tc build (full GEMM1 on fallback)
    cudaEventRecord(evG1a, 0);
    {
        // GEMM1 second N-half (columns 2048..4095)
        cudaLaunchConfig_t cfg = {};
        cfg.gridDim = dim3(2, NCLUST, 1);
        cfg.blockDim = dim3(256, 1, 1);
        cfg.dynamicSmemBytes = SMEM_DYN;
        cfg.stream = 0;
        cfg.attrs = cat;
        cfg.numAttrs = 1;
        cudaLaunchKernelEx(&cfg, moe_gemm_tc<true>, tAh, tAl, tB1h, tB1l, b1, 8, 3);
    }
    // side: postgelu on first half, overlapping GEMM1 second half
    cudaStreamWaitEvent(sSide, evG1a, 0);
    postgelu_kernel<<<PAIRS, 256, 0, sSide>>>(0);
    cudaEventRecord(evPa, sSide);
    // main: postgelu on second half
    postgelu_kernel<<<PAIRS, 256>>>(2048);
    cudaStreamWaitEvent(0, evPa, 0);
    cudaStreamWaitEvent(0, evW2, 0);  // join w2 split
    {
        cudaLaunchConfig_t cfg = {};
        cfg.gridDim = dim3(2, NCLUST, 1);
        cfg.blockDim = dim3(256, 1, 1);
        cfg.dynamicSmemBytes = SMEM_DYN;
        cfg.stream = 0;
        cfg.attrs = cat;
        cfg.numAttrs = 1;
        cudaLaunchKernelEx(&cfg, moe_gemm_tc<false>, tHh, tHl, tB2h, tB2l, b2, 0, 2);
    }
    moe_gemm_fb<false><<<dim3(DM / 128, MAXT2 * 2), 256>>>(w2, b2);  // no-op on tc build
    combine_kernel<<<T_TOKENS, 256>>>(out);
}